// round 12
// baseline (speedup 1.0000x reference)
#include <cuda_runtime.h>
#include <cuda_fp16.h>
#include <math.h>
#include <stdint.h>

#define BATCH 8
#define CCH 512
#define SS 1024
#define NHD 8
#define NGR 32
#define CG 16
#define C8 64
#define C2 256
#define GEPS 1e-6f

// ---------------- static scratch ----------------
__device__ float  d_hs   [BATCH*CCH*SS];
__device__ __half d_hst  [BATCH*SS*CCH];
__device__ __half d_shnt [BATCH*SS*CCH];
__device__ __half d_senht[BATCH*SS*CCH];
__device__ float  d_a1   [BATCH*C8*SS];
__device__ float  d_a2   [BATCH*C8*SS];
__device__ float  d_swt  [BATCH*SS];
__device__ __half d_q    [BATCH*SS*CCH];
__device__ __half d_k    [BATCH*SS*CCH];
__device__ __half d_v    [BATCH*SS*CCH];
__device__ __half d_qm   [2*BATCH*SS*C2];
__device__ __half d_km   [2*BATCH*SS*C2];
__device__ __half d_vm   [2*BATCH*SS*C2];
__device__ __half d_comb [BATCH*SS*2*CCH];
__device__ __half d_f1   [BATCH*SS*CCH];
__device__ __half d_fus  [BATCH*SS*CCH];
__device__ float  d_fin  [BATCH*SS*CCH];
__device__ __half d_w    [2654208];   // all weights converted to half

// ---------------- helpers ----------------
__device__ __forceinline__ float blk_sum(float v, float* sb, int tid) {
    sb[tid] = v; __syncthreads();
    for (int o = 128; o > 0; o >>= 1) { if (tid < o) sb[tid] += sb[tid + o]; __syncthreads(); }
    float r = sb[0]; __syncthreads(); return r;
}
__device__ __forceinline__ float silu_f(float x) { return x / (1.0f + expf(-x)); }
__device__ __forceinline__ uint32_t pack2(float a, float b) {
    __half2 h = __floats2half2_rn(a, b);
    return *reinterpret_cast<uint32_t*>(&h);
}
__device__ __forceinline__ void store2(float* p, float a, float b) {
    *(float2*)p = make_float2(a, b);
}
__device__ __forceinline__ void store2(__half* p, float a, float b) {
    *(uint32_t*)p = pack2(a, b);
}
__device__ __forceinline__ uint32_t cvsm(const void* p) {
    return (uint32_t)__cvta_generic_to_shared(p);
}
__device__ __forceinline__ void ldsm_x4(uint32_t& r0, uint32_t& r1, uint32_t& r2,
                                        uint32_t& r3, uint32_t addr) {
    asm volatile("ldmatrix.sync.aligned.m8n8.x4.shared.b16 {%0,%1,%2,%3}, [%4];"
        : "=r"(r0), "=r"(r1), "=r"(r2), "=r"(r3) : "r"(addr));
}
__device__ __forceinline__ void ldsm_x4_t(uint32_t& r0, uint32_t& r1, uint32_t& r2,
                                          uint32_t& r3, uint32_t addr) {
    asm volatile("ldmatrix.sync.aligned.m8n8.x4.trans.shared.b16 {%0,%1,%2,%3}, [%4];"
        : "=r"(r0), "=r"(r1), "=r"(r2), "=r"(r3) : "r"(addr));
}

#define MMA16(d, a0, a1, a2, a3, b0, b1) \
    asm volatile("mma.sync.aligned.m16n8k16.row.col.f32.f16.f16.f32 " \
        "{%0,%1,%2,%3},{%4,%5,%6,%7},{%8,%9},{%0,%1,%2,%3};" \
        : "+f"((d)[0]), "+f"((d)[1]), "+f"((d)[2]), "+f"((d)[3]) \
        : "r"(a0), "r"(a1), "r"(a2), "r"(a3), "r"(b0), "r"(b1))

// ---------------- weight conversion fp32 -> half ----------------
struct WC { const float* src[13]; int cnt4[13]; int off[13]; };
__global__ void wcvt(WC wc, __half* dst) {
    int which = blockIdx.y;
    int idx = blockIdx.x * 256 + threadIdx.x;
    if (idx < wc.cnt4[which]) {
        float4 v = *(const float4*)&wc.src[which][idx * 4];
        uint2 pk = make_uint2(pack2(v.x, v.y), pack2(v.z, v.w));
        *(uint2*)&dst[wc.off[which] + idx * 4] = pk;
    }
}

// =====================================================================
// Fused double GroupNorm (unchanged).
// =====================================================================
__global__ void gn_fused(const float* __restrict__ x,
                         const float* __restrict__ pre_g, const float* __restrict__ pre_b,
                         const float* __restrict__ pos,
                         const float* __restrict__ norm_g, const float* __restrict__ norm_b,
                         float* __restrict__ hs, __half* __restrict__ hs_t,
                         __half* __restrict__ shn_t) {
    extern __shared__ float xs[];
    __shared__ float sb[256];
    __shared__ float pgs[16], pbs[16], ngs[16], nbs[16];

    int tid = threadIdx.x;
    int b = blockIdx.x / NGR, gi = blockIdx.x % NGR;
    long base = (long)b * CCH * SS + (long)gi * CG * SS;
    if (tid < 16) {
        int c = gi * 16 + tid;
        pgs[tid] = pre_g[c]; pbs[tid] = pre_b[c];
        ngs[tid] = norm_g[c]; nbs[tid] = norm_b[c];
    }

    float s1 = 0.f, s2 = 0.f;
    for (int i = tid; i < CG * SS; i += 256) {
        float v = x[base + i];
        xs[i] = v; s1 += v; s2 += v * v;
    }
    s1 = blk_sum(s1, sb, tid);
    s2 = blk_sum(s2, sb, tid);
    float mu1 = s1 / (float)(CG * SS);
    float inv1 = rsqrtf(s2 / (float)(CG * SS) - mu1 * mu1 + GEPS);

    float t1 = 0.f, t2 = 0.f;
    for (int i = tid; i < CG * SS; i += 256) {
        int cl = i >> 10, s = i & 1023;
        int c = gi * CG + cl;
        float h = (xs[i] - mu1) * inv1 * pgs[cl] + pbs[cl] + pos[(long)c * SS + s];
        xs[i] = h;
        hs[base + i] = h;
        t1 += h; t2 += h * h;
    }
    t1 = blk_sum(t1, sb, tid);
    t2 = blk_sum(t2, sb, tid);
    float mu2 = t1 / (float)(CG * SS);
    float inv2 = rsqrtf(t2 / (float)(CG * SS) - mu2 * mu2 + GEPS);

    long tbase = ((long)b * SS) * CCH + gi * 16;
    for (int s = tid; s < SS; s += 256) {
        uint32_t wh[8], wn[8];
        #pragma unroll
        for (int cl = 0; cl < 16; cl += 2) {
            float h0 = xs[cl * 1024 + s], h1 = xs[(cl + 1) * 1024 + s];
            wh[cl >> 1] = pack2(h0, h1);
            float n0 = (h0 - mu2) * inv2 * ngs[cl] + nbs[cl];
            float n1 = (h1 - mu2) * inv2 * ngs[cl + 1] + nbs[cl + 1];
            wn[cl >> 1] = pack2(n0, n1);
        }
        __half* ph = hs_t + tbase + (long)s * CCH;
        *(uint4*)ph       = make_uint4(wh[0], wh[1], wh[2], wh[3]);
        *(uint4*)(ph + 8) = make_uint4(wh[4], wh[5], wh[6], wh[7]);
        __half* pn = shn_t + tbase + (long)s * CCH;
        *(uint4*)pn       = make_uint4(wn[0], wn[1], wn[2], wn[3]);
        *(uint4*)(pn + 8) = make_uint4(wn[4], wn[5], wn[6], wn[7]);
    }
}

// ---------------- group norm token-major + residual ----------------
__global__ void gn_post_k(const float* __restrict__ xt, const float* __restrict__ g,
                          const float* __restrict__ be, const float* __restrict__ resid,
                          float* __restrict__ y) {
    __shared__ float sb[256];
    int tid = threadIdx.x;
    int b = blockIdx.x / NGR, gi = blockIdx.x % NGR;
    long tbase = (long)b * SS * CCH + gi * CG;
    float s1 = 0.f, s2 = 0.f;
    for (int i = tid; i < CG * SS; i += 256) {
        int s = i >> 4, cl = i & 15;
        float v = xt[tbase + (long)s * CCH + cl]; s1 += v; s2 += v * v;
    }
    s1 = blk_sum(s1, sb, tid);
    s2 = blk_sum(s2, sb, tid);
    float mu = s1 / (float)(CG * SS);
    float var = s2 / (float)(CG * SS) - mu * mu;
    float inv = rsqrtf(var + GEPS);
    for (int i = tid; i < CG * SS; i += 256) {
        int s = i >> 4, cl = i & 15;
        int c = gi * CG + cl;
        float v = (xt[tbase + (long)s * CCH + cl] - mu) * inv * g[c] + be[c];
        long oidx = (long)b * CCH * SS + (long)c * SS + s;
        y[oidx] = v + resid[oidx];
    }
}

// =====================================================================
// Unified fp16 GEMM (NT), 128x128 tile, B now HALF (preconverted).
// =====================================================================
struct GArg {
    const __half* A[6]; const __half* W[6]; void* Y[6]; const float* bias[6];
    float sc[6];
    long aOuter, yOuter;
    int K, lda, N, ldy, act;
};

template<typename OutT>
__global__ __launch_bounds__(256, 2) void gemm128(GArg ga) {
    __shared__ __align__(16) uint32_t As32[2 * 128 * 20];
    __shared__ __align__(16) uint32_t Bs32[2 * 128 * 20];

    int z = blockIdx.z;
    int which = z >> 3, b = z & 7;
    const __half* Ab = ga.A[which] + (long)b * ga.aOuter;
    const __half* Bb = ga.W[which];
    OutT*         Yb = (OutT*)ga.Y[which] + (long)b * ga.yOuter;
    const float* bias = ga.bias[which];
    float scl = ga.sc[which];
    int K = ga.K, lda = ga.lda, ldy = ga.ldy, act = ga.act;
    int m0 = blockIdx.x * 128, n0 = blockIdx.y * 128;

    int tid = threadIdx.x;
    int w = tid >> 5, lane = tid & 31;
    int wm = w & 1, wn = w >> 1;
    int g = lane >> 2, tig = lane & 3;
    int rbase = wm * 64, cbase = wn * 32;
    int lrow = lane & 7, lmat = lane >> 3;
    int fr_row = (lmat & 1) * 8 + lrow;
    int fr_col = (lmat >> 1) * 4;
    uint32_t As_b = cvsm(As32), Bs_b = cvsm(Bs32);

    float acc[4][4][4];
    #pragma unroll
    for (int i = 0; i < 4; i++)
        #pragma unroll
        for (int j = 0; j < 4; j++)
            #pragma unroll
            for (int l = 0; l < 4; l++) acc[i][j][l] = 0.f;

    uint4 aR[2], bR[2];
    int w4 = (tid & 3) * 4, mb = tid >> 2;

    auto ldg = [&](int k0) {
        #pragma unroll
        for (int it = 0; it < 2; it++)
            aR[it] = *(const uint4*)&Ab[(long)(m0 + mb + it * 64) * lda + k0 + w4 * 2];
        #pragma unroll
        for (int it = 0; it < 2; it++)
            bR[it] = *(const uint4*)&Bb[(long)(n0 + mb + it * 64) * K + k0 + w4 * 2];
    };
    auto sts = [&](int p) {
        uint32_t* Ad = As32 + p * 2560;
        uint32_t* Bd = Bs32 + p * 2560;
        #pragma unroll
        for (int it = 0; it < 2; it++)
            *(uint4*)&Ad[(mb + it * 64) * 20 + w4] = aR[it];
        #pragma unroll
        for (int it = 0; it < 2; it++)
            *(uint4*)&Bd[(mb + it * 64) * 20 + w4] = bR[it];
    };

    ldg(0); sts(0);
    __syncthreads();
    for (int k0 = 0; k0 < K; k0 += 32) {
        int p = (k0 >> 5) & 1;
        bool more = (k0 + 32 < K);
        if (more) ldg(k0 + 32);

        uint32_t Ap = As_b + (uint32_t)p * 2560 * 4;
        uint32_t Bp = Bs_b + (uint32_t)p * 2560 * 4;
        #pragma unroll
        for (int ks = 0; ks < 2; ks++) {
            int kw = ks * 8;
            uint32_t af[4][4], bf[4][2];
            #pragma unroll
            for (int mt = 0; mt < 4; mt++) {
                int r0 = rbase + mt * 16;
                ldsm_x4(af[mt][0], af[mt][1], af[mt][2], af[mt][3],
                        Ap + (uint32_t)(((r0 + fr_row) * 20) + kw + fr_col) * 4);
            }
            ldsm_x4(bf[0][0], bf[1][0], bf[2][0], bf[3][0],
                    Bp + (uint32_t)(((cbase + lmat * 8 + lrow) * 20) + kw) * 4);
            ldsm_x4(bf[0][1], bf[1][1], bf[2][1], bf[3][1],
                    Bp + (uint32_t)(((cbase + lmat * 8 + lrow) * 20) + kw + 4) * 4);
            #pragma unroll
            for (int mt = 0; mt < 4; mt++)
                #pragma unroll
                for (int nt = 0; nt < 4; nt++)
                    MMA16(acc[mt][nt], af[mt][0], af[mt][1], af[mt][2], af[mt][3],
                          bf[nt][0], bf[nt][1]);
        }
        if (more) sts(p ^ 1);
        __syncthreads();
    }

    #pragma unroll
    for (int mt = 0; mt < 4; mt++)
        #pragma unroll
        for (int nt = 0; nt < 4; nt++) {
            int r = m0 + rbase + mt * 16 + g;
            int cN = n0 + cbase + nt * 8 + 2 * tig;
            float b0 = bias ? bias[cN] : 0.f;
            float b1 = bias ? bias[cN + 1] : 0.f;
            float v0 = acc[mt][nt][0] * scl + b0;
            float v1 = acc[mt][nt][1] * scl + b1;
            float v2 = acc[mt][nt][2] * scl + b0;
            float v3 = acc[mt][nt][3] * scl + b1;
            if (act == 1) { v0 = silu_f(v0); v1 = silu_f(v1); v2 = silu_f(v2); v3 = silu_f(v3); }
            store2(&Yb[(long)r * ldy + cN],       v0, v1);
            store2(&Yb[(long)(r + 8) * ldy + cN], v2, v3);
        }
}

// =====================================================================
// conv1 as GEMM (half weights): a1[b][oc][s] = silu(hst . w1 + b), transposed store
// =====================================================================
__global__ __launch_bounds__(256) void conv1_gemm(
        const __half* __restrict__ A, const __half* __restrict__ Bm,
        const float* __restrict__ bias, float* __restrict__ Y) {
    __shared__ __align__(16) uint32_t As32[2 * 128 * 20];
    __shared__ __align__(16) uint32_t Bs32[2 * 64 * 20];

    int b = blockIdx.z;
    const __half* Ab = A + (long)b * SS * CCH;
    float* Yb = Y + (long)b * C8 * SS;
    int m0 = blockIdx.x * 128;

    int tid = threadIdx.x;
    int w = tid >> 5, lane = tid & 31;
    int wm = w & 3, wn = w >> 2;
    int g = lane >> 2, tig = lane & 3;
    int rbase = wm * 32, cbase = wn * 32;
    int lrow = lane & 7, lmat = lane >> 3;
    int fr_row = (lmat & 1) * 8 + lrow;
    int fr_col = (lmat >> 1) * 4;
    uint32_t As_b = cvsm(As32), Bs_b = cvsm(Bs32);

    float acc[2][4][4];
    #pragma unroll
    for (int i = 0; i < 2; i++)
        #pragma unroll
        for (int j = 0; j < 4; j++)
            #pragma unroll
            for (int l = 0; l < 4; l++) acc[i][j][l] = 0.f;

    uint4 aR[2], bR;
    int w4 = (tid & 3) * 4, mb = tid >> 2;

    auto ldg = [&](int k0) {
        #pragma unroll
        for (int it = 0; it < 2; it++)
            aR[it] = *(const uint4*)&Ab[(long)(m0 + mb + it * 64) * CCH + k0 + w4 * 2];
        bR = *(const uint4*)&Bm[(long)mb * 512 + k0 + w4 * 2];
    };
    auto sts = [&](int p) {
        uint32_t* Ad = As32 + p * 2560;
        uint32_t* Bd = Bs32 + p * 1280;
        #pragma unroll
        for (int it = 0; it < 2; it++)
            *(uint4*)&Ad[(mb + it * 64) * 20 + w4] = aR[it];
        *(uint4*)&Bd[mb * 20 + w4] = bR;
    };

    ldg(0); sts(0);
    __syncthreads();
    for (int k0 = 0; k0 < 512; k0 += 32) {
        int p = (k0 >> 5) & 1;
        bool more = (k0 + 32 < 512);
        if (more) ldg(k0 + 32);

        uint32_t Ap = As_b + (uint32_t)p * 2560 * 4;
        uint32_t Bp = Bs_b + (uint32_t)p * 1280 * 4;
        #pragma unroll
        for (int ks = 0; ks < 2; ks++) {
            int kw = ks * 8;
            uint32_t af[2][4], bf[4][2];
            #pragma unroll
            for (int mt = 0; mt < 2; mt++) {
                int r0 = rbase + mt * 16;
                ldsm_x4(af[mt][0], af[mt][1], af[mt][2], af[mt][3],
                        Ap + (uint32_t)(((r0 + fr_row) * 20) + kw + fr_col) * 4);
            }
            ldsm_x4(bf[0][0], bf[1][0], bf[2][0], bf[3][0],
                    Bp + (uint32_t)(((cbase + lmat * 8 + lrow) * 20) + kw) * 4);
            ldsm_x4(bf[0][1], bf[1][1], bf[2][1], bf[3][1],
                    Bp + (uint32_t)(((cbase + lmat * 8 + lrow) * 20) + kw + 4) * 4);
            #pragma unroll
            for (int mt = 0; mt < 2; mt++)
                #pragma unroll
                for (int nt = 0; nt < 4; nt++)
                    MMA16(acc[mt][nt], af[mt][0], af[mt][1], af[mt][2], af[mt][3],
                          bf[nt][0], bf[nt][1]);
        }
        if (more) sts(p ^ 1);
        __syncthreads();
    }

    #pragma unroll
    for (int mt = 0; mt < 2; mt++)
        #pragma unroll
        for (int nt = 0; nt < 4; nt++) {
            int r = m0 + rbase + mt * 16 + g;
            int cN = cbase + nt * 8 + 2 * tig;
            float b0 = bias[cN], b1 = bias[cN + 1];
            Yb[(long)cN * SS + r]           = silu_f(acc[mt][nt][0] + b0);
            Yb[(long)(cN + 1) * SS + r]     = silu_f(acc[mt][nt][1] + b1);
            Yb[(long)cN * SS + r + 8]       = silu_f(acc[mt][nt][2] + b0);
            Yb[(long)(cN + 1) * SS + r + 8] = silu_f(acc[mt][nt][3] + b1);
        }
}

// =====================================================================
// Merged flash attention, K/V register-prefetched.
// =====================================================================
#define FL_WORDS 15872

__device__ __forceinline__ void flash_std_body(
        const __half* __restrict__ Q, const __half* __restrict__ K,
        const __half* __restrict__ V, __half* __restrict__ O,
        int bh, int xq, uint32_t* smw) {
    uint32_t* Qs = smw;
    uint32_t* KP = smw + 128 * 36;
    uint32_t* Vs = smw + 2 * 128 * 36;
    float* redm = (float*)(smw + 2 * 128 * 36 + 64 * 36);
    float* redl = redm + 256;

    int b = bh >> 3, h = bh & 7;
    const __half* Qb = Q + (long)b * SS * CCH + h * 64;
    const __half* Kb = K + (long)b * SS * CCH + h * 64;
    const __half* Vb = V + (long)b * SS * CCH + h * 64;
    __half* Ob = O + (long)b * SS * (2 * CCH) + h * 64;
    int q0 = xq * 128;

    int tid = threadIdx.x;
    int w = tid >> 5, lane = tid & 31;
    int wm = w & 3, wn = w >> 2;
    int g = lane >> 2, tig = lane & 3;
    int rbase = wm * 32, cbase = wn * 32;
    int lrow = lane & 7, lmat = lane >> 3;
    int fr_row = (lmat & 1) * 8 + lrow;
    int fr_col = (lmat >> 1) * 4;
    int t_kb = lmat >> 1, t_hb = lmat & 1;
    uint32_t Qs_b = cvsm(Qs), KP_b = cvsm(KP), Vs_b = cvsm(Vs);

    #pragma unroll
    for (int f = 0; f < 4; f++) {
        int idx = tid + f * 256;
        int r = idx >> 3, w4 = (idx & 7) * 4;
        uint4 v4 = *(const uint4*)&Qb[(long)(q0 + r) * CCH + (idx & 7) * 8];
        *(uint4*)&Qs[r * 36 + w4] = v4;
    }

    uint4 kR[2], vR[2];
    int st_r = tid >> 3, st_w4 = (tid & 7) * 4, st_c = (tid & 7) * 8;
    auto ldg_kv = [&](int j) {
        #pragma unroll
        for (int f = 0; f < 2; f++) {
            long goff = (long)(j * 64 + st_r + f * 32) * CCH + st_c;
            kR[f] = *(const uint4*)&Kb[goff];
            vR[f] = *(const uint4*)&Vb[goff];
        }
    };
    auto sts_kv = [&]() {
        #pragma unroll
        for (int f = 0; f < 2; f++) {
            *(uint4*)&KP[(st_r + f * 32) * 36 + st_w4] = kR[f];
            *(uint4*)&Vs[(st_r + f * 32) * 36 + st_w4] = vR[f];
        }
    };

    float accO[2][4][4];
    #pragma unroll
    for (int i = 0; i < 2; i++)
        #pragma unroll
        for (int j = 0; j < 4; j++)
            #pragma unroll
            for (int l = 0; l < 4; l++) accO[i][j][l] = 0.f;
    float mst[4] = { -1e30f, -1e30f, -1e30f, -1e30f };
    float lst[4] = { 0.f, 0.f, 0.f, 0.f };

    ldg_kv(0);
    for (int j = 0; j < 16; j++) {
        sts_kv();
        __syncthreads();
        if (j + 1 < 16) ldg_kv(j + 1);

        float acc[2][4][4];
        #pragma unroll
        for (int i = 0; i < 2; i++)
            #pragma unroll
            for (int jj = 0; jj < 4; jj++)
                #pragma unroll
                for (int l = 0; l < 4; l++) acc[i][jj][l] = 0.f;
        #pragma unroll
        for (int ks = 0; ks < 4; ks++) {
            int kw = ks * 8;
            uint32_t af[2][4], bf[4][2];
            #pragma unroll
            for (int mt = 0; mt < 2; mt++) {
                int r0 = rbase + mt * 16;
                ldsm_x4(af[mt][0], af[mt][1], af[mt][2], af[mt][3],
                        Qs_b + (uint32_t)(((r0 + fr_row) * 36) + kw + fr_col) * 4);
            }
            ldsm_x4(bf[0][0], bf[1][0], bf[2][0], bf[3][0],
                    KP_b + (uint32_t)(((cbase + lmat * 8 + lrow) * 36) + kw) * 4);
            ldsm_x4(bf[0][1], bf[1][1], bf[2][1], bf[3][1],
                    KP_b + (uint32_t)(((cbase + lmat * 8 + lrow) * 36) + kw + 4) * 4);
            #pragma unroll
            for (int mt = 0; mt < 2; mt++)
                #pragma unroll
                for (int nt = 0; nt < 4; nt++)
                    MMA16(acc[mt][nt], af[mt][0], af[mt][1], af[mt][2], af[mt][3],
                          bf[nt][0], bf[nt][1]);
        }

        #pragma unroll
        for (int mt = 0; mt < 2; mt++)
            #pragma unroll
            for (int hh = 0; hh < 2; hh++) {
                float mx = -1e30f;
                #pragma unroll
                for (int nt = 0; nt < 4; nt++) {
                    mx = fmaxf(mx, acc[mt][nt][hh * 2]);
                    mx = fmaxf(mx, acc[mt][nt][hh * 2 + 1]);
                }
                mx = fmaxf(mx, __shfl_xor_sync(0xffffffffu, mx, 1));
                mx = fmaxf(mx, __shfl_xor_sync(0xffffffffu, mx, 2));
                if (tig == 0) redm[wn * 128 + rbase + mt * 16 + hh * 8 + g] = mx;
            }
        __syncthreads();

        #pragma unroll
        for (int mt = 0; mt < 2; mt++)
            #pragma unroll
            for (int hh = 0; hh < 2; hh++) {
                int i = mt * 2 + hh;
                int rloc = rbase + mt * 16 + hh * 8 + g;
                float mch = fmaxf(redm[rloc], redm[128 + rloc]);
                float mnew = fmaxf(mst[i], mch);
                float corr = __expf(mst[i] - mnew);
                mst[i] = mnew;
                float s = 0.f;
                #pragma unroll
                for (int nt = 0; nt < 4; nt++) {
                    float p0 = __expf(acc[mt][nt][hh * 2]     - mnew);
                    float p1 = __expf(acc[mt][nt][hh * 2 + 1] - mnew);
                    s += p0 + p1;
                    KP[rloc * 36 + wn * 16 + nt * 4 + tig] = pack2(p0, p1);
                    accO[mt][nt][hh * 2]     *= corr;
                    accO[mt][nt][hh * 2 + 1] *= corr;
                }
                s += __shfl_xor_sync(0xffffffffu, s, 1);
                s += __shfl_xor_sync(0xffffffffu, s, 2);
                if (tig == 0) redl[wn * 128 + rloc] = s;
                lst[i] *= corr;
            }
        __syncthreads();
        #pragma unroll
        for (int mt = 0; mt < 2; mt++)
            #pragma unroll
            for (int hh = 0; hh < 2; hh++) {
                int rloc = rbase + mt * 16 + hh * 8 + g;
                lst[mt * 2 + hh] += redl[rloc] + redl[128 + rloc];
            }

        #pragma unroll
        for (int ks = 0; ks < 4; ks++) {
            int kw = ks * 8;
            uint32_t af[2][4], bf[4][2];
            #pragma unroll
            for (int mt = 0; mt < 2; mt++) {
                int r0 = rbase + mt * 16;
                ldsm_x4(af[mt][0], af[mt][1], af[mt][2], af[mt][3],
                        KP_b + (uint32_t)(((r0 + fr_row) * 36) + kw + fr_col) * 4);
            }
            uint32_t vaddr = Vs_b + (uint32_t)((ks * 16 + t_kb * 8 + lrow) * 144
                                               + (cbase + t_hb * 8) * 2);
            ldsm_x4_t(bf[0][0], bf[1][0], bf[0][1], bf[1][1], vaddr);
            ldsm_x4_t(bf[2][0], bf[3][0], bf[2][1], bf[3][1], vaddr + 32);
            #pragma unroll
            for (int mt = 0; mt < 2; mt++)
                #pragma unroll
                for (int nt = 0; nt < 4; nt++)
                    MMA16(accO[mt][nt], af[mt][0], af[mt][1], af[mt][2], af[mt][3],
                          bf[nt][0], bf[nt][1]);
        }
        __syncthreads();
    }

    #pragma unroll
    for (int mt = 0; mt < 2; mt++) {
        float inv0 = 1.0f / lst[mt * 2];
        float inv1 = 1.0f / lst[mt * 2 + 1];
        #pragma unroll
        for (int nt = 0; nt < 4; nt++) {
            int r = q0 + rbase + mt * 16 + g;
            int c = cbase + nt * 8 + 2 * tig;
            store2(&Ob[(long)r * 1024 + c],       accO[mt][nt][0] * inv0, accO[mt][nt][1] * inv0);
            store2(&Ob[(long)(r + 8) * 1024 + c], accO[mt][nt][2] * inv1, accO[mt][nt][3] * inv1);
        }
    }
}

__device__ __forceinline__ void flash_multi_body(
        const __half* __restrict__ Q, const __half* __restrict__ K,
        const __half* __restrict__ V, __half* __restrict__ O,
        int z, int xq, uint32_t* smw) {
    uint32_t* Qs = smw;
    uint32_t* Ks = smw + 8448;
    uint32_t* Ps = smw + 8448 + 2304;
    uint32_t* Vs = smw + 8448 + 2 * 2304;
    float* redm = (float*)(smw + 8448 + 3 * 2304);
    float* redl = redm + 256;

    const __half* Qb = Q + (long)z * SS * C2;
    const __half* Kb = K + (long)z * SS * C2;
    const __half* Vb = V + (long)z * SS * C2;
    int br = z >> 3, b = z & 7;
    __half* Ob = O + (long)b * SS * 1024 + 512 + br * 256;
    int q0 = xq * 64;

    int tid = threadIdx.x;
    int w = tid >> 5, lane = tid & 31;
    int wm = w & 1, wn = w >> 1;
    int g = lane >> 2, tig = lane & 3;
    int rbase = wm * 32;
    int lrow = lane & 7, lmat = lane >> 3;
    int fr_row = (lmat & 1) * 8 + lrow;
    int fr_col = (lmat >> 1) * 4;
    int t_kb = lmat >> 1, t_hb = lmat & 1;
    uint32_t Qs_b = cvsm(Qs), Ks_b = cvsm(Ks), Ps_b = cvsm(Ps), Vs_b = cvsm(Vs);

    #pragma unroll
    for (int f = 0; f < 8; f++) {
        int idx = tid + f * 256;
        int r = idx >> 5, c8 = idx & 31;
        uint4 qv = *(const uint4*)&Qb[(long)(q0 + r) * C2 + c8 * 8];
        *(uint4*)&Qs[r * 132 + c8 * 4] = qv;
    }

    int st_r = tid >> 3, st_w4 = (tid & 7) * 4, st_c = (tid & 7) * 8;
    uint4 sR[2];
    auto ldg_s = [&](const __half* P, int j, int dc) {
        #pragma unroll
        for (int f = 0; f < 2; f++)
            sR[f] = *(const uint4*)&P[(long)(j * 64 + st_r + f * 32) * C2 + dc * 64 + st_c];
    };
    auto sts_s = [&](uint32_t* D) {
        #pragma unroll
        for (int f = 0; f < 2; f++)
            *(uint4*)&D[(st_r + f * 32) * 36 + st_w4] = sR[f];
    };

    float accO[2][8][4];
    #pragma unroll
    for (int i = 0; i < 2; i++)
        #pragma unroll
        for (int j = 0; j < 8; j++)
            #pragma unroll
            for (int l = 0; l < 4; l++) accO[i][j][l] = 0.f;
    float mst[4] = { -1e30f, -1e30f, -1e30f, -1e30f };
    float lst[4] = { 0.f, 0.f, 0.f, 0.f };

    for (int j = 0; j < 16; j++) {
        float acc[2][2][4];
        #pragma unroll
        for (int i = 0; i < 2; i++)
            #pragma unroll
            for (int jj = 0; jj < 2; jj++)
                #pragma unroll
                for (int l = 0; l < 4; l++) acc[i][jj][l] = 0.f;

        ldg_s(Kb, j, 0);
        for (int dc = 0; dc < 4; dc++) {
            sts_s(Ks);
            __syncthreads();
            if (dc < 3) ldg_s(Kb, j, dc + 1);
            #pragma unroll
            for (int ks = 0; ks < 4; ks++) {
                int kw = ks * 8;
                uint32_t af[2][4], bf[2][2];
                #pragma unroll
                for (int mt = 0; mt < 2; mt++) {
                    int r0 = rbase + mt * 16;
                    ldsm_x4(af[mt][0], af[mt][1], af[mt][2], af[mt][3],
                            Qs_b + (uint32_t)(((r0 + fr_row) * 132) + dc * 32 + kw + fr_col) * 4);
                }
                ldsm_x4(bf[0][0], bf[1][0], bf[0][1], bf[1][1],
                        Ks_b + (uint32_t)(((wn * 16 + fr_row) * 36) + kw + fr_col) * 4);
                #pragma unroll
                for (int mt = 0; mt < 2; mt++)
                    #pragma unroll
                    for (int nt = 0; nt < 2; nt++)
                        MMA16(acc[mt][nt], af[mt][0], af[mt][1], af[mt][2], af[mt][3],
                              bf[nt][0], bf[nt][1]);
            }
            __syncthreads();
        }

        #pragma unroll
        for (int mt = 0; mt < 2; mt++)
            #pragma unroll
            for (int hh = 0; hh < 2; hh++) {
                float mx = -1e30f;
                #pragma unroll
                for (int nt = 0; nt < 2; nt++) {
                    mx = fmaxf(mx, acc[mt][nt][hh * 2]);
                    mx = fmaxf(mx, acc[mt][nt][hh * 2 + 1]);
                }
                mx = fmaxf(mx, __shfl_xor_sync(0xffffffffu, mx, 1));
                mx = fmaxf(mx, __shfl_xor_sync(0xffffffffu, mx, 2));
                if (tig == 0) redm[wn * 64 + rbase + mt * 16 + hh * 8 + g] = mx;
            }
        __syncthreads();

        #pragma unroll
        for (int mt = 0; mt < 2; mt++)
            #pragma unroll
            for (int hh = 0; hh < 2; hh++) {
                int i = mt * 2 + hh;
                int rloc = rbase + mt * 16 + hh * 8 + g;
                float mch = fmaxf(fmaxf(redm[rloc], redm[64 + rloc]),
                                  fmaxf(redm[128 + rloc], redm[192 + rloc]));
                float mnew = fmaxf(mst[i], mch);
                float corr = __expf(mst[i] - mnew);
                mst[i] = mnew;
                float s = 0.f;
                #pragma unroll
                for (int nt = 0; nt < 2; nt++) {
                    float p0 = __expf(acc[mt][nt][hh * 2]     - mnew);
                    float p1 = __expf(acc[mt][nt][hh * 2 + 1] - mnew);
                    s += p0 + p1;
                    Ps[rloc * 36 + wn * 8 + nt * 4 + tig] = pack2(p0, p1);
                }
                s += __shfl_xor_sync(0xffffffffu, s, 1);
                s += __shfl_xor_sync(0xffffffffu, s, 2);
                if (tig == 0) redl[wn * 64 + rloc] = s;
                lst[i] *= corr;
                #pragma unroll
                for (int nt = 0; nt < 8; nt++) {
                    accO[mt][nt][hh * 2]     *= corr;
                    accO[mt][nt][hh * 2 + 1] *= corr;
                }
            }
        __syncthreads();
        #pragma unroll
        for (int mt = 0; mt < 2; mt++)
            #pragma unroll
            for (int hh = 0; hh < 2; hh++) {
                int rloc = rbase + mt * 16 + hh * 8 + g;
                lst[mt * 2 + hh] += redl[rloc] + redl[64 + rloc]
                                  + redl[128 + rloc] + redl[192 + rloc];
            }

        ldg_s(Vb, j, 0);
        for (int dc = 0; dc < 4; dc++) {
            sts_s(Vs);
            __syncthreads();
            if (dc < 3) ldg_s(Vb, j, dc + 1);
            #pragma unroll
            for (int ks = 0; ks < 4; ks++) {
                int kw = ks * 8;
                uint32_t af[2][4], bf[2][2];
                #pragma unroll
                for (int mt = 0; mt < 2; mt++) {
                    int r0 = rbase + mt * 16;
                    ldsm_x4(af[mt][0], af[mt][1], af[mt][2], af[mt][3],
                            Ps_b + (uint32_t)(((r0 + fr_row) * 36) + kw + fr_col) * 4);
                }
                uint32_t vaddr = Vs_b + (uint32_t)((ks * 16 + t_kb * 8 + lrow) * 144
                                                   + (wn * 16 + t_hb * 8) * 2);
                ldsm_x4_t(bf[0][0], bf[1][0], bf[0][1], bf[1][1], vaddr);
                #pragma unroll
                for (int mt = 0; mt < 2; mt++)
                    #pragma unroll
                    for (int nt = 0; nt < 2; nt++)
                        MMA16(accO[mt][dc * 2 + nt], af[mt][0], af[mt][1], af[mt][2], af[mt][3],
                              bf[nt][0], bf[nt][1]);
            }
            __syncthreads();
        }
    }

    #pragma unroll
    for (int mt = 0; mt < 2; mt++) {
        float inv0 = 1.0f / lst[mt * 2];
        float inv1 = 1.0f / lst[mt * 2 + 1];
        #pragma unroll
        for (int u = 0; u < 8; u++) {
            int dc = u >> 1, nt = u & 1;
            int r = q0 + rbase + mt * 16 + g;
            int c = dc * 64 + wn * 16 + nt * 8 + 2 * tig;
            store2(&Ob[(long)r * 1024 + c],       accO[mt][u][0] * inv0, accO[mt][u][1] * inv0);
            store2(&Ob[(long)(r + 8) * 1024 + c], accO[mt][u][2] * inv1, accO[mt][u][3] * inv1);
        }
    }
}

__global__ __launch_bounds__(256, 2) void flash_all(
        const __half* __restrict__ q, const __half* __restrict__ k,
        const __half* __restrict__ v,
        const __half* __restrict__ qm, const __half* __restrict__ km,
        const __half* __restrict__ vm, __half* __restrict__ comb) {
    extern __shared__ uint32_t smw[];
    int bx = blockIdx.x;
    if (bx < 512) flash_std_body(q, k, v, comb, bx >> 3, bx & 7, smw);
    else { int i = bx - 512; flash_multi_body(qm, km, vm, comb, i >> 4, i & 15, smw); }
}

// ---------------- conv 3x3 (64 -> 64, SAME) + SiLU ----------------
__global__ void conv2_silu(const float* __restrict__ x, const float* __restrict__ w,
                           const float* __restrict__ bias, float* __restrict__ y) {
    __shared__ float ws[8 * 576];
    int tid = threadIdx.x;
    int o0 = blockIdx.y * 8, b = blockIdx.z;
    for (int i = tid; i < 8 * 576; i += 256) ws[i] = w[(long)o0 * 576 + i];
    __syncthreads();
    int s = blockIdx.x * 256 + tid;
    int yy = s >> 5, xx = s & 31;
    float acc[8];
    #pragma unroll
    for (int oo = 0; oo < 8; oo++) acc[oo] = bias[o0 + oo];
    const float* xb = x + (long)b * C8 * SS;
    for (int ci = 0; ci < 64; ci++) {
        #pragma unroll
        for (int ky = 0; ky < 3; ky++) {
            int py = yy + ky - 1;
            if (py < 0 || py >= 32) continue;
            #pragma unroll
            for (int kx = 0; kx < 3; kx++) {
                int px = xx + kx - 1;
                if (px < 0 || px >= 32) continue;
                float av = xb[(long)ci * SS + py * 32 + px];
                #pragma unroll
                for (int oo = 0; oo < 8; oo++)
                    acc[oo] += av * ws[oo * 576 + ci * 9 + ky * 3 + kx];
            }
        }
    }
    #pragma unroll
    for (int oo = 0; oo < 8; oo++)
        y[(long)b * C8 * SS + (long)(o0 + oo) * SS + s] = silu_f(acc[oo]);
}

// ---------------- conv 1x1 (64 -> 1) + sigmoid ----------------
__global__ void conv3_sig(const float* __restrict__ x, const float* __restrict__ w,
                          const float* __restrict__ bias, float* __restrict__ y) {
    int idx = blockIdx.x * 256 + threadIdx.x;
    int b = idx >> 10, s = idx & 1023;
    float acc = bias[0];
    const float* xb = x + (long)b * C8 * SS + s;
    #pragma unroll 8
    for (int i = 0; i < 64; i++) acc += xb[(long)i * SS] * w[i];
    y[idx] = 1.0f / (1.0f + expf(-acc));
}

// ---------------- senh_t = hs_t * sw ----------------
__global__ void senh_t_mul(const __half* __restrict__ hs_t, const float* __restrict__ sw,
                           __half* __restrict__ senh_t) {
    int idx = blockIdx.x * 256 + threadIdx.x;
    int token = idx >> 6, c8 = idx & 63;
    __half2 m = __float2half2_rn(sw[token]);
    uint4 v = *(const uint4*)&hs_t[(long)token * CCH + c8 * 8];
    __half2* h = (__half2*)&v;
    h[0] = __hmul2(h[0], m); h[1] = __hmul2(h[1], m);
    h[2] = __hmul2(h[2], m); h[3] = __hmul2(h[3], m);
    *(uint4*)&senh_t[(long)token * CCH + c8 * 8] = v;
}

// ---------------- launch ----------------
static void* symv(const void* s) { void* p = nullptr; cudaGetSymbolAddress(&p, s); return p; }

extern "C" void kernel_launch(void* const* d_in, const int* in_sizes, int n_in,
                              void* d_out, int out_size) {
    (void)in_sizes; (void)n_in; (void)out_size;
    const float* x      = (const float*)d_in[0];
    const float* pre_g  = (const float*)d_in[1];
    const float* pre_b  = (const float*)d_in[2];
    const float* norm_g = (const float*)d_in[3];
    const float* norm_b = (const float*)d_in[4];
    const float* post_g = (const float*)d_in[5];
    const float* post_b = (const float*)d_in[6];
    const float* pos    = (const float*)d_in[7];
    const float* sa_w1  = (const float*)d_in[8];
    const float* sa_b1  = (const float*)d_in[9];
    const float* sa_w2  = (const float*)d_in[10];
    const float* sa_b2  = (const float*)d_in[11];
    const float* sa_w3  = (const float*)d_in[12];
    const float* sa_b3  = (const float*)d_in[13];
    const float* wq     = (const float*)d_in[14];
    const float* wk     = (const float*)d_in[15];
    const float* wv     = (const float*)d_in[16];
    const float* wq0    = (const float*)d_in[17];
    const float* wk0    = (const float*)d_in[18];
    const float* wv0    = (const float*)d_in[19];
    const float* wq1    = (const float*)d_in[20];
    const float* wk1    = (const float*)d_in[21];
    const float* wv1    = (const float*)d_in[22];
    const float* ff_w1  = (const float*)d_in[23];
    const float* ff_b1  = (const float*)d_in[24];
    const float* ff_w2  = (const float*)d_in[25];
    const float* ff_b2  = (const float*)d_in[26];
    const float* out_w  = (const float*)d_in[27];
    const float* out_b  = (const float*)d_in[28];
    float* out = (float*)d_out;

    float  *hs = (float*)symv(d_hs);
    __half *hst = (__half*)symv(d_hst), *shnt = (__half*)symv(d_shnt), *senht = (__half*)symv(d_senht);
    float  *a1 = (float*)symv(d_a1), *a2 = (float*)symv(d_a2), *sw = (float*)symv(d_swt);
    __half *q = (__half*)symv(d_q), *k = (__half*)symv(d_k), *v = (__half*)symv(d_v);
    __half *qm = (__half*)symv(d_qm), *km = (__half*)symv(d_km), *vm = (__half*)symv(d_vm);
    __half *comb = (__half*)symv(d_comb), *f1 = (__half*)symv(d_f1), *fus = (__half*)symv(d_fus);
    float  *fin = (float*)symv(d_fin);
    __half *wb = (__half*)symv(d_w);

    const int flSmem = FL_WORDS * 4;
    cudaFuncSetAttribute(flash_all, cudaFuncAttributeMaxDynamicSharedMemorySize, flSmem);
    const int gnSmem = 16 * 1024 * 4;
    cudaFuncSetAttribute(gn_fused, cudaFuncAttributeMaxDynamicSharedMemorySize, gnSmem);

    // weight conversion: offsets into d_w
    const float* wsrc[13] = { wq, wk, wv, wq0, wk0, wv0, wq1, wk1, wv1,
                              ff_w1, ff_w2, out_w, sa_w1 };
    const int wcnt[13] = { 262144, 262144, 262144, 131072, 131072, 131072,
                           131072, 131072, 131072, 524288, 262144, 262144, 32768 };
    WC wc; int off = 0;
    __half* hw[13];
    for (int i = 0; i < 13; i++) {
        wc.src[i] = wsrc[i]; wc.cnt4[i] = wcnt[i] / 4; wc.off[i] = off;
        hw[i] = wb + off;
        off += wcnt[i];
    }
    wcvt<<<dim3(512, 13), 256>>>(wc, wb);

    gn_fused<<<BATCH * NGR, 256, gnSmem>>>(x, pre_g, pre_b, pos, norm_g, norm_b,
                                           hs, hst, shnt);
    conv1_gemm<<<dim3(8, 1, BATCH), 256>>>(hst, hw[12], sa_b1, a1);
    conv2_silu<<<dim3(4, 8, BATCH), 256>>>(a1, sa_w2, sa_b2, a2);
    conv3_sig<<<BATCH * SS / 256, 256>>>(a2, sa_w3, sa_b3, sw);
    senh_t_mul<<<BATCH * SS * CCH / 8 / 256, 256>>>(hst, sw, senht);

    // QKV projections (q pre-scaled by 1/8)
    GArg pq = {};
    pq.A[0] = shnt; pq.A[1] = shnt; pq.A[2] = shnt;
    pq.W[0] = hw[0]; pq.W[1] = hw[1]; pq.W[2] = hw[2];
    pq.Y[0] = q;    pq.Y[1] = k;    pq.Y[2] = v;
    pq.bias[0] = pq.bias[1] = pq.bias[2] = nullptr;
    pq.sc[0] = 0.125f; pq.sc[1] = 1.f; pq.sc[2] = 1.f;
    pq.aOuter = (long)SS * CCH; pq.yOuter = (long)SS * 512;
    pq.K = 512; pq.lda = 512; pq.N = 512; pq.ldy = 512; pq.act = 0;
    gemm128<__half><<<dim3(8, 4, 24), 256>>>(pq);

    // multi-scale projections (qm pre-scaled by 1/16)
    long moff = 8LL * SS * C2;
    GArg pm = {};
    pm.A[0] = senht; pm.A[1] = shnt; pm.A[2] = shnt;
    pm.A[3] = senht; pm.A[4] = shnt; pm.A[5] = shnt;
    pm.W[0] = hw[3]; pm.W[1] = hw[4]; pm.W[2] = hw[5];
    pm.W[3] = hw[6]; pm.W[4] = hw[7]; pm.W[5] = hw[8];
    pm.Y[0] = qm;        pm.Y[1] = km;        pm.Y[2] = vm;
    pm.Y[3] = qm + moff; pm.Y[4] = km + moff; pm.Y[5] = vm + moff;
    for (int i = 0; i < 6; i++) pm.bias[i] = nullptr;
    pm.sc[0] = 0.0625f; pm.sc[1] = 1.f; pm.sc[2] = 1.f;
    pm.sc[3] = 0.0625f; pm.sc[4] = 1.f; pm.sc[5] = 1.f;
    pm.aOuter = (long)SS * CCH; pm.yOuter = (long)SS * C2;
    pm.K = 512; pm.lda = 512; pm.N = 256; pm.ldy = 256; pm.act = 0;
    gemm128<__half><<<dim3(8, 2, 48), 256>>>(pm);

    // merged flash
    flash_all<<<768, 256, flSmem>>>(q, k, v, qm, km, vm, comb);

    // ff1 (silu)
    GArg f1a = {};
    f1a.A[0] = comb; f1a.W[0] = hw[9]; f1a.Y[0] = f1; f1a.bias[0] = ff_b1;
    f1a.sc[0] = 1.f;
    f1a.aOuter = (long)SS * 2 * CCH; f1a.yOuter = (long)SS * CCH;
    f1a.K = 1024; f1a.lda = 1024; f1a.N = 512; f1a.ldy = 512; f1a.act = 1;
    gemm128<__half><<<dim3(8, 4, 8), 256>>>(f1a);
    // ff2
    GArg f2a = {};
    f2a.A[0] = f1; f2a.W[0] = hw[10]; f2a.Y[0] = fus; f2a.bias[0] = ff_b2;
    f2a.sc[0] = 1.f;
    f2a.aOuter = (long)SS * CCH; f2a.yOuter = (long)SS * CCH;
    f2a.K = 512; f2a.lda = 512; f2a.N = 512; f2a.ldy = 512; f2a.act = 0;
    gemm128<__half><<<dim3(8, 4, 8), 256>>>(f2a);
    // out proj
    GArg oa = {};
    oa.A[0] = fus; oa.W[0] = hw[11]; oa.Y[0] = fin; oa.bias[0] = out_b;
    oa.sc[0] = 1.f;
    oa.aOuter = (long)SS * CCH; oa.yOuter = (long)SS * CCH;
    oa.K = 512; oa.lda = 512; oa.N = 512; oa.ldy = 512; oa.act = 0;
    gemm128<float><<<dim3(8, 4, 8), 256>>>(oa);

    // post GN + residual
    gn_post_k<<<BATCH * NGR, 256>>>(fin, post_g, post_b, x, out);
}

// round 13
// speedup vs baseline: 1.1113x; 1.1113x over previous
#include <cuda_runtime.h>
#include <cuda_fp16.h>
#include <math.h>
#include <stdint.h>

#define BATCH 8
#define CCH 512
#define SS 1024
#define NHD 8
#define NGR 32
#define CG 16
#define C8 64
#define C2 256
#define GEPS 1e-6f

// ---------------- static scratch ----------------
__device__ __half d_hst  [BATCH*SS*CCH];
__device__ __half d_shnt [BATCH*SS*CCH];
__device__ __half d_senht[BATCH*SS*CCH];
__device__ __half d_a1t  [BATCH*SS*C8];
__device__ __half d_a2t  [BATCH*SS*C8];
__device__ float  d_swt  [BATCH*SS];
__device__ __half d_q    [BATCH*SS*CCH];
__device__ __half d_k    [BATCH*SS*CCH];
__device__ __half d_v    [BATCH*SS*CCH];
__device__ __half d_qm   [2*BATCH*SS*C2];
__device__ __half d_km   [2*BATCH*SS*C2];
__device__ __half d_vm   [2*BATCH*SS*C2];
__device__ __half d_comb [BATCH*SS*2*CCH];
__device__ __half d_f1   [BATCH*SS*CCH];
__device__ __half d_fus  [BATCH*SS*CCH];
__device__ float  d_fin  [BATCH*SS*CCH];
__device__ __half d_w    [2654208];
__device__ __half d_w2   [36864];

// ---------------- helpers ----------------
__device__ __forceinline__ float blk_sum(float v, float* sb, int tid) {
    sb[tid] = v; __syncthreads();
    for (int o = 128; o > 0; o >>= 1) { if (tid < o) sb[tid] += sb[tid + o]; __syncthreads(); }
    float r = sb[0]; __syncthreads(); return r;
}
__device__ __forceinline__ float silu_f(float x) { return x / (1.0f + expf(-x)); }
__device__ __forceinline__ uint32_t pack2(float a, float b) {
    __half2 h = __floats2half2_rn(a, b);
    return *reinterpret_cast<uint32_t*>(&h);
}
__device__ __forceinline__ void store2(float* p, float a, float b) {
    *(float2*)p = make_float2(a, b);
}
__device__ __forceinline__ void store2(__half* p, float a, float b) {
    *(uint32_t*)p = pack2(a, b);
}
__device__ __forceinline__ uint32_t cvsm(const void* p) {
    return (uint32_t)__cvta_generic_to_shared(p);
}
__device__ __forceinline__ void ldsm_x4(uint32_t& r0, uint32_t& r1, uint32_t& r2,
                                        uint32_t& r3, uint32_t addr) {
    asm volatile("ldmatrix.sync.aligned.m8n8.x4.shared.b16 {%0,%1,%2,%3}, [%4];"
        : "=r"(r0), "=r"(r1), "=r"(r2), "=r"(r3) : "r"(addr));
}
__device__ __forceinline__ void ldsm_x4_t(uint32_t& r0, uint32_t& r1, uint32_t& r2,
                                          uint32_t& r3, uint32_t addr) {
    asm volatile("ldmatrix.sync.aligned.m8n8.x4.trans.shared.b16 {%0,%1,%2,%3}, [%4];"
        : "=r"(r0), "=r"(r1), "=r"(r2), "=r"(r3) : "r"(addr));
}

#define MMA16(d, a0, a1, a2, a3, b0, b1) \
    asm volatile("mma.sync.aligned.m16n8k16.row.col.f32.f16.f16.f32 " \
        "{%0,%1,%2,%3},{%4,%5,%6,%7},{%8,%9},{%0,%1,%2,%3};" \
        : "+f"((d)[0]), "+f"((d)[1]), "+f"((d)[2]), "+f"((d)[3]) \
        : "r"(a0), "r"(a1), "r"(a2), "r"(a3), "r"(b0), "r"(b1))

// ---------------- weight conversion fp32 -> half ----------------
struct WC { const float* src[13]; int cnt4[13]; int off[13]; };
__global__ void wcvt(WC wc, __half* dst) {
    int which = blockIdx.y;
    int idx = blockIdx.x * 256 + threadIdx.x;
    if (idx < wc.cnt4[which]) {
        float4 v = *(const float4*)&wc.src[which][idx * 4];
        uint2 pk = make_uint2(pack2(v.x, v.y), pack2(v.z, v.w));
        *(uint2*)&dst[wc.off[which] + idx * 4] = pk;
    }
}
// w2: [oc][ci][tap] -> [oc][tap*64+ci]
__global__ void w2cvt(const float* __restrict__ src, __half* __restrict__ dst) {
    int idx = blockIdx.x * 256 + threadIdx.x;
    if (idx < 36864) {
        int oc = idx / 576, rem = idx % 576;
        int tap = rem >> 6, ci = rem & 63;
        dst[idx] = __float2half(src[oc * 576 + ci * 9 + tap]);
    }
}

// =====================================================================
// Fused double GroupNorm -> half token-major hs_t, shn_t (no fp32 hs).
// =====================================================================
__global__ void gn_fused(const float* __restrict__ x,
                         const float* __restrict__ pre_g, const float* __restrict__ pre_b,
                         const float* __restrict__ pos,
                         const float* __restrict__ norm_g, const float* __restrict__ norm_b,
                         __half* __restrict__ hs_t, __half* __restrict__ shn_t) {
    extern __shared__ float xs[];
    __shared__ float sb[256];
    __shared__ float pgs[16], pbs[16], ngs[16], nbs[16];

    int tid = threadIdx.x;
    int b = blockIdx.x / NGR, gi = blockIdx.x % NGR;
    long base = (long)b * CCH * SS + (long)gi * CG * SS;
    if (tid < 16) {
        int c = gi * 16 + tid;
        pgs[tid] = pre_g[c]; pbs[tid] = pre_b[c];
        ngs[tid] = norm_g[c]; nbs[tid] = norm_b[c];
    }

    float s1 = 0.f, s2 = 0.f;
    for (int i = tid; i < CG * SS; i += 256) {
        float v = x[base + i];
        xs[i] = v; s1 += v; s2 += v * v;
    }
    s1 = blk_sum(s1, sb, tid);
    s2 = blk_sum(s2, sb, tid);
    float mu1 = s1 / (float)(CG * SS);
    float inv1 = rsqrtf(s2 / (float)(CG * SS) - mu1 * mu1 + GEPS);

    float t1 = 0.f, t2 = 0.f;
    for (int i = tid; i < CG * SS; i += 256) {
        int cl = i >> 10, s = i & 1023;
        int c = gi * CG + cl;
        float h = (xs[i] - mu1) * inv1 * pgs[cl] + pbs[cl] + pos[(long)c * SS + s];
        xs[i] = h;
        t1 += h; t2 += h * h;
    }
    t1 = blk_sum(t1, sb, tid);
    t2 = blk_sum(t2, sb, tid);
    float mu2 = t1 / (float)(CG * SS);
    float inv2 = rsqrtf(t2 / (float)(CG * SS) - mu2 * mu2 + GEPS);

    long tbase = ((long)b * SS) * CCH + gi * 16;
    for (int s = tid; s < SS; s += 256) {
        uint32_t wh[8], wn[8];
        #pragma unroll
        for (int cl = 0; cl < 16; cl += 2) {
            float h0 = xs[cl * 1024 + s], h1 = xs[(cl + 1) * 1024 + s];
            wh[cl >> 1] = pack2(h0, h1);
            float n0 = (h0 - mu2) * inv2 * ngs[cl] + nbs[cl];
            float n1 = (h1 - mu2) * inv2 * ngs[cl + 1] + nbs[cl + 1];
            wn[cl >> 1] = pack2(n0, n1);
        }
        __half* ph = hs_t + tbase + (long)s * CCH;
        *(uint4*)ph       = make_uint4(wh[0], wh[1], wh[2], wh[3]);
        *(uint4*)(ph + 8) = make_uint4(wh[4], wh[5], wh[6], wh[7]);
        __half* pn = shn_t + tbase + (long)s * CCH;
        *(uint4*)pn       = make_uint4(wn[0], wn[1], wn[2], wn[3]);
        *(uint4*)(pn + 8) = make_uint4(wn[4], wn[5], wn[6], wn[7]);
    }
}

// ---------------- group norm token-major + residual ----------------
__global__ void gn_post_k(const float* __restrict__ xt, const float* __restrict__ g,
                          const float* __restrict__ be, const float* __restrict__ resid,
                          float* __restrict__ y) {
    __shared__ float sb[256];
    int tid = threadIdx.x;
    int b = blockIdx.x / NGR, gi = blockIdx.x % NGR;
    long tbase = (long)b * SS * CCH + gi * CG;
    float s1 = 0.f, s2 = 0.f;
    for (int i = tid; i < CG * SS; i += 256) {
        int s = i >> 4, cl = i & 15;
        float v = xt[tbase + (long)s * CCH + cl]; s1 += v; s2 += v * v;
    }
    s1 = blk_sum(s1, sb, tid);
    s2 = blk_sum(s2, sb, tid);
    float mu = s1 / (float)(CG * SS);
    float var = s2 / (float)(CG * SS) - mu * mu;
    float inv = rsqrtf(var + GEPS);
    for (int i = tid; i < CG * SS; i += 256) {
        int s = i >> 4, cl = i & 15;
        int c = gi * CG + cl;
        float v = (xt[tbase + (long)s * CCH + cl] - mu) * inv * g[c] + be[c];
        long oidx = (long)b * CCH * SS + (long)c * SS + s;
        y[oidx] = v + resid[oidx];
    }
}

// =====================================================================
// Unified fp16 GEMM (NT), 128x128 tile, half weights.
// =====================================================================
struct GArg {
    const __half* A[6]; const __half* W[6]; void* Y[6]; const float* bias[6];
    float sc[6];
    long aOuter, yOuter;
    int K, lda, N, ldy, act;
};

template<typename OutT>
__global__ __launch_bounds__(256, 2) void gemm128(GArg ga) {
    __shared__ __align__(16) uint32_t As32[2 * 128 * 20];
    __shared__ __align__(16) uint32_t Bs32[2 * 128 * 20];

    int z = blockIdx.z;
    int which = z >> 3, b = z & 7;
    const __half* Ab = ga.A[which] + (long)b * ga.aOuter;
    const __half* Bb = ga.W[which];
    OutT*         Yb = (OutT*)ga.Y[which] + (long)b * ga.yOuter;
    const float* bias = ga.bias[which];
    float scl = ga.sc[which];
    int K = ga.K, lda = ga.lda, ldy = ga.ldy, act = ga.act;
    int m0 = blockIdx.x * 128, n0 = blockIdx.y * 128;

    int tid = threadIdx.x;
    int w = tid >> 5, lane = tid & 31;
    int wm = w & 1, wn = w >> 1;
    int g = lane >> 2, tig = lane & 3;
    int rbase = wm * 64, cbase = wn * 32;
    int lrow = lane & 7, lmat = lane >> 3;
    int fr_row = (lmat & 1) * 8 + lrow;
    int fr_col = (lmat >> 1) * 4;
    uint32_t As_b = cvsm(As32), Bs_b = cvsm(Bs32);

    float acc[4][4][4];
    #pragma unroll
    for (int i = 0; i < 4; i++)
        #pragma unroll
        for (int j = 0; j < 4; j++)
            #pragma unroll
            for (int l = 0; l < 4; l++) acc[i][j][l] = 0.f;

    uint4 aR[2], bR[2];
    int w4 = (tid & 3) * 4, mb = tid >> 2;

    auto ldg = [&](int k0) {
        #pragma unroll
        for (int it = 0; it < 2; it++)
            aR[it] = *(const uint4*)&Ab[(long)(m0 + mb + it * 64) * lda + k0 + w4 * 2];
        #pragma unroll
        for (int it = 0; it < 2; it++)
            bR[it] = *(const uint4*)&Bb[(long)(n0 + mb + it * 64) * K + k0 + w4 * 2];
    };
    auto sts = [&](int p) {
        uint32_t* Ad = As32 + p * 2560;
        uint32_t* Bd = Bs32 + p * 2560;
        #pragma unroll
        for (int it = 0; it < 2; it++)
            *(uint4*)&Ad[(mb + it * 64) * 20 + w4] = aR[it];
        #pragma unroll
        for (int it = 0; it < 2; it++)
            *(uint4*)&Bd[(mb + it * 64) * 20 + w4] = bR[it];
    };

    ldg(0); sts(0);
    __syncthreads();
    for (int k0 = 0; k0 < K; k0 += 32) {
        int p = (k0 >> 5) & 1;
        bool more = (k0 + 32 < K);
        if (more) ldg(k0 + 32);

        uint32_t Ap = As_b + (uint32_t)p * 2560 * 4;
        uint32_t Bp = Bs_b + (uint32_t)p * 2560 * 4;
        #pragma unroll
        for (int ks = 0; ks < 2; ks++) {
            int kw = ks * 8;
            uint32_t af[4][4], bf[4][2];
            #pragma unroll
            for (int mt = 0; mt < 4; mt++) {
                int r0 = rbase + mt * 16;
                ldsm_x4(af[mt][0], af[mt][1], af[mt][2], af[mt][3],
                        Ap + (uint32_t)(((r0 + fr_row) * 20) + kw + fr_col) * 4);
            }
            ldsm_x4(bf[0][0], bf[1][0], bf[2][0], bf[3][0],
                    Bp + (uint32_t)(((cbase + lmat * 8 + lrow) * 20) + kw) * 4);
            ldsm_x4(bf[0][1], bf[1][1], bf[2][1], bf[3][1],
                    Bp + (uint32_t)(((cbase + lmat * 8 + lrow) * 20) + kw + 4) * 4);
            #pragma unroll
            for (int mt = 0; mt < 4; mt++)
                #pragma unroll
                for (int nt = 0; nt < 4; nt++)
                    MMA16(acc[mt][nt], af[mt][0], af[mt][1], af[mt][2], af[mt][3],
                          bf[nt][0], bf[nt][1]);
        }
        if (more) sts(p ^ 1);
        __syncthreads();
    }

    #pragma unroll
    for (int mt = 0; mt < 4; mt++)
        #pragma unroll
        for (int nt = 0; nt < 4; nt++) {
            int r = m0 + rbase + mt * 16 + g;
            int cN = n0 + cbase + nt * 8 + 2 * tig;
            float b0 = bias ? bias[cN] : 0.f;
            float b1 = bias ? bias[cN + 1] : 0.f;
            float v0 = acc[mt][nt][0] * scl + b0;
            float v1 = acc[mt][nt][1] * scl + b1;
            float v2 = acc[mt][nt][2] * scl + b0;
            float v3 = acc[mt][nt][3] * scl + b1;
            if (act == 1) { v0 = silu_f(v0); v1 = silu_f(v1); v2 = silu_f(v2); v3 = silu_f(v3); }
            store2(&Yb[(long)r * ldy + cN],       v0, v1);
            store2(&Yb[(long)(r + 8) * ldy + cN], v2, v3);
        }
}

// =====================================================================
// conv1 as GEMM: a1t[b][s][oc] = silu(hst . w1 + b), half token-major out.
// =====================================================================
__global__ __launch_bounds__(256) void conv1_gemm(
        const __half* __restrict__ A, const __half* __restrict__ Bm,
        const float* __restrict__ bias, __half* __restrict__ Y) {
    __shared__ __align__(16) uint32_t As32[2 * 128 * 20];
    __shared__ __align__(16) uint32_t Bs32[2 * 64 * 20];

    int b = blockIdx.z;
    const __half* Ab = A + (long)b * SS * CCH;
    __half* Yb = Y + (long)b * SS * C8;
    int m0 = blockIdx.x * 128;

    int tid = threadIdx.x;
    int w = tid >> 5, lane = tid & 31;
    int wm = w & 3, wn = w >> 2;
    int g = lane >> 2, tig = lane & 3;
    int rbase = wm * 32, cbase = wn * 32;
    int lrow = lane & 7, lmat = lane >> 3;
    int fr_row = (lmat & 1) * 8 + lrow;
    int fr_col = (lmat >> 1) * 4;
    uint32_t As_b = cvsm(As32), Bs_b = cvsm(Bs32);

    float acc[2][4][4];
    #pragma unroll
    for (int i = 0; i < 2; i++)
        #pragma unroll
        for (int j = 0; j < 4; j++)
            #pragma unroll
            for (int l = 0; l < 4; l++) acc[i][j][l] = 0.f;

    uint4 aR[2], bR;
    int w4 = (tid & 3) * 4, mb = tid >> 2;

    auto ldg = [&](int k0) {
        #pragma unroll
        for (int it = 0; it < 2; it++)
            aR[it] = *(const uint4*)&Ab[(long)(m0 + mb + it * 64) * CCH + k0 + w4 * 2];
        bR = *(const uint4*)&Bm[(long)mb * 512 + k0 + w4 * 2];
    };
    auto sts = [&](int p) {
        uint32_t* Ad = As32 + p * 2560;
        uint32_t* Bd = Bs32 + p * 1280;
        #pragma unroll
        for (int it = 0; it < 2; it++)
            *(uint4*)&Ad[(mb + it * 64) * 20 + w4] = aR[it];
        *(uint4*)&Bd[mb * 20 + w4] = bR;
    };

    ldg(0); sts(0);
    __syncthreads();
    for (int k0 = 0; k0 < 512; k0 += 32) {
        int p = (k0 >> 5) & 1;
        bool more = (k0 + 32 < 512);
        if (more) ldg(k0 + 32);

        uint32_t Ap = As_b + (uint32_t)p * 2560 * 4;
        uint32_t Bp = Bs_b + (uint32_t)p * 1280 * 4;
        #pragma unroll
        for (int ks = 0; ks < 2; ks++) {
            int kw = ks * 8;
            uint32_t af[2][4], bf[4][2];
            #pragma unroll
            for (int mt = 0; mt < 2; mt++) {
                int r0 = rbase + mt * 16;
                ldsm_x4(af[mt][0], af[mt][1], af[mt][2], af[mt][3],
                        Ap + (uint32_t)(((r0 + fr_row) * 20) + kw + fr_col) * 4);
            }
            ldsm_x4(bf[0][0], bf[1][0], bf[2][0], bf[3][0],
                    Bp + (uint32_t)(((cbase + lmat * 8 + lrow) * 20) + kw) * 4);
            ldsm_x4(bf[0][1], bf[1][1], bf[2][1], bf[3][1],
                    Bp + (uint32_t)(((cbase + lmat * 8 + lrow) * 20) + kw + 4) * 4);
            #pragma unroll
            for (int mt = 0; mt < 2; mt++)
                #pragma unroll
                for (int nt = 0; nt < 4; nt++)
                    MMA16(acc[mt][nt], af[mt][0], af[mt][1], af[mt][2], af[mt][3],
                          bf[nt][0], bf[nt][1]);
        }
        if (more) sts(p ^ 1);
        __syncthreads();
    }

    #pragma unroll
    for (int mt = 0; mt < 2; mt++)
        #pragma unroll
        for (int nt = 0; nt < 4; nt++) {
            int r = m0 + rbase + mt * 16 + g;
            int cN = cbase + nt * 8 + 2 * tig;
            float b0 = bias[cN], b1 = bias[cN + 1];
            store2(&Yb[(long)r * C8 + cN],       silu_f(acc[mt][nt][0] + b0), silu_f(acc[mt][nt][1] + b1));
            store2(&Yb[(long)(r + 8) * C8 + cN], silu_f(acc[mt][nt][2] + b0), silu_f(acc[mt][nt][3] + b1));
        }
}

// =====================================================================
// conv2 as IMPLICIT GEMM: a2t[s][oc] = silu( sum_tap,ci a1t[shift(s,tap)][ci]
//                                            * w2h[oc][tap*64+ci] + bias )
// M=1024 px, N=64, K=9 taps x 64. 128x64 tile. Zero-padded tap shifts.
// =====================================================================
__global__ __launch_bounds__(256) void conv2_gemm(
        const __half* __restrict__ A, const __half* __restrict__ Bm,
        const float* __restrict__ bias, __half* __restrict__ Y) {
    __shared__ __align__(16) uint32_t As32[128 * 36];
    __shared__ __align__(16) uint32_t Bs32[64 * 36];

    int b = blockIdx.z;
    const __half* Ab = A + (long)b * SS * C8;
    __half* Yb = Y + (long)b * SS * C8;
    int m0 = blockIdx.x * 128;

    int tid = threadIdx.x;
    int w = tid >> 5, lane = tid & 31;
    int wm = w & 3, wn = w >> 2;
    int g = lane >> 2, tig = lane & 3;
    int rbase = wm * 32, cbase = wn * 32;
    int lrow = lane & 7, lmat = lane >> 3;
    int fr_row = (lmat & 1) * 8 + lrow;
    int fr_col = (lmat >> 1) * 4;
    uint32_t As_b = cvsm(As32), Bs_b = cvsm(Bs32);

    float acc[2][4][4];
    #pragma unroll
    for (int i = 0; i < 2; i++)
        #pragma unroll
        for (int j = 0; j < 4; j++)
            #pragma unroll
            for (int l = 0; l < 4; l++) acc[i][j][l] = 0.f;

    uint4 aR[4], bR[2];

    auto ldg_tap = [&](int tap) {
        int dy = tap / 3 - 1, dx = tap % 3 - 1;
        #pragma unroll
        for (int f = 0; f < 4; f++) {
            int idx = tid + f * 256;
            int r = idx >> 3, c8 = idx & 7;
            int s = m0 + r;
            int sy = (s >> 5) + dy, sx = (s & 31) + dx;
            bool valid = ((unsigned)sy < 32u) && ((unsigned)sx < 32u);
            aR[f] = valid ? *(const uint4*)&Ab[(long)((sy << 5) + sx) * C8 + c8 * 8]
                          : make_uint4(0u, 0u, 0u, 0u);
        }
        #pragma unroll
        for (int f = 0; f < 2; f++) {
            int idx = tid + f * 256;
            int r = idx >> 3, c8 = idx & 7;
            bR[f] = *(const uint4*)&Bm[(long)r * 576 + tap * 64 + c8 * 8];
        }
    };
    auto sts_tap = [&]() {
        #pragma unroll
        for (int f = 0; f < 4; f++) {
            int idx = tid + f * 256;
            int r = idx >> 3, c8 = idx & 7;
            *(uint4*)&As32[r * 36 + c8 * 4] = aR[f];
        }
        #pragma unroll
        for (int f = 0; f < 2; f++) {
            int idx = tid + f * 256;
            int r = idx >> 3, c8 = idx & 7;
            *(uint4*)&Bs32[r * 36 + c8 * 4] = bR[f];
        }
    };

    ldg_tap(0);
    for (int tap = 0; tap < 9; tap++) {
        sts_tap();
        __syncthreads();
        if (tap < 8) ldg_tap(tap + 1);

        #pragma unroll
        for (int ks = 0; ks < 4; ks++) {
            int kw = ks * 8;
            uint32_t af[2][4], bf[4][2];
            #pragma unroll
            for (int mt = 0; mt < 2; mt++) {
                int r0 = rbase + mt * 16;
                ldsm_x4(af[mt][0], af[mt][1], af[mt][2], af[mt][3],
                        As_b + (uint32_t)(((r0 + fr_row) * 36) + kw + fr_col) * 4);
            }
            ldsm_x4(bf[0][0], bf[1][0], bf[2][0], bf[3][0],
                    Bs_b + (uint32_t)(((cbase + lmat * 8 + lrow) * 36) + kw) * 4);
            ldsm_x4(bf[0][1], bf[1][1], bf[2][1], bf[3][1],
                    Bs_b + (uint32_t)(((cbase + lmat * 8 + lrow) * 36) + kw + 4) * 4);
            #pragma unroll
            for (int mt = 0; mt < 2; mt++)
                #pragma unroll
                for (int nt = 0; nt < 4; nt++)
                    MMA16(acc[mt][nt], af[mt][0], af[mt][1], af[mt][2], af[mt][3],
                          bf[nt][0], bf[nt][1]);
        }
        __syncthreads();
    }

    #pragma unroll
    for (int mt = 0; mt < 2; mt++)
        #pragma unroll
        for (int nt = 0; nt < 4; nt++) {
            int r = m0 + rbase + mt * 16 + g;
            int cN = cbase + nt * 8 + 2 * tig;
            float b0 = bias[cN], b1 = bias[cN + 1];
            store2(&Yb[(long)r * C8 + cN],       silu_f(acc[mt][nt][0] + b0), silu_f(acc[mt][nt][1] + b1));
            store2(&Yb[(long)(r + 8) * C8 + cN], silu_f(acc[mt][nt][2] + b0), silu_f(acc[mt][nt][3] + b1));
        }
}

// ---------------- conv3 (64->1) + sigmoid, token-major half input ----------------
__global__ void conv3_sig_t(const __half* __restrict__ a2t, const float* __restrict__ w,
                            const float* __restrict__ bias, float* __restrict__ y) {
    __shared__ float ws[64];
    int tid = threadIdx.x;
    if (tid < 64) ws[tid] = w[tid];
    __syncthreads();
    int idx = blockIdx.x * 256 + tid;   // over B*S
    const __half* p = a2t + (long)idx * C8;
    float acc = bias[0];
    #pragma unroll
    for (int f = 0; f < 8; f++) {
        uint4 v = *(const uint4*)&p[f * 8];
        const __half2* h2 = (const __half2*)&v;
        #pragma unroll
        for (int u = 0; u < 4; u++) {
            float2 fv = __half22float2(h2[u]);
            acc += fv.x * ws[f * 8 + u * 2] + fv.y * ws[f * 8 + u * 2 + 1];
        }
    }
    y[idx] = 1.0f / (1.0f + expf(-acc));
}

// ---------------- senh_t = hs_t * sw ----------------
__global__ void senh_t_mul(const __half* __restrict__ hs_t, const float* __restrict__ sw,
                           __half* __restrict__ senh_t) {
    int idx = blockIdx.x * 256 + threadIdx.x;
    int token = idx >> 6, c8 = idx & 63;
    __half2 m = __float2half2_rn(sw[token]);
    uint4 v = *(const uint4*)&hs_t[(long)token * CCH + c8 * 8];
    __half2* h = (__half2*)&v;
    h[0] = __hmul2(h[0], m); h[1] = __hmul2(h[1], m);
    h[2] = __hmul2(h[2], m); h[3] = __hmul2(h[3], m);
    *(uint4*)&senh_t[(long)token * CCH + c8 * 8] = v;
}

// =====================================================================
// Merged flash attention (unchanged from R12).
// =====================================================================
#define FL_WORDS 15872

__device__ __forceinline__ void flash_std_body(
        const __half* __restrict__ Q, const __half* __restrict__ K,
        const __half* __restrict__ V, __half* __restrict__ O,
        int bh, int xq, uint32_t* smw) {
    uint32_t* Qs = smw;
    uint32_t* KP = smw + 128 * 36;
    uint32_t* Vs = smw + 2 * 128 * 36;
    float* redm = (float*)(smw + 2 * 128 * 36 + 64 * 36);
    float* redl = redm + 256;

    int b = bh >> 3, h = bh & 7;
    const __half* Qb = Q + (long)b * SS * CCH + h * 64;
    const __half* Kb = K + (long)b * SS * CCH + h * 64;
    const __half* Vb = V + (long)b * SS * CCH + h * 64;
    __half* Ob = O + (long)b * SS * (2 * CCH) + h * 64;
    int q0 = xq * 128;

    int tid = threadIdx.x;
    int w = tid >> 5, lane = tid & 31;
    int wm = w & 3, wn = w >> 2;
    int g = lane >> 2, tig = lane & 3;
    int rbase = wm * 32, cbase = wn * 32;
    int lrow = lane & 7, lmat = lane >> 3;
    int fr_row = (lmat & 1) * 8 + lrow;
    int fr_col = (lmat >> 1) * 4;
    int t_kb = lmat >> 1, t_hb = lmat & 1;
    uint32_t Qs_b = cvsm(Qs), KP_b = cvsm(KP), Vs_b = cvsm(Vs);

    #pragma unroll
    for (int f = 0; f < 4; f++) {
        int idx = tid + f * 256;
        int r = idx >> 3, w4 = (idx & 7) * 4;
        uint4 v4 = *(const uint4*)&Qb[(long)(q0 + r) * CCH + (idx & 7) * 8];
        *(uint4*)&Qs[r * 36 + w4] = v4;
    }

    uint4 kR[2], vR[2];
    int st_r = tid >> 3, st_w4 = (tid & 7) * 4, st_c = (tid & 7) * 8;
    auto ldg_kv = [&](int j) {
        #pragma unroll
        for (int f = 0; f < 2; f++) {
            long goff = (long)(j * 64 + st_r + f * 32) * CCH + st_c;
            kR[f] = *(const uint4*)&Kb[goff];
            vR[f] = *(const uint4*)&Vb[goff];
        }
    };
    auto sts_kv = [&]() {
        #pragma unroll
        for (int f = 0; f < 2; f++) {
            *(uint4*)&KP[(st_r + f * 32) * 36 + st_w4] = kR[f];
            *(uint4*)&Vs[(st_r + f * 32) * 36 + st_w4] = vR[f];
        }
    };

    float accO[2][4][4];
    #pragma unroll
    for (int i = 0; i < 2; i++)
        #pragma unroll
        for (int j = 0; j < 4; j++)
            #pragma unroll
            for (int l = 0; l < 4; l++) accO[i][j][l] = 0.f;
    float mst[4] = { -1e30f, -1e30f, -1e30f, -1e30f };
    float lst[4] = { 0.f, 0.f, 0.f, 0.f };

    ldg_kv(0);
    for (int j = 0; j < 16; j++) {
        sts_kv();
        __syncthreads();
        if (j + 1 < 16) ldg_kv(j + 1);

        float acc[2][4][4];
        #pragma unroll
        for (int i = 0; i < 2; i++)
            #pragma unroll
            for (int jj = 0; jj < 4; jj++)
                #pragma unroll
                for (int l = 0; l < 4; l++) acc[i][jj][l] = 0.f;
        #pragma unroll
        for (int ks = 0; ks < 4; ks++) {
            int kw = ks * 8;
            uint32_t af[2][4], bf[4][2];
            #pragma unroll
            for (int mt = 0; mt < 2; mt++) {
                int r0 = rbase + mt * 16;
                ldsm_x4(af[mt][0], af[mt][1], af[mt][2], af[mt][3],
                        Qs_b + (uint32_t)(((r0 + fr_row) * 36) + kw + fr_col) * 4);
            }
            ldsm_x4(bf[0][0], bf[1][0], bf[2][0], bf[3][0],
                    KP_b + (uint32_t)(((cbase + lmat * 8 + lrow) * 36) + kw) * 4);
            ldsm_x4(bf[0][1], bf[1][1], bf[2][1], bf[3][1],
                    KP_b + (uint32_t)(((cbase + lmat * 8 + lrow) * 36) + kw + 4) * 4);
            #pragma unroll
            for (int mt = 0; mt < 2; mt++)
                #pragma unroll
                for (int nt = 0; nt < 4; nt++)
                    MMA16(acc[mt][nt], af[mt][0], af[mt][1], af[mt][2], af[mt][3],
                          bf[nt][0], bf[nt][1]);
        }

        #pragma unroll
        for (int mt = 0; mt < 2; mt++)
            #pragma unroll
            for (int hh = 0; hh < 2; hh++) {
                float mx = -1e30f;
                #pragma unroll
                for (int nt = 0; nt < 4; nt++) {
                    mx = fmaxf(mx, acc[mt][nt][hh * 2]);
                    mx = fmaxf(mx, acc[mt][nt][hh * 2 + 1]);
                }
                mx = fmaxf(mx, __shfl_xor_sync(0xffffffffu, mx, 1));
                mx = fmaxf(mx, __shfl_xor_sync(0xffffffffu, mx, 2));
                if (tig == 0) redm[wn * 128 + rbase + mt * 16 + hh * 8 + g] = mx;
            }
        __syncthreads();

        #pragma unroll
        for (int mt = 0; mt < 2; mt++)
            #pragma unroll
            for (int hh = 0; hh < 2; hh++) {
                int i = mt * 2 + hh;
                int rloc = rbase + mt * 16 + hh * 8 + g;
                float mch = fmaxf(redm[rloc], redm[128 + rloc]);
                float mnew = fmaxf(mst[i], mch);
                float corr = __expf(mst[i] - mnew);
                mst[i] = mnew;
                float s = 0.f;
                #pragma unroll
                for (int nt = 0; nt < 4; nt++) {
                    float p0 = __expf(acc[mt][nt][hh * 2]     - mnew);
                    float p1 = __expf(acc[mt][nt][hh * 2 + 1] - mnew);
                    s += p0 + p1;
                    KP[rloc * 36 + wn * 16 + nt * 4 + tig] = pack2(p0, p1);
                    accO[mt][nt][hh * 2]     *= corr;
                    accO[mt][nt][hh * 2 + 1] *= corr;
                }
                s += __shfl_xor_sync(0xffffffffu, s, 1);
                s += __shfl_xor_sync(0xffffffffu, s, 2);
                if (tig == 0) redl[wn * 128 + rloc] = s;
                lst[i] *= corr;
            }
        __syncthreads();
        #pragma unroll
        for (int mt = 0; mt < 2; mt++)
            #pragma unroll
            for (int hh = 0; hh < 2; hh++) {
                int rloc = rbase + mt * 16 + hh * 8 + g;
                lst[mt * 2 + hh] += redl[rloc] + redl[128 + rloc];
            }

        #pragma unroll
        for (int ks = 0; ks < 4; ks++) {
            int kw = ks * 8;
            uint32_t af[2][4], bf[4][2];
            #pragma unroll
            for (int mt = 0; mt < 2; mt++) {
                int r0 = rbase + mt * 16;
                ldsm_x4(af[mt][0], af[mt][1], af[mt][2], af[mt][3],
                        KP_b + (uint32_t)(((r0 + fr_row) * 36) + kw + fr_col) * 4);
            }
            uint32_t vaddr = Vs_b + (uint32_t)((ks * 16 + t_kb * 8 + lrow) * 144
                                               + (cbase + t_hb * 8) * 2);
            ldsm_x4_t(bf[0][0], bf[1][0], bf[0][1], bf[1][1], vaddr);
            ldsm_x4_t(bf[2][0], bf[3][0], bf[2][1], bf[3][1], vaddr + 32);
            #pragma unroll
            for (int mt = 0; mt < 2; mt++)
                #pragma unroll
                for (int nt = 0; nt < 4; nt++)
                    MMA16(accO[mt][nt], af[mt][0], af[mt][1], af[mt][2], af[mt][3],
                          bf[nt][0], bf[nt][1]);
        }
        __syncthreads();
    }

    #pragma unroll
    for (int mt = 0; mt < 2; mt++) {
        float inv0 = 1.0f / lst[mt * 2];
        float inv1 = 1.0f / lst[mt * 2 + 1];
        #pragma unroll
        for (int nt = 0; nt < 4; nt++) {
            int r = q0 + rbase + mt * 16 + g;
            int c = cbase + nt * 8 + 2 * tig;
            store2(&Ob[(long)r * 1024 + c],       accO[mt][nt][0] * inv0, accO[mt][nt][1] * inv0);
            store2(&Ob[(long)(r + 8) * 1024 + c], accO[mt][nt][2] * inv1, accO[mt][nt][3] * inv1);
        }
    }
}

__device__ __forceinline__ void flash_multi_body(
        const __half* __restrict__ Q, const __half* __restrict__ K,
        const __half* __restrict__ V, __half* __restrict__ O,
        int z, int xq, uint32_t* smw) {
    uint32_t* Qs = smw;
    uint32_t* Ks = smw + 8448;
    uint32_t* Ps = smw + 8448 + 2304;
    uint32_t* Vs = smw + 8448 + 2 * 2304;
    float* redm = (float*)(smw + 8448 + 3 * 2304);
    float* redl = redm + 256;

    const __half* Qb = Q + (long)z * SS * C2;
    const __half* Kb = K + (long)z * SS * C2;
    const __half* Vb = V + (long)z * SS * C2;
    int br = z >> 3, b = z & 7;
    __half* Ob = O + (long)b * SS * 1024 + 512 + br * 256;
    int q0 = xq * 64;

    int tid = threadIdx.x;
    int w = tid >> 5, lane = tid & 31;
    int wm = w & 1, wn = w >> 1;
    int g = lane >> 2, tig = lane & 3;
    int rbase = wm * 32;
    int lrow = lane & 7, lmat = lane >> 3;
    int fr_row = (lmat & 1) * 8 + lrow;
    int fr_col = (lmat >> 1) * 4;
    int t_kb = lmat >> 1, t_hb = lmat & 1;
    uint32_t Qs_b = cvsm(Qs), Ks_b = cvsm(Ks), Ps_b = cvsm(Ps), Vs_b = cvsm(Vs);

    #pragma unroll
    for (int f = 0; f < 8; f++) {
        int idx = tid + f * 256;
        int r = idx >> 5, c8 = idx & 31;
        uint4 qv = *(const uint4*)&Qb[(long)(q0 + r) * C2 + c8 * 8];
        *(uint4*)&Qs[r * 132 + c8 * 4] = qv;
    }

    int st_r = tid >> 3, st_w4 = (tid & 7) * 4, st_c = (tid & 7) * 8;
    uint4 sR[2];
    auto ldg_s = [&](const __half* P, int j, int dc) {
        #pragma unroll
        for (int f = 0; f < 2; f++)
            sR[f] = *(const uint4*)&P[(long)(j * 64 + st_r + f * 32) * C2 + dc * 64 + st_c];
    };
    auto sts_s = [&](uint32_t* D) {
        #pragma unroll
        for (int f = 0; f < 2; f++)
            *(uint4*)&D[(st_r + f * 32) * 36 + st_w4] = sR[f];
    };

    float accO[2][8][4];
    #pragma unroll
    for (int i = 0; i < 2; i++)
        #pragma unroll
        for (int j = 0; j < 8; j++)
            #pragma unroll
            for (int l = 0; l < 4; l++) accO[i][j][l] = 0.f;
    float mst[4] = { -1e30f, -1e30f, -1e30f, -1e30f };
    float lst[4] = { 0.f, 0.f, 0.f, 0.f };

    for (int j = 0; j < 16; j++) {
        float acc[2][2][4];
        #pragma unroll
        for (int i = 0; i < 2; i++)
            #pragma unroll
            for (int jj = 0; jj < 2; jj++)
                #pragma unroll
                for (int l = 0; l < 4; l++) acc[i][jj][l] = 0.f;

        ldg_s(Kb, j, 0);
        for (int dc = 0; dc < 4; dc++) {
            sts_s(Ks);
            __syncthreads();
            if (dc < 3) ldg_s(Kb, j, dc + 1);
            #pragma unroll
            for (int ks = 0; ks < 4; ks++) {
                int kw = ks * 8;
                uint32_t af[2][4], bf[2][2];
                #pragma unroll
                for (int mt = 0; mt < 2; mt++) {
                    int r0 = rbase + mt * 16;
                    ldsm_x4(af[mt][0], af[mt][1], af[mt][2], af[mt][3],
                            Qs_b + (uint32_t)(((r0 + fr_row) * 132) + dc * 32 + kw + fr_col) * 4);
                }
                ldsm_x4(bf[0][0], bf[1][0], bf[0][1], bf[1][1],
                        Ks_b + (uint32_t)(((wn * 16 + fr_row) * 36) + kw + fr_col) * 4);
                #pragma unroll
                for (int mt = 0; mt < 2; mt++)
                    #pragma unroll
                    for (int nt = 0; nt < 2; nt++)
                        MMA16(acc[mt][nt], af[mt][0], af[mt][1], af[mt][2], af[mt][3],
                              bf[nt][0], bf[nt][1]);
            }
            __syncthreads();
        }

        #pragma unroll
        for (int mt = 0; mt < 2; mt++)
            #pragma unroll
            for (int hh = 0; hh < 2; hh++) {
                float mx = -1e30f;
                #pragma unroll
                for (int nt = 0; nt < 2; nt++) {
                    mx = fmaxf(mx, acc[mt][nt][hh * 2]);
                    mx = fmaxf(mx, acc[mt][nt][hh * 2 + 1]);
                }
                mx = fmaxf(mx, __shfl_xor_sync(0xffffffffu, mx, 1));
                mx = fmaxf(mx, __shfl_xor_sync(0xffffffffu, mx, 2));
                if (tig == 0) redm[wn * 64 + rbase + mt * 16 + hh * 8 + g] = mx;
            }
        __syncthreads();

        #pragma unroll
        for (int mt = 0; mt < 2; mt++)
            #pragma unroll
            for (int hh = 0; hh < 2; hh++) {
                int i = mt * 2 + hh;
                int rloc = rbase + mt * 16 + hh * 8 + g;
                float mch = fmaxf(fmaxf(redm[rloc], redm[64 + rloc]),
                                  fmaxf(redm[128 + rloc], redm[192 + rloc]));
                float mnew = fmaxf(mst[i], mch);
                float corr = __expf(mst[i] - mnew);
                mst[i] = mnew;
                float s = 0.f;
                #pragma unroll
                for (int nt = 0; nt < 2; nt++) {
                    float p0 = __expf(acc[mt][nt][hh * 2]     - mnew);
                    float p1 = __expf(acc[mt][nt][hh * 2 + 1] - mnew);
                    s += p0 + p1;
                    Ps[rloc * 36 + wn * 8 + nt * 4 + tig] = pack2(p0, p1);
                }
                s += __shfl_xor_sync(0xffffffffu, s, 1);
                s += __shfl_xor_sync(0xffffffffu, s, 2);
                if (tig == 0) redl[wn * 64 + rloc] = s;
                lst[i] *= corr;
                #pragma unroll
                for (int nt = 0; nt < 8; nt++) {
                    accO[mt][nt][hh * 2]     *= corr;
                    accO[mt][nt][hh * 2 + 1] *= corr;
                }
            }
        __syncthreads();
        #pragma unroll
        for (int mt = 0; mt < 2; mt++)
            #pragma unroll
            for (int hh = 0; hh < 2; hh++) {
                int rloc = rbase + mt * 16 + hh * 8 + g;
                lst[mt * 2 + hh] += redl[rloc] + redl[64 + rloc]
                                  + redl[128 + rloc] + redl[192 + rloc];
            }

        ldg_s(Vb, j, 0);
        for (int dc = 0; dc < 4; dc++) {
            sts_s(Vs);
            __syncthreads();
            if (dc < 3) ldg_s(Vb, j, dc + 1);
            #pragma unroll
            for (int ks = 0; ks < 4; ks++) {
                int kw = ks * 8;
                uint32_t af[2][4], bf[2][2];
                #pragma unroll
                for (int mt = 0; mt < 2; mt++) {
                    int r0 = rbase + mt * 16;
                    ldsm_x4(af[mt][0], af[mt][1], af[mt][2], af[mt][3],
                            Ps_b + (uint32_t)(((r0 + fr_row) * 36) + kw + fr_col) * 4);
                }
                uint32_t vaddr = Vs_b + (uint32_t)((ks * 16 + t_kb * 8 + lrow) * 144
                                                   + (wn * 16 + t_hb * 8) * 2);
                ldsm_x4_t(bf[0][0], bf[1][0], bf[0][1], bf[1][1], vaddr);
                #pragma unroll
                for (int mt = 0; mt < 2; mt++)
                    #pragma unroll
                    for (int nt = 0; nt < 2; nt++)
                        MMA16(accO[mt][dc * 2 + nt], af[mt][0], af[mt][1], af[mt][2], af[mt][3],
                              bf[nt][0], bf[nt][1]);
            }
            __syncthreads();
        }
    }

    #pragma unroll
    for (int mt = 0; mt < 2; mt++) {
        float inv0 = 1.0f / lst[mt * 2];
        float inv1 = 1.0f / lst[mt * 2 + 1];
        #pragma unroll
        for (int u = 0; u < 8; u++) {
            int dc = u >> 1, nt = u & 1;
            int r = q0 + rbase + mt * 16 + g;
            int c = dc * 64 + wn * 16 + nt * 8 + 2 * tig;
            store2(&Ob[(long)r * 1024 + c],       accO[mt][u][0] * inv0, accO[mt][u][1] * inv0);
            store2(&Ob[(long)(r + 8) * 1024 + c], accO[mt][u][2] * inv1, accO[mt][u][3] * inv1);
        }
    }
}

__global__ __launch_bounds__(256, 2) void flash_all(
        const __half* __restrict__ q, const __half* __restrict__ k,
        const __half* __restrict__ v,
        const __half* __restrict__ qm, const __half* __restrict__ km,
        const __half* __restrict__ vm, __half* __restrict__ comb) {
    extern __shared__ uint32_t smw[];
    int bx = blockIdx.x;
    if (bx < 512) flash_std_body(q, k, v, comb, bx >> 3, bx & 7, smw);
    else { int i = bx - 512; flash_multi_body(qm, km, vm, comb, i >> 4, i & 15, smw); }
}

// ---------------- launch ----------------
static void* symv(const void* s) { void* p = nullptr; cudaGetSymbolAddress(&p, s); return p; }

extern "C" void kernel_launch(void* const* d_in, const int* in_sizes, int n_in,
                              void* d_out, int out_size) {
    (void)in_sizes; (void)n_in; (void)out_size;
    const float* x      = (const float*)d_in[0];
    const float* pre_g  = (const float*)d_in[1];
    const float* pre_b  = (const float*)d_in[2];
    const float* norm_g = (const float*)d_in[3];
    const float* norm_b = (const float*)d_in[4];
    const float* post_g = (const float*)d_in[5];
    const float* post_b = (const float*)d_in[6];
    const float* pos    = (const float*)d_in[7];
    const float* sa_w1  = (const float*)d_in[8];
    const float* sa_b1  = (const float*)d_in[9];
    const float* sa_w2  = (const float*)d_in[10];
    const float* sa_b2  = (const float*)d_in[11];
    const float* sa_w3  = (const float*)d_in[12];
    const float* sa_b3  = (const float*)d_in[13];
    const float* wq     = (const float*)d_in[14];
    const float* wk     = (const float*)d_in[15];
    const float* wv     = (const float*)d_in[16];
    const float* wq0    = (const float*)d_in[17];
    const float* wk0    = (const float*)d_in[18];
    const float* wv0    = (const float*)d_in[19];
    const float* wq1    = (const float*)d_in[20];
    const float* wk1    = (const float*)d_in[21];
    const float* wv1    = (const float*)d_in[22];
    const float* ff_w1  = (const float*)d_in[23];
    const float* ff_b1  = (const float*)d_in[24];
    const float* ff_w2  = (const float*)d_in[25];
    const float* ff_b2  = (const float*)d_in[26];
    const float* out_w  = (const float*)d_in[27];
    const float* out_b  = (const float*)d_in[28];
    float* out = (float*)d_out;

    __half *hst = (__half*)symv(d_hst), *shnt = (__half*)symv(d_shnt), *senht = (__half*)symv(d_senht);
    __half *a1t = (__half*)symv(d_a1t), *a2t = (__half*)symv(d_a2t);
    float  *sw = (float*)symv(d_swt);
    __half *q = (__half*)symv(d_q), *k = (__half*)symv(d_k), *v = (__half*)symv(d_v);
    __half *qm = (__half*)symv(d_qm), *km = (__half*)symv(d_km), *vm = (__half*)symv(d_vm);
    __half *comb = (__half*)symv(d_comb), *f1 = (__half*)symv(d_f1), *fus = (__half*)symv(d_fus);
    float  *fin = (float*)symv(d_fin);
    __half *wb = (__half*)symv(d_w);
    __half *w2h = (__half*)symv(d_w2);

    const int flSmem = FL_WORDS * 4;
    cudaFuncSetAttribute(flash_all, cudaFuncAttributeMaxDynamicSharedMemorySize, flSmem);
    const int gnSmem = 16 * 1024 * 4;
    cudaFuncSetAttribute(gn_fused, cudaFuncAttributeMaxDynamicSharedMemorySize, gnSmem);

    // weight conversion
    const float* wsrc[13] = { wq, wk, wv, wq0, wk0, wv0, wq1, wk1, wv1,
                              ff_w1, ff_w2, out_w, sa_w1 };
    const int wcnt[13] = { 262144, 262144, 262144, 131072, 131072, 131072,
                           131072, 131072, 131072, 524288, 262144, 262144, 32768 };
    WC wc; int off = 0;
    __half* hw[13];
    for (int i = 0; i < 13; i++) {
        wc.src[i] = wsrc[i]; wc.cnt4[i] = wcnt[i] / 4; wc.off[i] = off;
        hw[i] = wb + off;
        off += wcnt[i];
    }
    wcvt<<<dim3(512, 13), 256>>>(wc, wb);
    w2cvt<<<144, 256>>>(sa_w2, w2h);

    gn_fused<<<BATCH * NGR, 256, gnSmem>>>(x, pre_g, pre_b, pos, norm_g, norm_b,
                                           hst, shnt);
    conv1_gemm<<<dim3(8, 1, BATCH), 256>>>(hst, hw[12], sa_b1, a1t);
    conv2_gemm<<<dim3(8, 1, BATCH), 256>>>(a1t, w2h, sa_b2, a2t);
    conv3_sig_t<<<BATCH * SS / 256, 256>>>(a2t, sa_w3, sa_b3, sw);
    senh_t_mul<<<BATCH * SS * CCH / 8 / 256, 256>>>(hst, sw, senht);

    // QKV projections (q pre-scaled by 1/8)
    GArg pq = {};
    pq.A[0] = shnt; pq.A[1] = shnt; pq.A[2] = shnt;
    pq.W[0] = hw[0]; pq.W[1] = hw[1]; pq.W[2] = hw[2];
    pq.Y[0] = q;    pq.Y[1] = k;    pq.Y[2] = v;
    pq.bias[0] = pq.bias[1] = pq.bias[2] = nullptr;
    pq.sc[0] = 0.125f; pq.sc[1] = 1.f; pq.sc[2] = 1.f;
    pq.aOuter = (long)SS * CCH; pq.yOuter = (long)SS * 512;
    pq.K = 512; pq.lda = 512; pq.N = 512; pq.ldy = 512; pq.act = 0;
    gemm128<__half><<<dim3(8, 4, 24), 256>>>(pq);

    // multi-scale projections (qm pre-scaled by 1/16)
    long moff = 8LL * SS * C2;
    GArg pm = {};
    pm.A[0] = senht; pm.A[1] = shnt; pm.A[2] = shnt;
    pm.A[3] = senht; pm.A[4] = shnt; pm.A[5] = shnt;
    pm.W[0] = hw[3]; pm.W[1] = hw[4]; pm.W[2] = hw[5];
    pm.W[3] = hw[6]; pm.W[4] = hw[7]; pm.W[5] = hw[8];
    pm.Y[0] = qm;        pm.Y[1] = km;        pm.Y[2] = vm;
    pm.Y[3] = qm + moff; pm.Y[4] = km + moff; pm.Y[5] = vm + moff;
    for (int i = 0; i < 6; i++) pm.bias[i] = nullptr;
    pm.sc[0] = 0.0625f; pm.sc[1] = 1.f; pm.sc[2] = 1.f;
    pm.sc[3] = 0.0625f; pm.sc[4] = 1.f; pm.sc[5] = 1.f;
    pm.aOuter = (long)SS * CCH; pm.yOuter = (long)SS * C2;
    pm.K = 512; pm.lda = 512; pm.N = 256; pm.ldy = 256; pm.act = 0;
    gemm128<__half><<<dim3(8, 2, 48), 256>>>(pm);

    // merged flash
    flash_all<<<768, 256, flSmem>>>(q, k, v, qm, km, vm, comb);

    // ff1 (silu)
    GArg f1a = {};
    f1a.A[0] = comb; f1a.W[0] = hw[9]; f1a.Y[0] = f1; f1a.bias[0] = ff_b1;
    f1a.sc[0] = 1.f;
    f1a.aOuter = (long)SS * 2 * CCH; f1a.yOuter = (long)SS * CCH;
    f1a.K = 1024; f1a.lda = 1024; f1a.N = 512; f1a.ldy = 512; f1a.act = 1;
    gemm128<__half><<<dim3(8, 4, 8), 256>>>(f1a);
    // ff2
    GArg f2a = {};
    f2a.A[0] = f1; f2a.W[0] = hw[10]; f2a.Y[0] = fus; f2a.bias[0] = ff_b2;
    f2a.sc[0] = 1.f;
    f2a.aOuter = (long)SS * CCH; f2a.yOuter = (long)SS * CCH;
    f2a.K = 512; f2a.lda = 512; f2a.N = 512; f2a.ldy = 512; f2a.act = 0;
    gemm128<__half><<<dim3(8, 4, 8), 256>>>(f2a);
    // out proj
    GArg oa = {};
    oa.A[0] = fus; oa.W[0] = hw[11]; oa.Y[0] = fin; oa.bias[0] = out_b;
    oa.sc[0] = 1.f;
    oa.aOuter = (long)SS * CCH; oa.yOuter = (long)SS * CCH;
    oa.K = 512; oa.lda = 512; oa.N = 512; oa.ldy = 512; oa.act = 0;
    gemm128<float><<<dim3(8, 4, 8), 256>>>(oa);

    // post GN + residual
    gn_post_k<<<BATCH * NGR, 256>>>(fin, post_g, post_b, x, out);
}

// round 14
// speedup vs baseline: 1.1166x; 1.0048x over previous
#include <cuda_runtime.h>
#include <cuda_fp16.h>
#include <math.h>
#include <stdint.h>

#define BATCH 8
#define CCH 512
#define SS 1024
#define NHD 8
#define NGR 32
#define CG 16
#define C8 64
#define C2 256
#define GEPS 1e-6f
#define L2E 1.4426950408889634f

// ---------------- static scratch ----------------
__device__ __half d_hst  [BATCH*SS*CCH];
__device__ __half d_shnt [BATCH*SS*CCH];
__device__ __half d_senht[BATCH*SS*CCH];
__device__ __half d_a1t  [BATCH*SS*C8];
__device__ __half d_a2t  [BATCH*SS*C8];
__device__ float  d_swt  [BATCH*SS];
__device__ __half d_q    [BATCH*SS*CCH];
__device__ __half d_k    [BATCH*SS*CCH];
__device__ __half d_v    [BATCH*SS*CCH];
__device__ __half d_qm   [2*BATCH*SS*C2];
__device__ __half d_km   [2*BATCH*SS*C2];
__device__ __half d_vm   [2*BATCH*SS*C2];
__device__ __half d_comb [BATCH*SS*2*CCH];
__device__ __half d_f1   [BATCH*SS*CCH];
__device__ __half d_fus  [BATCH*SS*CCH];
__device__ float  d_fin  [BATCH*SS*CCH];
__device__ __half d_w    [2654208];
__device__ __half d_w2   [36864];

// ---------------- helpers ----------------
__device__ __forceinline__ float blk_sum(float v, float* sb, int tid) {
    sb[tid] = v; __syncthreads();
    for (int o = 128; o > 0; o >>= 1) { if (tid < o) sb[tid] += sb[tid + o]; __syncthreads(); }
    float r = sb[0]; __syncthreads(); return r;
}
__device__ __forceinline__ float silu_f(float x) { return x / (1.0f + expf(-x)); }
__device__ __forceinline__ uint32_t pack2(float a, float b) {
    __half2 h = __floats2half2_rn(a, b);
    return *reinterpret_cast<uint32_t*>(&h);
}
__device__ __forceinline__ void store2(float* p, float a, float b) {
    *(float2*)p = make_float2(a, b);
}
__device__ __forceinline__ void store2(__half* p, float a, float b) {
    *(uint32_t*)p = pack2(a, b);
}
// two exps in one MUFU: p = 2^(t) elementwise on half2
__device__ __forceinline__ uint32_t exp2_h2(float t0, float t1) {
    uint32_t h = pack2(t0, t1);
    uint32_t r;
    asm("ex2.approx.f16x2 %0, %1;" : "=r"(r) : "r"(h));
    return r;
}
__device__ __forceinline__ uint32_t cvsm(const void* p) {
    return (uint32_t)__cvta_generic_to_shared(p);
}
__device__ __forceinline__ void ldsm_x4(uint32_t& r0, uint32_t& r1, uint32_t& r2,
                                        uint32_t& r3, uint32_t addr) {
    asm volatile("ldmatrix.sync.aligned.m8n8.x4.shared.b16 {%0,%1,%2,%3}, [%4];"
        : "=r"(r0), "=r"(r1), "=r"(r2), "=r"(r3) : "r"(addr));
}
__device__ __forceinline__ void ldsm_x4_t(uint32_t& r0, uint32_t& r1, uint32_t& r2,
                                          uint32_t& r3, uint32_t addr) {
    asm volatile("ldmatrix.sync.aligned.m8n8.x4.trans.shared.b16 {%0,%1,%2,%3}, [%4];"
        : "=r"(r0), "=r"(r1), "=r"(r2), "=r"(r3) : "r"(addr));
}

#define MMA16(d, a0, a1, a2, a3, b0, b1) \
    asm volatile("mma.sync.aligned.m16n8k16.row.col.f32.f16.f16.f32 " \
        "{%0,%1,%2,%3},{%4,%5,%6,%7},{%8,%9},{%0,%1,%2,%3};" \
        : "+f"((d)[0]), "+f"((d)[1]), "+f"((d)[2]), "+f"((d)[3]) \
        : "r"(a0), "r"(a1), "r"(a2), "r"(a3), "r"(b0), "r"(b1))

// ---------------- weight conversion fp32 -> half ----------------
struct WC { const float* src[13]; int cnt4[13]; int off[13]; };
__global__ void wcvt(WC wc, __half* dst) {
    int which = blockIdx.y;
    int idx = blockIdx.x * 256 + threadIdx.x;
    if (idx < wc.cnt4[which]) {
        float4 v = *(const float4*)&wc.src[which][idx * 4];
        uint2 pk = make_uint2(pack2(v.x, v.y), pack2(v.z, v.w));
        *(uint2*)&dst[wc.off[which] + idx * 4] = pk;
    }
}
__global__ void w2cvt(const float* __restrict__ src, __half* __restrict__ dst) {
    int idx = blockIdx.x * 256 + threadIdx.x;
    if (idx < 36864) {
        int oc = idx / 576, rem = idx % 576;
        int tap = rem >> 6, ci = rem & 63;
        dst[idx] = __float2half(src[oc * 576 + ci * 9 + tap]);
    }
}

// =====================================================================
// Fused double GroupNorm -> half token-major hs_t, shn_t.
// =====================================================================
__global__ void gn_fused(const float* __restrict__ x,
                         const float* __restrict__ pre_g, const float* __restrict__ pre_b,
                         const float* __restrict__ pos,
                         const float* __restrict__ norm_g, const float* __restrict__ norm_b,
                         __half* __restrict__ hs_t, __half* __restrict__ shn_t) {
    extern __shared__ float xs[];
    __shared__ float sb[256];
    __shared__ float pgs[16], pbs[16], ngs[16], nbs[16];

    int tid = threadIdx.x;
    int b = blockIdx.x / NGR, gi = blockIdx.x % NGR;
    long base = (long)b * CCH * SS + (long)gi * CG * SS;
    if (tid < 16) {
        int c = gi * 16 + tid;
        pgs[tid] = pre_g[c]; pbs[tid] = pre_b[c];
        ngs[tid] = norm_g[c]; nbs[tid] = norm_b[c];
    }

    float s1 = 0.f, s2 = 0.f;
    for (int i = tid; i < CG * SS; i += 256) {
        float v = x[base + i];
        xs[i] = v; s1 += v; s2 += v * v;
    }
    s1 = blk_sum(s1, sb, tid);
    s2 = blk_sum(s2, sb, tid);
    float mu1 = s1 / (float)(CG * SS);
    float inv1 = rsqrtf(s2 / (float)(CG * SS) - mu1 * mu1 + GEPS);

    float t1 = 0.f, t2 = 0.f;
    for (int i = tid; i < CG * SS; i += 256) {
        int cl = i >> 10, s = i & 1023;
        int c = gi * CG + cl;
        float h = (xs[i] - mu1) * inv1 * pgs[cl] + pbs[cl] + pos[(long)c * SS + s];
        xs[i] = h;
        t1 += h; t2 += h * h;
    }
    t1 = blk_sum(t1, sb, tid);
    t2 = blk_sum(t2, sb, tid);
    float mu2 = t1 / (float)(CG * SS);
    float inv2 = rsqrtf(t2 / (float)(CG * SS) - mu2 * mu2 + GEPS);

    long tbase = ((long)b * SS) * CCH + gi * 16;
    for (int s = tid; s < SS; s += 256) {
        uint32_t wh[8], wn[8];
        #pragma unroll
        for (int cl = 0; cl < 16; cl += 2) {
            float h0 = xs[cl * 1024 + s], h1 = xs[(cl + 1) * 1024 + s];
            wh[cl >> 1] = pack2(h0, h1);
            float n0 = (h0 - mu2) * inv2 * ngs[cl] + nbs[cl];
            float n1 = (h1 - mu2) * inv2 * ngs[cl + 1] + nbs[cl + 1];
            wn[cl >> 1] = pack2(n0, n1);
        }
        __half* ph = hs_t + tbase + (long)s * CCH;
        *(uint4*)ph       = make_uint4(wh[0], wh[1], wh[2], wh[3]);
        *(uint4*)(ph + 8) = make_uint4(wh[4], wh[5], wh[6], wh[7]);
        __half* pn = shn_t + tbase + (long)s * CCH;
        *(uint4*)pn       = make_uint4(wn[0], wn[1], wn[2], wn[3]);
        *(uint4*)(pn + 8) = make_uint4(wn[4], wn[5], wn[6], wn[7]);
    }
}

// ---------------- group norm token-major + residual ----------------
__global__ void gn_post_k(const float* __restrict__ xt, const float* __restrict__ g,
                          const float* __restrict__ be, const float* __restrict__ resid,
                          float* __restrict__ y) {
    __shared__ float sb[256];
    int tid = threadIdx.x;
    int b = blockIdx.x / NGR, gi = blockIdx.x % NGR;
    long tbase = (long)b * SS * CCH + gi * CG;
    float s1 = 0.f, s2 = 0.f;
    for (int i = tid; i < CG * SS; i += 256) {
        int s = i >> 4, cl = i & 15;
        float v = xt[tbase + (long)s * CCH + cl]; s1 += v; s2 += v * v;
    }
    s1 = blk_sum(s1, sb, tid);
    s2 = blk_sum(s2, sb, tid);
    float mu = s1 / (float)(CG * SS);
    float var = s2 / (float)(CG * SS) - mu * mu;
    float inv = rsqrtf(var + GEPS);
    for (int i = tid; i < CG * SS; i += 256) {
        int s = i >> 4, cl = i & 15;
        int c = gi * CG + cl;
        float v = (xt[tbase + (long)s * CCH + cl] - mu) * inv * g[c] + be[c];
        long oidx = (long)b * CCH * SS + (long)c * SS + s;
        y[oidx] = v + resid[oidx];
    }
}

// =====================================================================
// Unified fp16 GEMM (NT), 128x128 tile, half weights.
// =====================================================================
struct GArg {
    const __half* A[6]; const __half* W[6]; void* Y[6]; const float* bias[6];
    float sc[6];
    long aOuter, yOuter;
    int K, lda, N, ldy, act;
};

template<typename OutT>
__global__ __launch_bounds__(256, 2) void gemm128(GArg ga) {
    __shared__ __align__(16) uint32_t As32[2 * 128 * 20];
    __shared__ __align__(16) uint32_t Bs32[2 * 128 * 20];

    int z = blockIdx.z;
    int which = z >> 3, b = z & 7;
    const __half* Ab = ga.A[which] + (long)b * ga.aOuter;
    const __half* Bb = ga.W[which];
    OutT*         Yb = (OutT*)ga.Y[which] + (long)b * ga.yOuter;
    const float* bias = ga.bias[which];
    float scl = ga.sc[which];
    int K = ga.K, lda = ga.lda, ldy = ga.ldy, act = ga.act;
    int m0 = blockIdx.x * 128, n0 = blockIdx.y * 128;

    int tid = threadIdx.x;
    int w = tid >> 5, lane = tid & 31;
    int wm = w & 1, wn = w >> 1;
    int g = lane >> 2, tig = lane & 3;
    int rbase = wm * 64, cbase = wn * 32;
    int lrow = lane & 7, lmat = lane >> 3;
    int fr_row = (lmat & 1) * 8 + lrow;
    int fr_col = (lmat >> 1) * 4;
    uint32_t As_b = cvsm(As32), Bs_b = cvsm(Bs32);

    float acc[4][4][4];
    #pragma unroll
    for (int i = 0; i < 4; i++)
        #pragma unroll
        for (int j = 0; j < 4; j++)
            #pragma unroll
            for (int l = 0; l < 4; l++) acc[i][j][l] = 0.f;

    uint4 aR[2], bR[2];
    int w4 = (tid & 3) * 4, mb = tid >> 2;

    auto ldg = [&](int k0) {
        #pragma unroll
        for (int it = 0; it < 2; it++)
            aR[it] = *(const uint4*)&Ab[(long)(m0 + mb + it * 64) * lda + k0 + w4 * 2];
        #pragma unroll
        for (int it = 0; it < 2; it++)
            bR[it] = *(const uint4*)&Bb[(long)(n0 + mb + it * 64) * K + k0 + w4 * 2];
    };
    auto sts = [&](int p) {
        uint32_t* Ad = As32 + p * 2560;
        uint32_t* Bd = Bs32 + p * 2560;
        #pragma unroll
        for (int it = 0; it < 2; it++)
            *(uint4*)&Ad[(mb + it * 64) * 20 + w4] = aR[it];
        #pragma unroll
        for (int it = 0; it < 2; it++)
            *(uint4*)&Bd[(mb + it * 64) * 20 + w4] = bR[it];
    };

    ldg(0); sts(0);
    __syncthreads();
    for (int k0 = 0; k0 < K; k0 += 32) {
        int p = (k0 >> 5) & 1;
        bool more = (k0 + 32 < K);
        if (more) ldg(k0 + 32);

        uint32_t Ap = As_b + (uint32_t)p * 2560 * 4;
        uint32_t Bp = Bs_b + (uint32_t)p * 2560 * 4;
        #pragma unroll
        for (int ks = 0; ks < 2; ks++) {
            int kw = ks * 8;
            uint32_t af[4][4], bf[4][2];
            #pragma unroll
            for (int mt = 0; mt < 4; mt++) {
                int r0 = rbase + mt * 16;
                ldsm_x4(af[mt][0], af[mt][1], af[mt][2], af[mt][3],
                        Ap + (uint32_t)(((r0 + fr_row) * 20) + kw + fr_col) * 4);
            }
            ldsm_x4(bf[0][0], bf[1][0], bf[2][0], bf[3][0],
                    Bp + (uint32_t)(((cbase + lmat * 8 + lrow) * 20) + kw) * 4);
            ldsm_x4(bf[0][1], bf[1][1], bf[2][1], bf[3][1],
                    Bp + (uint32_t)(((cbase + lmat * 8 + lrow) * 20) + kw + 4) * 4);
            #pragma unroll
            for (int mt = 0; mt < 4; mt++)
                #pragma unroll
                for (int nt = 0; nt < 4; nt++)
                    MMA16(acc[mt][nt], af[mt][0], af[mt][1], af[mt][2], af[mt][3],
                          bf[nt][0], bf[nt][1]);
        }
        if (more) sts(p ^ 1);
        __syncthreads();
    }

    #pragma unroll
    for (int mt = 0; mt < 4; mt++)
        #pragma unroll
        for (int nt = 0; nt < 4; nt++) {
            int r = m0 + rbase + mt * 16 + g;
            int cN = n0 + cbase + nt * 8 + 2 * tig;
            float b0 = bias ? bias[cN] : 0.f;
            float b1 = bias ? bias[cN + 1] : 0.f;
            float v0 = acc[mt][nt][0] * scl + b0;
            float v1 = acc[mt][nt][1] * scl + b1;
            float v2 = acc[mt][nt][2] * scl + b0;
            float v3 = acc[mt][nt][3] * scl + b1;
            if (act == 1) { v0 = silu_f(v0); v1 = silu_f(v1); v2 = silu_f(v2); v3 = silu_f(v3); }
            store2(&Yb[(long)r * ldy + cN],       v0, v1);
            store2(&Yb[(long)(r + 8) * ldy + cN], v2, v3);
        }
}

// =====================================================================
// conv1 as GEMM: a1t = silu(hst . w1 + b), half token-major out.
// =====================================================================
__global__ __launch_bounds__(256) void conv1_gemm(
        const __half* __restrict__ A, const __half* __restrict__ Bm,
        const float* __restrict__ bias, __half* __restrict__ Y) {
    __shared__ __align__(16) uint32_t As32[2 * 128 * 20];
    __shared__ __align__(16) uint32_t Bs32[2 * 64 * 20];

    int b = blockIdx.z;
    const __half* Ab = A + (long)b * SS * CCH;
    __half* Yb = Y + (long)b * SS * C8;
    int m0 = blockIdx.x * 128;

    int tid = threadIdx.x;
    int w = tid >> 5, lane = tid & 31;
    int wm = w & 3, wn = w >> 2;
    int g = lane >> 2, tig = lane & 3;
    int rbase = wm * 32, cbase = wn * 32;
    int lrow = lane & 7, lmat = lane >> 3;
    int fr_row = (lmat & 1) * 8 + lrow;
    int fr_col = (lmat >> 1) * 4;
    uint32_t As_b = cvsm(As32), Bs_b = cvsm(Bs32);

    float acc[2][4][4];
    #pragma unroll
    for (int i = 0; i < 2; i++)
        #pragma unroll
        for (int j = 0; j < 4; j++)
            #pragma unroll
            for (int l = 0; l < 4; l++) acc[i][j][l] = 0.f;

    uint4 aR[2], bR;
    int w4 = (tid & 3) * 4, mb = tid >> 2;

    auto ldg = [&](int k0) {
        #pragma unroll
        for (int it = 0; it < 2; it++)
            aR[it] = *(const uint4*)&Ab[(long)(m0 + mb + it * 64) * CCH + k0 + w4 * 2];
        bR = *(const uint4*)&Bm[(long)mb * 512 + k0 + w4 * 2];
    };
    auto sts = [&](int p) {
        uint32_t* Ad = As32 + p * 2560;
        uint32_t* Bd = Bs32 + p * 1280;
        #pragma unroll
        for (int it = 0; it < 2; it++)
            *(uint4*)&Ad[(mb + it * 64) * 20 + w4] = aR[it];
        *(uint4*)&Bd[mb * 20 + w4] = bR;
    };

    ldg(0); sts(0);
    __syncthreads();
    for (int k0 = 0; k0 < 512; k0 += 32) {
        int p = (k0 >> 5) & 1;
        bool more = (k0 + 32 < 512);
        if (more) ldg(k0 + 32);

        uint32_t Ap = As_b + (uint32_t)p * 2560 * 4;
        uint32_t Bp = Bs_b + (uint32_t)p * 1280 * 4;
        #pragma unroll
        for (int ks = 0; ks < 2; ks++) {
            int kw = ks * 8;
            uint32_t af[2][4], bf[4][2];
            #pragma unroll
            for (int mt = 0; mt < 2; mt++) {
                int r0 = rbase + mt * 16;
                ldsm_x4(af[mt][0], af[mt][1], af[mt][2], af[mt][3],
                        Ap + (uint32_t)(((r0 + fr_row) * 20) + kw + fr_col) * 4);
            }
            ldsm_x4(bf[0][0], bf[1][0], bf[2][0], bf[3][0],
                    Bp + (uint32_t)(((cbase + lmat * 8 + lrow) * 20) + kw) * 4);
            ldsm_x4(bf[0][1], bf[1][1], bf[2][1], bf[3][1],
                    Bp + (uint32_t)(((cbase + lmat * 8 + lrow) * 20) + kw + 4) * 4);
            #pragma unroll
            for (int mt = 0; mt < 2; mt++)
                #pragma unroll
                for (int nt = 0; nt < 4; nt++)
                    MMA16(acc[mt][nt], af[mt][0], af[mt][1], af[mt][2], af[mt][3],
                          bf[nt][0], bf[nt][1]);
        }
        if (more) sts(p ^ 1);
        __syncthreads();
    }

    #pragma unroll
    for (int mt = 0; mt < 2; mt++)
        #pragma unroll
        for (int nt = 0; nt < 4; nt++) {
            int r = m0 + rbase + mt * 16 + g;
            int cN = cbase + nt * 8 + 2 * tig;
            float b0 = bias[cN], b1 = bias[cN + 1];
            store2(&Yb[(long)r * C8 + cN],       silu_f(acc[mt][nt][0] + b0), silu_f(acc[mt][nt][1] + b1));
            store2(&Yb[(long)(r + 8) * C8 + cN], silu_f(acc[mt][nt][2] + b0), silu_f(acc[mt][nt][3] + b1));
        }
}

// =====================================================================
// conv2 as IMPLICIT GEMM (9 taps x 64 ci), zero-padded shifts.
// =====================================================================
__global__ __launch_bounds__(256) void conv2_gemm(
        const __half* __restrict__ A, const __half* __restrict__ Bm,
        const float* __restrict__ bias, __half* __restrict__ Y) {
    __shared__ __align__(16) uint32_t As32[128 * 36];
    __shared__ __align__(16) uint32_t Bs32[64 * 36];

    int b = blockIdx.z;
    const __half* Ab = A + (long)b * SS * C8;
    __half* Yb = Y + (long)b * SS * C8;
    int m0 = blockIdx.x * 128;

    int tid = threadIdx.x;
    int w = tid >> 5, lane = tid & 31;
    int wm = w & 3, wn = w >> 2;
    int g = lane >> 2, tig = lane & 3;
    int rbase = wm * 32, cbase = wn * 32;
    int lrow = lane & 7, lmat = lane >> 3;
    int fr_row = (lmat & 1) * 8 + lrow;
    int fr_col = (lmat >> 1) * 4;
    uint32_t As_b = cvsm(As32), Bs_b = cvsm(Bs32);

    float acc[2][4][4];
    #pragma unroll
    for (int i = 0; i < 2; i++)
        #pragma unroll
        for (int j = 0; j < 4; j++)
            #pragma unroll
            for (int l = 0; l < 4; l++) acc[i][j][l] = 0.f;

    uint4 aR[4], bR[2];

    auto ldg_tap = [&](int tap) {
        int dy = tap / 3 - 1, dx = tap % 3 - 1;
        #pragma unroll
        for (int f = 0; f < 4; f++) {
            int idx = tid + f * 256;
            int r = idx >> 3, c8 = idx & 7;
            int s = m0 + r;
            int sy = (s >> 5) + dy, sx = (s & 31) + dx;
            bool valid = ((unsigned)sy < 32u) && ((unsigned)sx < 32u);
            aR[f] = valid ? *(const uint4*)&Ab[(long)((sy << 5) + sx) * C8 + c8 * 8]
                          : make_uint4(0u, 0u, 0u, 0u);
        }
        #pragma unroll
        for (int f = 0; f < 2; f++) {
            int idx = tid + f * 256;
            int r = idx >> 3, c8 = idx & 7;
            bR[f] = *(const uint4*)&Bm[(long)r * 576 + tap * 64 + c8 * 8];
        }
    };
    auto sts_tap = [&]() {
        #pragma unroll
        for (int f = 0; f < 4; f++) {
            int idx = tid + f * 256;
            int r = idx >> 3, c8 = idx & 7;
            *(uint4*)&As32[r * 36 + c8 * 4] = aR[f];
        }
        #pragma unroll
        for (int f = 0; f < 2; f++) {
            int idx = tid + f * 256;
            int r = idx >> 3, c8 = idx & 7;
            *(uint4*)&Bs32[r * 36 + c8 * 4] = bR[f];
        }
    };

    ldg_tap(0);
    for (int tap = 0; tap < 9; tap++) {
        sts_tap();
        __syncthreads();
        if (tap < 8) ldg_tap(tap + 1);

        #pragma unroll
        for (int ks = 0; ks < 4; ks++) {
            int kw = ks * 8;
            uint32_t af[2][4], bf[4][2];
            #pragma unroll
            for (int mt = 0; mt < 2; mt++) {
                int r0 = rbase + mt * 16;
                ldsm_x4(af[mt][0], af[mt][1], af[mt][2], af[mt][3],
                        As_b + (uint32_t)(((r0 + fr_row) * 36) + kw + fr_col) * 4);
            }
            ldsm_x4(bf[0][0], bf[1][0], bf[2][0], bf[3][0],
                    Bs_b + (uint32_t)(((cbase + lmat * 8 + lrow) * 36) + kw) * 4);
            ldsm_x4(bf[0][1], bf[1][1], bf[2][1], bf[3][1],
                    Bs_b + (uint32_t)(((cbase + lmat * 8 + lrow) * 36) + kw + 4) * 4);
            #pragma unroll
            for (int mt = 0; mt < 2; mt++)
                #pragma unroll
                for (int nt = 0; nt < 4; nt++)
                    MMA16(acc[mt][nt], af[mt][0], af[mt][1], af[mt][2], af[mt][3],
                          bf[nt][0], bf[nt][1]);
        }
        __syncthreads();
    }

    #pragma unroll
    for (int mt = 0; mt < 2; mt++)
        #pragma unroll
        for (int nt = 0; nt < 4; nt++) {
            int r = m0 + rbase + mt * 16 + g;
            int cN = cbase + nt * 8 + 2 * tig;
            float b0 = bias[cN], b1 = bias[cN + 1];
            store2(&Yb[(long)r * C8 + cN],       silu_f(acc[mt][nt][0] + b0), silu_f(acc[mt][nt][1] + b1));
            store2(&Yb[(long)(r + 8) * C8 + cN], silu_f(acc[mt][nt][2] + b0), silu_f(acc[mt][nt][3] + b1));
        }
}

// ---------------- conv3 (64->1) + sigmoid, token-major half input ----------------
__global__ void conv3_sig_t(const __half* __restrict__ a2t, const float* __restrict__ w,
                            const float* __restrict__ bias, float* __restrict__ y) {
    __shared__ float ws[64];
    int tid = threadIdx.x;
    if (tid < 64) ws[tid] = w[tid];
    __syncthreads();
    int idx = blockIdx.x * 256 + tid;
    const __half* p = a2t + (long)idx * C8;
    float acc = bias[0];
    #pragma unroll
    for (int f = 0; f < 8; f++) {
        uint4 v = *(const uint4*)&p[f * 8];
        const __half2* h2 = (const __half2*)&v;
        #pragma unroll
        for (int u = 0; u < 4; u++) {
            float2 fv = __half22float2(h2[u]);
            acc += fv.x * ws[f * 8 + u * 2] + fv.y * ws[f * 8 + u * 2 + 1];
        }
    }
    y[idx] = 1.0f / (1.0f + expf(-acc));
}

// ---------------- senh_t = hs_t * sw ----------------
__global__ void senh_t_mul(const __half* __restrict__ hs_t, const float* __restrict__ sw,
                           __half* __restrict__ senh_t) {
    int idx = blockIdx.x * 256 + threadIdx.x;
    int token = idx >> 6, c8 = idx & 63;
    __half2 m = __float2half2_rn(sw[token]);
    uint4 v = *(const uint4*)&hs_t[(long)token * CCH + c8 * 8];
    __half2* h = (__half2*)&v;
    h[0] = __hmul2(h[0], m); h[1] = __hmul2(h[1], m);
    h[2] = __hmul2(h[2], m); h[3] = __hmul2(h[3], m);
    *(uint4*)&senh_t[(long)token * CCH + c8 * 8] = v;
}

// =====================================================================
// Merged flash attention, exp via ex2.approx.f16x2 (2 exps / MUFU op).
// =====================================================================
#define FL_WORDS 15872

__device__ __forceinline__ void flash_std_body(
        const __half* __restrict__ Q, const __half* __restrict__ K,
        const __half* __restrict__ V, __half* __restrict__ O,
        int bh, int xq, uint32_t* smw) {
    uint32_t* Qs = smw;
    uint32_t* KP = smw + 128 * 36;
    uint32_t* Vs = smw + 2 * 128 * 36;
    float* redm = (float*)(smw + 2 * 128 * 36 + 64 * 36);
    float* redl = redm + 256;

    int b = bh >> 3, h = bh & 7;
    const __half* Qb = Q + (long)b * SS * CCH + h * 64;
    const __half* Kb = K + (long)b * SS * CCH + h * 64;
    const __half* Vb = V + (long)b * SS * CCH + h * 64;
    __half* Ob = O + (long)b * SS * (2 * CCH) + h * 64;
    int q0 = xq * 128;

    int tid = threadIdx.x;
    int w = tid >> 5, lane = tid & 31;
    int wm = w & 3, wn = w >> 2;
    int g = lane >> 2, tig = lane & 3;
    int rbase = wm * 32, cbase = wn * 32;
    int lrow = lane & 7, lmat = lane >> 3;
    int fr_row = (lmat & 1) * 8 + lrow;
    int fr_col = (lmat >> 1) * 4;
    int t_kb = lmat >> 1, t_hb = lmat & 1;
    uint32_t Qs_b = cvsm(Qs), KP_b = cvsm(KP), Vs_b = cvsm(Vs);

    #pragma unroll
    for (int f = 0; f < 4; f++) {
        int idx = tid + f * 256;
        int r = idx >> 3, w4 = (idx & 7) * 4;
        uint4 v4 = *(const uint4*)&Qb[(long)(q0 + r) * CCH + (idx & 7) * 8];
        *(uint4*)&Qs[r * 36 + w4] = v4;
    }

    uint4 kR[2], vR[2];
    int st_r = tid >> 3, st_w4 = (tid & 7) * 4, st_c = (tid & 7) * 8;
    auto ldg_kv = [&](int j) {
        #pragma unroll
        for (int f = 0; f < 2; f++) {
            long goff = (long)(j * 64 + st_r + f * 32) * CCH + st_c;
            kR[f] = *(const uint4*)&Kb[goff];
            vR[f] = *(const uint4*)&Vb[goff];
        }
    };
    auto sts_kv = [&]() {
        #pragma unroll
        for (int f = 0; f < 2; f++) {
            *(uint4*)&KP[(st_r + f * 32) * 36 + st_w4] = kR[f];
            *(uint4*)&Vs[(st_r + f * 32) * 36 + st_w4] = vR[f];
        }
    };

    float accO[2][4][4];
    #pragma unroll
    for (int i = 0; i < 2; i++)
        #pragma unroll
        for (int j = 0; j < 4; j++)
            #pragma unroll
            for (int l = 0; l < 4; l++) accO[i][j][l] = 0.f;
    float mst[4] = { -1e30f, -1e30f, -1e30f, -1e30f };
    float lst[4] = { 0.f, 0.f, 0.f, 0.f };

    ldg_kv(0);
    for (int j = 0; j < 16; j++) {
        sts_kv();
        __syncthreads();
        if (j + 1 < 16) ldg_kv(j + 1);

        float acc[2][4][4];
        #pragma unroll
        for (int i = 0; i < 2; i++)
            #pragma unroll
            for (int jj = 0; jj < 4; jj++)
                #pragma unroll
                for (int l = 0; l < 4; l++) acc[i][jj][l] = 0.f;
        #pragma unroll
        for (int ks = 0; ks < 4; ks++) {
            int kw = ks * 8;
            uint32_t af[2][4], bf[4][2];
            #pragma unroll
            for (int mt = 0; mt < 2; mt++) {
                int r0 = rbase + mt * 16;
                ldsm_x4(af[mt][0], af[mt][1], af[mt][2], af[mt][3],
                        Qs_b + (uint32_t)(((r0 + fr_row) * 36) + kw + fr_col) * 4);
            }
            ldsm_x4(bf[0][0], bf[1][0], bf[2][0], bf[3][0],
                    KP_b + (uint32_t)(((cbase + lmat * 8 + lrow) * 36) + kw) * 4);
            ldsm_x4(bf[0][1], bf[1][1], bf[2][1], bf[3][1],
                    KP_b + (uint32_t)(((cbase + lmat * 8 + lrow) * 36) + kw + 4) * 4);
            #pragma unroll
            for (int mt = 0; mt < 2; mt++)
                #pragma unroll
                for (int nt = 0; nt < 4; nt++)
                    MMA16(acc[mt][nt], af[mt][0], af[mt][1], af[mt][2], af[mt][3],
                          bf[nt][0], bf[nt][1]);
        }

        #pragma unroll
        for (int mt = 0; mt < 2; mt++)
            #pragma unroll
            for (int hh = 0; hh < 2; hh++) {
                float mx = -1e30f;
                #pragma unroll
                for (int nt = 0; nt < 4; nt++) {
                    mx = fmaxf(mx, acc[mt][nt][hh * 2]);
                    mx = fmaxf(mx, acc[mt][nt][hh * 2 + 1]);
                }
                mx = fmaxf(mx, __shfl_xor_sync(0xffffffffu, mx, 1));
                mx = fmaxf(mx, __shfl_xor_sync(0xffffffffu, mx, 2));
                if (tig == 0) redm[wn * 128 + rbase + mt * 16 + hh * 8 + g] = mx;
            }
        __syncthreads();

        #pragma unroll
        for (int mt = 0; mt < 2; mt++)
            #pragma unroll
            for (int hh = 0; hh < 2; hh++) {
                int i = mt * 2 + hh;
                int rloc = rbase + mt * 16 + hh * 8 + g;
                float mch = fmaxf(redm[rloc], redm[128 + rloc]);
                float mnew = fmaxf(mst[i], mch);
                float corr = __expf(mst[i] - mnew);
                mst[i] = mnew;
                float s = 0.f;
                #pragma unroll
                for (int nt = 0; nt < 4; nt++) {
                    uint32_t ph = exp2_h2((acc[mt][nt][hh * 2]     - mnew) * L2E,
                                          (acc[mt][nt][hh * 2 + 1] - mnew) * L2E);
                    KP[rloc * 36 + wn * 16 + nt * 4 + tig] = ph;
                    float2 pf = __half22float2(*(__half2*)&ph);
                    s += pf.x + pf.y;
                    accO[mt][nt][hh * 2]     *= corr;
                    accO[mt][nt][hh * 2 + 1] *= corr;
                }
                s += __shfl_xor_sync(0xffffffffu, s, 1);
                s += __shfl_xor_sync(0xffffffffu, s, 2);
                if (tig == 0) redl[wn * 128 + rloc] = s;
                lst[i] *= corr;
            }
        __syncthreads();
        #pragma unroll
        for (int mt = 0; mt < 2; mt++)
            #pragma unroll
            for (int hh = 0; hh < 2; hh++) {
                int rloc = rbase + mt * 16 + hh * 8 + g;
                lst[mt * 2 + hh] += redl[rloc] + redl[128 + rloc];
            }

        #pragma unroll
        for (int ks = 0; ks < 4; ks++) {
            int kw = ks * 8;
            uint32_t af[2][4], bf[4][2];
            #pragma unroll
            for (int mt = 0; mt < 2; mt++) {
                int r0 = rbase + mt * 16;
                ldsm_x4(af[mt][0], af[mt][1], af[mt][2], af[mt][3],
                        KP_b + (uint32_t)(((r0 + fr_row) * 36) + kw + fr_col) * 4);
            }
            uint32_t vaddr = Vs_b + (uint32_t)((ks * 16 + t_kb * 8 + lrow) * 144
                                               + (cbase + t_hb * 8) * 2);
            ldsm_x4_t(bf[0][0], bf[1][0], bf[0][1], bf[1][1], vaddr);
            ldsm_x4_t(bf[2][0], bf[3][0], bf[2][1], bf[3][1], vaddr + 32);
            #pragma unroll
            for (int mt = 0; mt < 2; mt++)
                #pragma unroll
                for (int nt = 0; nt < 4; nt++)
                    MMA16(accO[mt][nt], af[mt][0], af[mt][1], af[mt][2], af[mt][3],
                          bf[nt][0], bf[nt][1]);
        }
        __syncthreads();
    }

    #pragma unroll
    for (int mt = 0; mt < 2; mt++) {
        float inv0 = 1.0f / lst[mt * 2];
        float inv1 = 1.0f / lst[mt * 2 + 1];
        #pragma unroll
        for (int nt = 0; nt < 4; nt++) {
            int r = q0 + rbase + mt * 16 + g;
            int c = cbase + nt * 8 + 2 * tig;
            store2(&Ob[(long)r * 1024 + c],       accO[mt][nt][0] * inv0, accO[mt][nt][1] * inv0);
            store2(&Ob[(long)(r + 8) * 1024 + c], accO[mt][nt][2] * inv1, accO[mt][nt][3] * inv1);
        }
    }
}

__device__ __forceinline__ void flash_multi_body(
        const __half* __restrict__ Q, const __half* __restrict__ K,
        const __half* __restrict__ V, __half* __restrict__ O,
        int z, int xq, uint32_t* smw) {
    uint32_t* Qs = smw;
    uint32_t* Ks = smw + 8448;
    uint32_t* Ps = smw + 8448 + 2304;
    uint32_t* Vs = smw + 8448 + 2 * 2304;
    float* redm = (float*)(smw + 8448 + 3 * 2304);
    float* redl = redm + 256;

    const __half* Qb = Q + (long)z * SS * C2;
    const __half* Kb = K + (long)z * SS * C2;
    const __half* Vb = V + (long)z * SS * C2;
    int br = z >> 3, b = z & 7;
    __half* Ob = O + (long)b * SS * 1024 + 512 + br * 256;
    int q0 = xq * 64;

    int tid = threadIdx.x;
    int w = tid >> 5, lane = tid & 31;
    int wm = w & 1, wn = w >> 1;
    int g = lane >> 2, tig = lane & 3;
    int rbase = wm * 32;
    int lrow = lane & 7, lmat = lane >> 3;
    int fr_row = (lmat & 1) * 8 + lrow;
    int fr_col = (lmat >> 1) * 4;
    int t_kb = lmat >> 1, t_hb = lmat & 1;
    uint32_t Qs_b = cvsm(Qs), Ks_b = cvsm(Ks), Ps_b = cvsm(Ps), Vs_b = cvsm(Vs);

    #pragma unroll
    for (int f = 0; f < 8; f++) {
        int idx = tid + f * 256;
        int r = idx >> 5, c8 = idx & 31;
        uint4 qv = *(const uint4*)&Qb[(long)(q0 + r) * C2 + c8 * 8];
        *(uint4*)&Qs[r * 132 + c8 * 4] = qv;
    }

    int st_r = tid >> 3, st_w4 = (tid & 7) * 4, st_c = (tid & 7) * 8;
    uint4 sR[2];
    auto ldg_s = [&](const __half* P, int j, int dc) {
        #pragma unroll
        for (int f = 0; f < 2; f++)
            sR[f] = *(const uint4*)&P[(long)(j * 64 + st_r + f * 32) * C2 + dc * 64 + st_c];
    };
    auto sts_s = [&](uint32_t* D) {
        #pragma unroll
        for (int f = 0; f < 2; f++)
            *(uint4*)&D[(st_r + f * 32) * 36 + st_w4] = sR[f];
    };

    float accO[2][8][4];
    #pragma unroll
    for (int i = 0; i < 2; i++)
        #pragma unroll
        for (int j = 0; j < 8; j++)
            #pragma unroll
            for (int l = 0; l < 4; l++) accO[i][j][l] = 0.f;
    float mst[4] = { -1e30f, -1e30f, -1e30f, -1e30f };
    float lst[4] = { 0.f, 0.f, 0.f, 0.f };

    for (int j = 0; j < 16; j++) {
        float acc[2][2][4];
        #pragma unroll
        for (int i = 0; i < 2; i++)
            #pragma unroll
            for (int jj = 0; jj < 2; jj++)
                #pragma unroll
                for (int l = 0; l < 4; l++) acc[i][jj][l] = 0.f;

        ldg_s(Kb, j, 0);
        for (int dc = 0; dc < 4; dc++) {
            sts_s(Ks);
            __syncthreads();
            if (dc < 3) ldg_s(Kb, j, dc + 1);
            #pragma unroll
            for (int ks = 0; ks < 4; ks++) {
                int kw = ks * 8;
                uint32_t af[2][4], bf[2][2];
                #pragma unroll
                for (int mt = 0; mt < 2; mt++) {
                    int r0 = rbase + mt * 16;
                    ldsm_x4(af[mt][0], af[mt][1], af[mt][2], af[mt][3],
                            Qs_b + (uint32_t)(((r0 + fr_row) * 132) + dc * 32 + kw + fr_col) * 4);
                }
                ldsm_x4(bf[0][0], bf[1][0], bf[0][1], bf[1][1],
                        Ks_b + (uint32_t)(((wn * 16 + fr_row) * 36) + kw + fr_col) * 4);
                #pragma unroll
                for (int mt = 0; mt < 2; mt++)
                    #pragma unroll
                    for (int nt = 0; nt < 2; nt++)
                        MMA16(acc[mt][nt], af[mt][0], af[mt][1], af[mt][2], af[mt][3],
                              bf[nt][0], bf[nt][1]);
            }
            __syncthreads();
        }

        #pragma unroll
        for (int mt = 0; mt < 2; mt++)
            #pragma unroll
            for (int hh = 0; hh < 2; hh++) {
                float mx = -1e30f;
                #pragma unroll
                for (int nt = 0; nt < 2; nt++) {
                    mx = fmaxf(mx, acc[mt][nt][hh * 2]);
                    mx = fmaxf(mx, acc[mt][nt][hh * 2 + 1]);
                }
                mx = fmaxf(mx, __shfl_xor_sync(0xffffffffu, mx, 1));
                mx = fmaxf(mx, __shfl_xor_sync(0xffffffffu, mx, 2));
                if (tig == 0) redm[wn * 64 + rbase + mt * 16 + hh * 8 + g] = mx;
            }
        __syncthreads();

        #pragma unroll
        for (int mt = 0; mt < 2; mt++)
            #pragma unroll
            for (int hh = 0; hh < 2; hh++) {
                int i = mt * 2 + hh;
                int rloc = rbase + mt * 16 + hh * 8 + g;
                float mch = fmaxf(fmaxf(redm[rloc], redm[64 + rloc]),
                                  fmaxf(redm[128 + rloc], redm[192 + rloc]));
                float mnew = fmaxf(mst[i], mch);
                float corr = __expf(mst[i] - mnew);
                mst[i] = mnew;
                float s = 0.f;
                #pragma unroll
                for (int nt = 0; nt < 2; nt++) {
                    uint32_t ph = exp2_h2((acc[mt][nt][hh * 2]     - mnew) * L2E,
                                          (acc[mt][nt][hh * 2 + 1] - mnew) * L2E);
                    Ps[rloc * 36 + wn * 8 + nt * 4 + tig] = ph;
                    float2 pf = __half22float2(*(__half2*)&ph);
                    s += pf.x + pf.y;
                }
                s += __shfl_xor_sync(0xffffffffu, s, 1);
                s += __shfl_xor_sync(0xffffffffu, s, 2);
                if (tig == 0) redl[wn * 64 + rloc] = s;
                lst[i] *= corr;
                #pragma unroll
                for (int nt = 0; nt < 8; nt++) {
                    accO[mt][nt][hh * 2]     *= corr;
                    accO[mt][nt][hh * 2 + 1] *= corr;
                }
            }
        __syncthreads();
        #pragma unroll
        for (int mt = 0; mt < 2; mt++)
            #pragma unroll
            for (int hh = 0; hh < 2; hh++) {
                int rloc = rbase + mt * 16 + hh * 8 + g;
                lst[mt * 2 + hh] += redl[rloc] + redl[64 + rloc]
                                  + redl[128 + rloc] + redl[192 + rloc];
            }

        ldg_s(Vb, j, 0);
        for (int dc = 0; dc < 4; dc++) {
            sts_s(Vs);
            __syncthreads();
            if (dc < 3) ldg_s(Vb, j, dc + 1);
            #pragma unroll
            for (int ks = 0; ks < 4; ks++) {
                int kw = ks * 8;
                uint32_t af[2][4], bf[2][2];
                #pragma unroll
                for (int mt = 0; mt < 2; mt++) {
                    int r0 = rbase + mt * 16;
                    ldsm_x4(af[mt][0], af[mt][1], af[mt][2], af[mt][3],
                            Ps_b + (uint32_t)(((r0 + fr_row) * 36) + kw + fr_col) * 4);
                }
                uint32_t vaddr = Vs_b + (uint32_t)((ks * 16 + t_kb * 8 + lrow) * 144
                                                   + (wn * 16 + t_hb * 8) * 2);
                ldsm_x4_t(bf[0][0], bf[1][0], bf[0][1], bf[1][1], vaddr);
                #pragma unroll
                for (int mt = 0; mt < 2; mt++)
                    #pragma unroll
                    for (int nt = 0; nt < 2; nt++)
                        MMA16(accO[mt][dc * 2 + nt], af[mt][0], af[mt][1], af[mt][2], af[mt][3],
                              bf[nt][0], bf[nt][1]);
            }
            __syncthreads();
        }
    }

    #pragma unroll
    for (int mt = 0; mt < 2; mt++) {
        float inv0 = 1.0f / lst[mt * 2];
        float inv1 = 1.0f / lst[mt * 2 + 1];
        #pragma unroll
        for (int u = 0; u < 8; u++) {
            int dc = u >> 1, nt = u & 1;
            int r = q0 + rbase + mt * 16 + g;
            int c = dc * 64 + wn * 16 + nt * 8 + 2 * tig;
            store2(&Ob[(long)r * 1024 + c],       accO[mt][u][0] * inv0, accO[mt][u][1] * inv0);
            store2(&Ob[(long)(r + 8) * 1024 + c], accO[mt][u][2] * inv1, accO[mt][u][3] * inv1);
        }
    }
}

__global__ __launch_bounds__(256, 2) void flash_all(
        const __half* __restrict__ q, const __half* __restrict__ k,
        const __half* __restrict__ v,
        const __half* __restrict__ qm, const __half* __restrict__ km,
        const __half* __restrict__ vm, __half* __restrict__ comb) {
    extern __shared__ uint32_t smw[];
    int bx = blockIdx.x;
    if (bx < 512) flash_std_body(q, k, v, comb, bx >> 3, bx & 7, smw);
    else { int i = bx - 512; flash_multi_body(qm, km, vm, comb, i >> 4, i & 15, smw); }
}

// ---------------- launch ----------------
static void* symv(const void* s) { void* p = nullptr; cudaGetSymbolAddress(&p, s); return p; }

extern "C" void kernel_launch(void* const* d_in, const int* in_sizes, int n_in,
                              void* d_out, int out_size) {
    (void)in_sizes; (void)n_in; (void)out_size;
    const float* x      = (const float*)d_in[0];
    const float* pre_g  = (const float*)d_in[1];
    const float* pre_b  = (const float*)d_in[2];
    const float* norm_g = (const float*)d_in[3];
    const float* norm_b = (const float*)d_in[4];
    const float* post_g = (const float*)d_in[5];
    const float* post_b = (const float*)d_in[6];
    const float* pos    = (const float*)d_in[7];
    const float* sa_w1  = (const float*)d_in[8];
    const float* sa_b1  = (const float*)d_in[9];
    const float* sa_w2  = (const float*)d_in[10];
    const float* sa_b2  = (const float*)d_in[11];
    const float* sa_w3  = (const float*)d_in[12];
    const float* sa_b3  = (const float*)d_in[13];
    const float* wq     = (const float*)d_in[14];
    const float* wk     = (const float*)d_in[15];
    const float* wv     = (const float*)d_in[16];
    const float* wq0    = (const float*)d_in[17];
    const float* wk0    = (const float*)d_in[18];
    const float* wv0    = (const float*)d_in[19];
    const float* wq1    = (const float*)d_in[20];
    const float* wk1    = (const float*)d_in[21];
    const float* wv1    = (const float*)d_in[22];
    const float* ff_w1  = (const float*)d_in[23];
    const float* ff_b1  = (const float*)d_in[24];
    const float* ff_w2  = (const float*)d_in[25];
    const float* ff_b2  = (const float*)d_in[26];
    const float* out_w  = (const float*)d_in[27];
    const float* out_b  = (const float*)d_in[28];
    float* out = (float*)d_out;

    __half *hst = (__half*)symv(d_hst), *shnt = (__half*)symv(d_shnt), *senht = (__half*)symv(d_senht);
    __half *a1t = (__half*)symv(d_a1t), *a2t = (__half*)symv(d_a2t);
    float  *sw = (float*)symv(d_swt);
    __half *q = (__half*)symv(d_q), *k = (__half*)symv(d_k), *v = (__half*)symv(d_v);
    __half *qm = (__half*)symv(d_qm), *km = (__half*)symv(d_km), *vm = (__half*)symv(d_vm);
    __half *comb = (__half*)symv(d_comb), *f1 = (__half*)symv(d_f1), *fus = (__half*)symv(d_fus);
    float  *fin = (float*)symv(d_fin);
    __half *wb = (__half*)symv(d_w);
    __half *w2h = (__half*)symv(d_w2);

    const int flSmem = FL_WORDS * 4;
    cudaFuncSetAttribute(flash_all, cudaFuncAttributeMaxDynamicSharedMemorySize, flSmem);
    const int gnSmem = 16 * 1024 * 4;
    cudaFuncSetAttribute(gn_fused, cudaFuncAttributeMaxDynamicSharedMemorySize, gnSmem);

    const float* wsrc[13] = { wq, wk, wv, wq0, wk0, wv0, wq1, wk1, wv1,
                              ff_w1, ff_w2, out_w, sa_w1 };
    const int wcnt[13] = { 262144, 262144, 262144, 131072, 131072, 131072,
                           131072, 131072, 131072, 524288, 262144, 262144, 32768 };
    WC wc; int off = 0;
    __half* hw[13];
    for (int i = 0; i < 13; i++) {
        wc.src[i] = wsrc[i]; wc.cnt4[i] = wcnt[i] / 4; wc.off[i] = off;
        hw[i] = wb + off;
        off += wcnt[i];
    }
    wcvt<<<dim3(512, 13), 256>>>(wc, wb);
    w2cvt<<<144, 256>>>(sa_w2, w2h);

    gn_fused<<<BATCH * NGR, 256, gnSmem>>>(x, pre_g, pre_b, pos, norm_g, norm_b,
                                           hst, shnt);
    conv1_gemm<<<dim3(8, 1, BATCH), 256>>>(hst, hw[12], sa_b1, a1t);
    conv2_gemm<<<dim3(8, 1, BATCH), 256>>>(a1t, w2h, sa_b2, a2t);
    conv3_sig_t<<<BATCH * SS / 256, 256>>>(a2t, sa_w3, sa_b3, sw);
    senh_t_mul<<<BATCH * SS * CCH / 8 / 256, 256>>>(hst, sw, senht);

    // QKV projections (q pre-scaled by 1/8)
    GArg pq = {};
    pq.A[0] = shnt; pq.A[1] = shnt; pq.A[2] = shnt;
    pq.W[0] = hw[0]; pq.W[1] = hw[1]; pq.W[2] = hw[2];
    pq.Y[0] = q;    pq.Y[1] = k;    pq.Y[2] = v;
    pq.bias[0] = pq.bias[1] = pq.bias[2] = nullptr;
    pq.sc[0] = 0.125f; pq.sc[1] = 1.f; pq.sc[2] = 1.f;
    pq.aOuter = (long)SS * CCH; pq.yOuter = (long)SS * 512;
    pq.K = 512; pq.lda = 512; pq.N = 512; pq.ldy = 512; pq.act = 0;
    gemm128<__half><<<dim3(8, 4, 24), 256>>>(pq);

    // multi-scale projections (qm pre-scaled by 1/16)
    long moff = 8LL * SS * C2;
    GArg pm = {};
    pm.A[0] = senht; pm.A[1] = shnt; pm.A[2] = shnt;
    pm.A[3] = senht; pm.A[4] = shnt; pm.A[5] = shnt;
    pm.W[0] = hw[3]; pm.W[1] = hw[4]; pm.W[2] = hw[5];
    pm.W[3] = hw[6]; pm.W[4] = hw[7]; pm.W[5] = hw[8];
    pm.Y[0] = qm;        pm.Y[1] = km;        pm.Y[2] = vm;
    pm.Y[3] = qm + moff; pm.Y[4] = km + moff; pm.Y[5] = vm + moff;
    for (int i = 0; i < 6; i++) pm.bias[i] = nullptr;
    pm.sc[0] = 0.0625f; pm.sc[1] = 1.f; pm.sc[2] = 1.f;
    pm.sc[3] = 0.0625f; pm.sc[4] = 1.f; pm.sc[5] = 1.f;
    pm.aOuter = (long)SS * CCH; pm.yOuter = (long)SS * C2;
    pm.K = 512; pm.lda = 512; pm.N = 256; pm.ldy = 256; pm.act = 0;
    gemm128<__half><<<dim3(8, 2, 48), 256>>>(pm);

    // merged flash
    flash_all<<<768, 256, flSmem>>>(q, k, v, qm, km, vm, comb);

    // ff1 (silu)
    GArg f1a = {};
    f1a.A[0] = comb; f1a.W[0] = hw[9]; f1a.Y[0] = f1; f1a.bias[0] = ff_b1;
    f1a.sc[0] = 1.f;
    f1a.aOuter = (long)SS * 2 * CCH; f1a.yOuter = (long)SS * CCH;
    f1a.K = 1024; f1a.lda = 1024; f1a.N = 512; f1a.ldy = 512; f1a.act = 1;
    gemm128<__half><<<dim3(8, 4, 8), 256>>>(f1a);
    // ff2
    GArg f2a = {};
    f2a.A[0] = f1; f2a.W[0] = hw[10]; f2a.Y[0] = fus; f2a.bias[0] = ff_b2;
    f2a.sc[0] = 1.f;
    f2a.aOuter = (long)SS * CCH; f2a.yOuter = (long)SS * CCH;
    f2a.K = 512; f2a.lda = 512; f2a.N = 512; f2a.ldy = 512; f2a.act = 0;
    gemm128<__half><<<dim3(8, 4, 8), 256>>>(f2a);
    // out proj
    GArg oa = {};
    oa.A[0] = fus; oa.W[0] = hw[11]; oa.Y[0] = fin; oa.bias[0] = out_b;
    oa.sc[0] = 1.f;
    oa.aOuter = (long)SS * CCH; oa.yOuter = (long)SS * CCH;
    oa.K = 512; oa.lda = 512; oa.N = 512; oa.ldy = 512; oa.act = 0;
    gemm128<float><<<dim3(8, 4, 8), 256>>>(oa);

    // post GN + residual
    gn_post_k<<<BATCH * NGR, 256>>>(fin, post_g, post_b, x, out);
}

// round 15
// speedup vs baseline: 1.1277x; 1.0099x over previous
#include <cuda_runtime.h>
#include <cuda_fp16.h>
#include <math.h>
#include <stdint.h>

#define BATCH 8
#define CCH 512
#define SS 1024
#define NHD 8
#define NGR 32
#define CG 16
#define C8 64
#define C2 256
#define GEPS 1e-6f
#define L2E 1.4426950408889634f

// ---------------- static scratch ----------------
__device__ __half d_hst  [BATCH*SS*CCH];
__device__ __half d_shnt [BATCH*SS*CCH];
__device__ __half d_senht[BATCH*SS*CCH];
__device__ __half d_a1t  [BATCH*SS*C8];
__device__ __half d_a2t  [BATCH*SS*C8];
__device__ float  d_swt  [BATCH*SS];
__device__ __half d_q    [BATCH*SS*CCH];
__device__ __half d_k    [BATCH*SS*CCH];
__device__ __half d_v    [BATCH*SS*CCH];
__device__ __half d_qm   [2*BATCH*SS*C2];
__device__ __half d_km   [2*BATCH*SS*C2];
__device__ __half d_vm   [2*BATCH*SS*C2];
__device__ __half d_comb [BATCH*SS*2*CCH];
__device__ __half d_f1   [BATCH*SS*CCH];
__device__ __half d_fus  [BATCH*SS*CCH];
__device__ float  d_fin  [BATCH*SS*CCH];
__device__ __half d_w    [2654208];
__device__ __half d_w2   [36864];

// ---------------- helpers ----------------
__device__ __forceinline__ float blk_sum(float v, float* sb, int tid) {
    sb[tid] = v; __syncthreads();
    for (int o = 128; o > 0; o >>= 1) { if (tid < o) sb[tid] += sb[tid + o]; __syncthreads(); }
    float r = sb[0]; __syncthreads(); return r;
}
__device__ __forceinline__ float silu_f(float x) { return x / (1.0f + expf(-x)); }
__device__ __forceinline__ uint32_t pack2(float a, float b) {
    __half2 h = __floats2half2_rn(a, b);
    return *reinterpret_cast<uint32_t*>(&h);
}
__device__ __forceinline__ void store2(float* p, float a, float b) {
    *(float2*)p = make_float2(a, b);
}
__device__ __forceinline__ void store2(__half* p, float a, float b) {
    *(uint32_t*)p = pack2(a, b);
}
__device__ __forceinline__ uint32_t exp2_h2(float t0, float t1) {
    uint32_t h = pack2(t0, t1);
    uint32_t r;
    asm("ex2.approx.f16x2 %0, %1;" : "=r"(r) : "r"(h));
    return r;
}
__device__ __forceinline__ uint32_t cvsm(const void* p) {
    return (uint32_t)__cvta_generic_to_shared(p);
}
__device__ __forceinline__ void ldsm_x4(uint32_t& r0, uint32_t& r1, uint32_t& r2,
                                        uint32_t& r3, uint32_t addr) {
    asm volatile("ldmatrix.sync.aligned.m8n8.x4.shared.b16 {%0,%1,%2,%3}, [%4];"
        : "=r"(r0), "=r"(r1), "=r"(r2), "=r"(r3) : "r"(addr));
}
__device__ __forceinline__ void ldsm_x4_t(uint32_t& r0, uint32_t& r1, uint32_t& r2,
                                          uint32_t& r3, uint32_t addr) {
    asm volatile("ldmatrix.sync.aligned.m8n8.x4.trans.shared.b16 {%0,%1,%2,%3}, [%4];"
        : "=r"(r0), "=r"(r1), "=r"(r2), "=r"(r3) : "r"(addr));
}

#define MMA16(d, a0, a1, a2, a3, b0, b1) \
    asm volatile("mma.sync.aligned.m16n8k16.row.col.f32.f16.f16.f32 " \
        "{%0,%1,%2,%3},{%4,%5,%6,%7},{%8,%9},{%0,%1,%2,%3};" \
        : "+f"((d)[0]), "+f"((d)[1]), "+f"((d)[2]), "+f"((d)[3]) \
        : "r"(a0), "r"(a1), "r"(a2), "r"(a3), "r"(b0), "r"(b1))

// ---------------- weight conversion fp32 -> half ----------------
struct WC { const float* src[13]; int cnt4[13]; int off[13]; };
__global__ void wcvt(WC wc, __half* dst) {
    int which = blockIdx.y;
    int idx = blockIdx.x * 256 + threadIdx.x;
    if (idx < wc.cnt4[which]) {
        float4 v = *(const float4*)&wc.src[which][idx * 4];
        uint2 pk = make_uint2(pack2(v.x, v.y), pack2(v.z, v.w));
        *(uint2*)&dst[wc.off[which] + idx * 4] = pk;
    }
}
__global__ void w2cvt(const float* __restrict__ src, __half* __restrict__ dst) {
    int idx = blockIdx.x * 256 + threadIdx.x;
    if (idx < 36864) {
        int oc = idx / 576, rem = idx % 576;
        int tap = rem >> 6, ci = rem & 63;
        dst[idx] = __float2half(src[oc * 576 + ci * 9 + tap]);
    }
}

// =====================================================================
// Fused double GroupNorm -> half token-major hs_t, shn_t.
// =====================================================================
__global__ void gn_fused(const float* __restrict__ x,
                         const float* __restrict__ pre_g, const float* __restrict__ pre_b,
                         const float* __restrict__ pos,
                         const float* __restrict__ norm_g, const float* __restrict__ norm_b,
                         __half* __restrict__ hs_t, __half* __restrict__ shn_t) {
    extern __shared__ float xs[];
    __shared__ float sb[256];
    __shared__ float pgs[16], pbs[16], ngs[16], nbs[16];

    int tid = threadIdx.x;
    int b = blockIdx.x / NGR, gi = blockIdx.x % NGR;
    long base = (long)b * CCH * SS + (long)gi * CG * SS;
    if (tid < 16) {
        int c = gi * 16 + tid;
        pgs[tid] = pre_g[c]; pbs[tid] = pre_b[c];
        ngs[tid] = norm_g[c]; nbs[tid] = norm_b[c];
    }

    float s1 = 0.f, s2 = 0.f;
    for (int i = tid; i < CG * SS; i += 256) {
        float v = x[base + i];
        xs[i] = v; s1 += v; s2 += v * v;
    }
    s1 = blk_sum(s1, sb, tid);
    s2 = blk_sum(s2, sb, tid);
    float mu1 = s1 / (float)(CG * SS);
    float inv1 = rsqrtf(s2 / (float)(CG * SS) - mu1 * mu1 + GEPS);

    float t1 = 0.f, t2 = 0.f;
    for (int i = tid; i < CG * SS; i += 256) {
        int cl = i >> 10, s = i & 1023;
        int c = gi * CG + cl;
        float h = (xs[i] - mu1) * inv1 * pgs[cl] + pbs[cl] + pos[(long)c * SS + s];
        xs[i] = h;
        t1 += h; t2 += h * h;
    }
    t1 = blk_sum(t1, sb, tid);
    t2 = blk_sum(t2, sb, tid);
    float mu2 = t1 / (float)(CG * SS);
    float inv2 = rsqrtf(t2 / (float)(CG * SS) - mu2 * mu2 + GEPS);

    long tbase = ((long)b * SS) * CCH + gi * 16;
    for (int s = tid; s < SS; s += 256) {
        uint32_t wh[8], wn[8];
        #pragma unroll
        for (int cl = 0; cl < 16; cl += 2) {
            float h0 = xs[cl * 1024 + s], h1 = xs[(cl + 1) * 1024 + s];
            wh[cl >> 1] = pack2(h0, h1);
            float n0 = (h0 - mu2) * inv2 * ngs[cl] + nbs[cl];
            float n1 = (h1 - mu2) * inv2 * ngs[cl + 1] + nbs[cl + 1];
            wn[cl >> 1] = pack2(n0, n1);
        }
        __half* ph = hs_t + tbase + (long)s * CCH;
        *(uint4*)ph       = make_uint4(wh[0], wh[1], wh[2], wh[3]);
        *(uint4*)(ph + 8) = make_uint4(wh[4], wh[5], wh[6], wh[7]);
        __half* pn = shn_t + tbase + (long)s * CCH;
        *(uint4*)pn       = make_uint4(wn[0], wn[1], wn[2], wn[3]);
        *(uint4*)(pn + 8) = make_uint4(wn[4], wn[5], wn[6], wn[7]);
    }
}

// ---------------- group norm token-major + residual ----------------
__global__ void gn_post_k(const float* __restrict__ xt, const float* __restrict__ g,
                          const float* __restrict__ be, const float* __restrict__ resid,
                          float* __restrict__ y) {
    __shared__ float sb[256];
    int tid = threadIdx.x;
    int b = blockIdx.x / NGR, gi = blockIdx.x % NGR;
    long tbase = (long)b * SS * CCH + gi * CG;
    float s1 = 0.f, s2 = 0.f;
    for (int i = tid; i < CG * SS; i += 256) {
        int s = i >> 4, cl = i & 15;
        float v = xt[tbase + (long)s * CCH + cl]; s1 += v; s2 += v * v;
    }
    s1 = blk_sum(s1, sb, tid);
    s2 = blk_sum(s2, sb, tid);
    float mu = s1 / (float)(CG * SS);
    float var = s2 / (float)(CG * SS) - mu * mu;
    float inv = rsqrtf(var + GEPS);
    for (int i = tid; i < CG * SS; i += 256) {
        int s = i >> 4, cl = i & 15;
        int c = gi * CG + cl;
        float v = (xt[tbase + (long)s * CCH + cl] - mu) * inv * g[c] + be[c];
        long oidx = (long)b * CCH * SS + (long)c * SS + s;
        y[oidx] = v + resid[oidx];
    }
}

// =====================================================================
// Unified fp16 GEMM (NT), 128x128 tile, half weights.
// =====================================================================
struct GArg {
    const __half* A[6]; const __half* W[6]; void* Y[6]; const float* bias[6];
    float sc[6];
    long aOuter, yOuter;
    int K, lda, N, ldy, act;
};

template<typename OutT>
__global__ __launch_bounds__(256, 2) void gemm128(GArg ga) {
    __shared__ __align__(16) uint32_t As32[2 * 128 * 20];
    __shared__ __align__(16) uint32_t Bs32[2 * 128 * 20];

    int z = blockIdx.z;
    int which = z >> 3, b = z & 7;
    const __half* Ab = ga.A[which] + (long)b * ga.aOuter;
    const __half* Bb = ga.W[which];
    OutT*         Yb = (OutT*)ga.Y[which] + (long)b * ga.yOuter;
    const float* bias = ga.bias[which];
    float scl = ga.sc[which];
    int K = ga.K, lda = ga.lda, ldy = ga.ldy, act = ga.act;
    int m0 = blockIdx.x * 128, n0 = blockIdx.y * 128;

    int tid = threadIdx.x;
    int w = tid >> 5, lane = tid & 31;
    int wm = w & 1, wn = w >> 1;
    int g = lane >> 2, tig = lane & 3;
    int rbase = wm * 64, cbase = wn * 32;
    int lrow = lane & 7, lmat = lane >> 3;
    int fr_row = (lmat & 1) * 8 + lrow;
    int fr_col = (lmat >> 1) * 4;
    uint32_t As_b = cvsm(As32), Bs_b = cvsm(Bs32);

    float acc[4][4][4];
    #pragma unroll
    for (int i = 0; i < 4; i++)
        #pragma unroll
        for (int j = 0; j < 4; j++)
            #pragma unroll
            for (int l = 0; l < 4; l++) acc[i][j][l] = 0.f;

    uint4 aR[2], bR[2];
    int w4 = (tid & 3) * 4, mb = tid >> 2;

    auto ldg = [&](int k0) {
        #pragma unroll
        for (int it = 0; it < 2; it++)
            aR[it] = *(const uint4*)&Ab[(long)(m0 + mb + it * 64) * lda + k0 + w4 * 2];
        #pragma unroll
        for (int it = 0; it < 2; it++)
            bR[it] = *(const uint4*)&Bb[(long)(n0 + mb + it * 64) * K + k0 + w4 * 2];
    };
    auto sts = [&](int p) {
        uint32_t* Ad = As32 + p * 2560;
        uint32_t* Bd = Bs32 + p * 2560;
        #pragma unroll
        for (int it = 0; it < 2; it++)
            *(uint4*)&Ad[(mb + it * 64) * 20 + w4] = aR[it];
        #pragma unroll
        for (int it = 0; it < 2; it++)
            *(uint4*)&Bd[(mb + it * 64) * 20 + w4] = bR[it];
    };

    ldg(0); sts(0);
    __syncthreads();
    for (int k0 = 0; k0 < K; k0 += 32) {
        int p = (k0 >> 5) & 1;
        bool more = (k0 + 32 < K);
        if (more) ldg(k0 + 32);

        uint32_t Ap = As_b + (uint32_t)p * 2560 * 4;
        uint32_t Bp = Bs_b + (uint32_t)p * 2560 * 4;
        #pragma unroll
        for (int ks = 0; ks < 2; ks++) {
            int kw = ks * 8;
            uint32_t af[4][4], bf[4][2];
            #pragma unroll
            for (int mt = 0; mt < 4; mt++) {
                int r0 = rbase + mt * 16;
                ldsm_x4(af[mt][0], af[mt][1], af[mt][2], af[mt][3],
                        Ap + (uint32_t)(((r0 + fr_row) * 20) + kw + fr_col) * 4);
            }
            ldsm_x4(bf[0][0], bf[1][0], bf[2][0], bf[3][0],
                    Bp + (uint32_t)(((cbase + lmat * 8 + lrow) * 20) + kw) * 4);
            ldsm_x4(bf[0][1], bf[1][1], bf[2][1], bf[3][1],
                    Bp + (uint32_t)(((cbase + lmat * 8 + lrow) * 20) + kw + 4) * 4);
            #pragma unroll
            for (int mt = 0; mt < 4; mt++)
                #pragma unroll
                for (int nt = 0; nt < 4; nt++)
                    MMA16(acc[mt][nt], af[mt][0], af[mt][1], af[mt][2], af[mt][3],
                          bf[nt][0], bf[nt][1]);
        }
        if (more) sts(p ^ 1);
        __syncthreads();
    }

    #pragma unroll
    for (int mt = 0; mt < 4; mt++)
        #pragma unroll
        for (int nt = 0; nt < 4; nt++) {
            int r = m0 + rbase + mt * 16 + g;
            int cN = n0 + cbase + nt * 8 + 2 * tig;
            float b0 = bias ? bias[cN] : 0.f;
            float b1 = bias ? bias[cN + 1] : 0.f;
            float v0 = acc[mt][nt][0] * scl + b0;
            float v1 = acc[mt][nt][1] * scl + b1;
            float v2 = acc[mt][nt][2] * scl + b0;
            float v3 = acc[mt][nt][3] * scl + b1;
            if (act == 1) { v0 = silu_f(v0); v1 = silu_f(v1); v2 = silu_f(v2); v3 = silu_f(v3); }
            store2(&Yb[(long)r * ldy + cN],       v0, v1);
            store2(&Yb[(long)(r + 8) * ldy + cN], v2, v3);
        }
}

// =====================================================================
// conv1 as GEMM: a1t = silu(hst . w1 + b), half token-major out.
// =====================================================================
__global__ __launch_bounds__(256) void conv1_gemm(
        const __half* __restrict__ A, const __half* __restrict__ Bm,
        const float* __restrict__ bias, __half* __restrict__ Y) {
    __shared__ __align__(16) uint32_t As32[2 * 128 * 20];
    __shared__ __align__(16) uint32_t Bs32[2 * 64 * 20];

    int b = blockIdx.z;
    const __half* Ab = A + (long)b * SS * CCH;
    __half* Yb = Y + (long)b * SS * C8;
    int m0 = blockIdx.x * 128;

    int tid = threadIdx.x;
    int w = tid >> 5, lane = tid & 31;
    int wm = w & 3, wn = w >> 2;
    int g = lane >> 2, tig = lane & 3;
    int rbase = wm * 32, cbase = wn * 32;
    int lrow = lane & 7, lmat = lane >> 3;
    int fr_row = (lmat & 1) * 8 + lrow;
    int fr_col = (lmat >> 1) * 4;
    uint32_t As_b = cvsm(As32), Bs_b = cvsm(Bs32);

    float acc[2][4][4];
    #pragma unroll
    for (int i = 0; i < 2; i++)
        #pragma unroll
        for (int j = 0; j < 4; j++)
            #pragma unroll
            for (int l = 0; l < 4; l++) acc[i][j][l] = 0.f;

    uint4 aR[2], bR;
    int w4 = (tid & 3) * 4, mb = tid >> 2;

    auto ldg = [&](int k0) {
        #pragma unroll
        for (int it = 0; it < 2; it++)
            aR[it] = *(const uint4*)&Ab[(long)(m0 + mb + it * 64) * CCH + k0 + w4 * 2];
        bR = *(const uint4*)&Bm[(long)mb * 512 + k0 + w4 * 2];
    };
    auto sts = [&](int p) {
        uint32_t* Ad = As32 + p * 2560;
        uint32_t* Bd = Bs32 + p * 1280;
        #pragma unroll
        for (int it = 0; it < 2; it++)
            *(uint4*)&Ad[(mb + it * 64) * 20 + w4] = aR[it];
        *(uint4*)&Bd[mb * 20 + w4] = bR;
    };

    ldg(0); sts(0);
    __syncthreads();
    for (int k0 = 0; k0 < 512; k0 += 32) {
        int p = (k0 >> 5) & 1;
        bool more = (k0 + 32 < 512);
        if (more) ldg(k0 + 32);

        uint32_t Ap = As_b + (uint32_t)p * 2560 * 4;
        uint32_t Bp = Bs_b + (uint32_t)p * 1280 * 4;
        #pragma unroll
        for (int ks = 0; ks < 2; ks++) {
            int kw = ks * 8;
            uint32_t af[2][4], bf[4][2];
            #pragma unroll
            for (int mt = 0; mt < 2; mt++) {
                int r0 = rbase + mt * 16;
                ldsm_x4(af[mt][0], af[mt][1], af[mt][2], af[mt][3],
                        Ap + (uint32_t)(((r0 + fr_row) * 20) + kw + fr_col) * 4);
            }
            ldsm_x4(bf[0][0], bf[1][0], bf[2][0], bf[3][0],
                    Bp + (uint32_t)(((cbase + lmat * 8 + lrow) * 20) + kw) * 4);
            ldsm_x4(bf[0][1], bf[1][1], bf[2][1], bf[3][1],
                    Bp + (uint32_t)(((cbase + lmat * 8 + lrow) * 20) + kw + 4) * 4);
            #pragma unroll
            for (int mt = 0; mt < 2; mt++)
                #pragma unroll
                for (int nt = 0; nt < 4; nt++)
                    MMA16(acc[mt][nt], af[mt][0], af[mt][1], af[mt][2], af[mt][3],
                          bf[nt][0], bf[nt][1]);
        }
        if (more) sts(p ^ 1);
        __syncthreads();
    }

    #pragma unroll
    for (int mt = 0; mt < 2; mt++)
        #pragma unroll
        for (int nt = 0; nt < 4; nt++) {
            int r = m0 + rbase + mt * 16 + g;
            int cN = cbase + nt * 8 + 2 * tig;
            float b0 = bias[cN], b1 = bias[cN + 1];
            store2(&Yb[(long)r * C8 + cN],       silu_f(acc[mt][nt][0] + b0), silu_f(acc[mt][nt][1] + b1));
            store2(&Yb[(long)(r + 8) * C8 + cN], silu_f(acc[mt][nt][2] + b0), silu_f(acc[mt][nt][3] + b1));
        }
}

// =====================================================================
// conv2 as IMPLICIT GEMM (9 taps x 64 ci), zero-padded shifts.
// =====================================================================
__global__ __launch_bounds__(256) void conv2_gemm(
        const __half* __restrict__ A, const __half* __restrict__ Bm,
        const float* __restrict__ bias, __half* __restrict__ Y) {
    __shared__ __align__(16) uint32_t As32[128 * 36];
    __shared__ __align__(16) uint32_t Bs32[64 * 36];

    int b = blockIdx.z;
    const __half* Ab = A + (long)b * SS * C8;
    __half* Yb = Y + (long)b * SS * C8;
    int m0 = blockIdx.x * 128;

    int tid = threadIdx.x;
    int w = tid >> 5, lane = tid & 31;
    int wm = w & 3, wn = w >> 2;
    int g = lane >> 2, tig = lane & 3;
    int rbase = wm * 32, cbase = wn * 32;
    int lrow = lane & 7, lmat = lane >> 3;
    int fr_row = (lmat & 1) * 8 + lrow;
    int fr_col = (lmat >> 1) * 4;
    uint32_t As_b = cvsm(As32), Bs_b = cvsm(Bs32);

    float acc[2][4][4];
    #pragma unroll
    for (int i = 0; i < 2; i++)
        #pragma unroll
        for (int j = 0; j < 4; j++)
            #pragma unroll
            for (int l = 0; l < 4; l++) acc[i][j][l] = 0.f;

    uint4 aR[4], bR[2];

    auto ldg_tap = [&](int tap) {
        int dy = tap / 3 - 1, dx = tap % 3 - 1;
        #pragma unroll
        for (int f = 0; f < 4; f++) {
            int idx = tid + f * 256;
            int r = idx >> 3, c8 = idx & 7;
            int s = m0 + r;
            int sy = (s >> 5) + dy, sx = (s & 31) + dx;
            bool valid = ((unsigned)sy < 32u) && ((unsigned)sx < 32u);
            aR[f] = valid ? *(const uint4*)&Ab[(long)((sy << 5) + sx) * C8 + c8 * 8]
                          : make_uint4(0u, 0u, 0u, 0u);
        }
        #pragma unroll
        for (int f = 0; f < 2; f++) {
            int idx = tid + f * 256;
            int r = idx >> 3, c8 = idx & 7;
            bR[f] = *(const uint4*)&Bm[(long)r * 576 + tap * 64 + c8 * 8];
        }
    };
    auto sts_tap = [&]() {
        #pragma unroll
        for (int f = 0; f < 4; f++) {
            int idx = tid + f * 256;
            int r = idx >> 3, c8 = idx & 7;
            *(uint4*)&As32[r * 36 + c8 * 4] = aR[f];
        }
        #pragma unroll
        for (int f = 0; f < 2; f++) {
            int idx = tid + f * 256;
            int r = idx >> 3, c8 = idx & 7;
            *(uint4*)&Bs32[r * 36 + c8 * 4] = bR[f];
        }
    };

    ldg_tap(0);
    for (int tap = 0; tap < 9; tap++) {
        sts_tap();
        __syncthreads();
        if (tap < 8) ldg_tap(tap + 1);

        #pragma unroll
        for (int ks = 0; ks < 4; ks++) {
            int kw = ks * 8;
            uint32_t af[2][4], bf[4][2];
            #pragma unroll
            for (int mt = 0; mt < 2; mt++) {
                int r0 = rbase + mt * 16;
                ldsm_x4(af[mt][0], af[mt][1], af[mt][2], af[mt][3],
                        As_b + (uint32_t)(((r0 + fr_row) * 36) + kw + fr_col) * 4);
            }
            ldsm_x4(bf[0][0], bf[1][0], bf[2][0], bf[3][0],
                    Bs_b + (uint32_t)(((cbase + lmat * 8 + lrow) * 36) + kw) * 4);
            ldsm_x4(bf[0][1], bf[1][1], bf[2][1], bf[3][1],
                    Bs_b + (uint32_t)(((cbase + lmat * 8 + lrow) * 36) + kw + 4) * 4);
            #pragma unroll
            for (int mt = 0; mt < 2; mt++)
                #pragma unroll
                for (int nt = 0; nt < 4; nt++)
                    MMA16(acc[mt][nt], af[mt][0], af[mt][1], af[mt][2], af[mt][3],
                          bf[nt][0], bf[nt][1]);
        }
        __syncthreads();
    }

    #pragma unroll
    for (int mt = 0; mt < 2; mt++)
        #pragma unroll
        for (int nt = 0; nt < 4; nt++) {
            int r = m0 + rbase + mt * 16 + g;
            int cN = cbase + nt * 8 + 2 * tig;
            float b0 = bias[cN], b1 = bias[cN + 1];
            store2(&Yb[(long)r * C8 + cN],       silu_f(acc[mt][nt][0] + b0), silu_f(acc[mt][nt][1] + b1));
            store2(&Yb[(long)(r + 8) * C8 + cN], silu_f(acc[mt][nt][2] + b0), silu_f(acc[mt][nt][3] + b1));
        }
}

// ---------------- conv3 (64->1) + sigmoid ----------------
__global__ void conv3_sig_t(const __half* __restrict__ a2t, const float* __restrict__ w,
                            const float* __restrict__ bias, float* __restrict__ y) {
    __shared__ float ws[64];
    int tid = threadIdx.x;
    if (tid < 64) ws[tid] = w[tid];
    __syncthreads();
    int idx = blockIdx.x * 256 + tid;
    const __half* p = a2t + (long)idx * C8;
    float acc = bias[0];
    #pragma unroll
    for (int f = 0; f < 8; f++) {
        uint4 v = *(const uint4*)&p[f * 8];
        const __half2* h2 = (const __half2*)&v;
        #pragma unroll
        for (int u = 0; u < 4; u++) {
            float2 fv = __half22float2(h2[u]);
            acc += fv.x * ws[f * 8 + u * 2] + fv.y * ws[f * 8 + u * 2 + 1];
        }
    }
    y[idx] = 1.0f / (1.0f + expf(-acc));
}

// ---------------- senh_t = hs_t * sw ----------------
__global__ void senh_t_mul(const __half* __restrict__ hs_t, const float* __restrict__ sw,
                           __half* __restrict__ senh_t) {
    int idx = blockIdx.x * 256 + threadIdx.x;
    int token = idx >> 6, c8 = idx & 63;
    __half2 m = __float2half2_rn(sw[token]);
    uint4 v = *(const uint4*)&hs_t[(long)token * CCH + c8 * 8];
    __half2* h = (__half2*)&v;
    h[0] = __hmul2(h[0], m); h[1] = __hmul2(h[1], m);
    h[2] = __hmul2(h[2], m); h[3] = __hmul2(h[3], m);
    *(uint4*)&senh_t[(long)token * CCH + c8 * 8] = v;
}

// =====================================================================
// Merged flash attention, exp via ex2.approx.f16x2.
// =====================================================================
#define FL_WORDS 15872

__device__ __forceinline__ void flash_std_body(
        const __half* __restrict__ Q, const __half* __restrict__ K,
        const __half* __restrict__ V, __half* __restrict__ O,
        int bh, int xq, uint32_t* smw) {
    uint32_t* Qs = smw;
    uint32_t* KP = smw + 128 * 36;
    uint32_t* Vs = smw + 2 * 128 * 36;
    float* redm = (float*)(smw + 2 * 128 * 36 + 64 * 36);
    float* redl = redm + 256;

    int b = bh >> 3, h = bh & 7;
    const __half* Qb = Q + (long)b * SS * CCH + h * 64;
    const __half* Kb = K + (long)b * SS * CCH + h * 64;
    const __half* Vb = V + (long)b * SS * CCH + h * 64;
    __half* Ob = O + (long)b * SS * (2 * CCH) + h * 64;
    int q0 = xq * 128;

    int tid = threadIdx.x;
    int w = tid >> 5, lane = tid & 31;
    int wm = w & 3, wn = w >> 2;
    int g = lane >> 2, tig = lane & 3;
    int rbase = wm * 32, cbase = wn * 32;
    int lrow = lane & 7, lmat = lane >> 3;
    int fr_row = (lmat & 1) * 8 + lrow;
    int fr_col = (lmat >> 1) * 4;
    int t_kb = lmat >> 1, t_hb = lmat & 1;
    uint32_t Qs_b = cvsm(Qs), KP_b = cvsm(KP), Vs_b = cvsm(Vs);

    #pragma unroll
    for (int f = 0; f < 4; f++) {
        int idx = tid + f * 256;
        int r = idx >> 3, w4 = (idx & 7) * 4;
        uint4 v4 = *(const uint4*)&Qb[(long)(q0 + r) * CCH + (idx & 7) * 8];
        *(uint4*)&Qs[r * 36 + w4] = v4;
    }

    uint4 kR[2], vR[2];
    int st_r = tid >> 3, st_w4 = (tid & 7) * 4, st_c = (tid & 7) * 8;
    auto ldg_kv = [&](int j) {
        #pragma unroll
        for (int f = 0; f < 2; f++) {
            long goff = (long)(j * 64 + st_r + f * 32) * CCH + st_c;
            kR[f] = *(const uint4*)&Kb[goff];
            vR[f] = *(const uint4*)&Vb[goff];
        }
    };
    auto sts_kv = [&]() {
        #pragma unroll
        for (int f = 0; f < 2; f++) {
            *(uint4*)&KP[(st_r + f * 32) * 36 + st_w4] = kR[f];
            *(uint4*)&Vs[(st_r + f * 32) * 36 + st_w4] = vR[f];
        }
    };

    float accO[2][4][4];
    #pragma unroll
    for (int i = 0; i < 2; i++)
        #pragma unroll
        for (int j = 0; j < 4; j++)
            #pragma unroll
            for (int l = 0; l < 4; l++) accO[i][j][l] = 0.f;
    float mst[4] = { -1e30f, -1e30f, -1e30f, -1e30f };
    float lst[4] = { 0.f, 0.f, 0.f, 0.f };

    ldg_kv(0);
    for (int j = 0; j < 16; j++) {
        sts_kv();
        __syncthreads();
        if (j + 1 < 16) ldg_kv(j + 1);

        float acc[2][4][4];
        #pragma unroll
        for (int i = 0; i < 2; i++)
            #pragma unroll
            for (int jj = 0; jj < 4; jj++)
                #pragma unroll
                for (int l = 0; l < 4; l++) acc[i][jj][l] = 0.f;
        #pragma unroll
        for (int ks = 0; ks < 4; ks++) {
            int kw = ks * 8;
            uint32_t af[2][4], bf[4][2];
            #pragma unroll
            for (int mt = 0; mt < 2; mt++) {
                int r0 = rbase + mt * 16;
                ldsm_x4(af[mt][0], af[mt][1], af[mt][2], af[mt][3],
                        Qs_b + (uint32_t)(((r0 + fr_row) * 36) + kw + fr_col) * 4);
            }
            ldsm_x4(bf[0][0], bf[1][0], bf[2][0], bf[3][0],
                    KP_b + (uint32_t)(((cbase + lmat * 8 + lrow) * 36) + kw) * 4);
            ldsm_x4(bf[0][1], bf[1][1], bf[2][1], bf[3][1],
                    KP_b + (uint32_t)(((cbase + lmat * 8 + lrow) * 36) + kw + 4) * 4);
            #pragma unroll
            for (int mt = 0; mt < 2; mt++)
                #pragma unroll
                for (int nt = 0; nt < 4; nt++)
                    MMA16(acc[mt][nt], af[mt][0], af[mt][1], af[mt][2], af[mt][3],
                          bf[nt][0], bf[nt][1]);
        }

        #pragma unroll
        for (int mt = 0; mt < 2; mt++)
            #pragma unroll
            for (int hh = 0; hh < 2; hh++) {
                float mx = -1e30f;
                #pragma unroll
                for (int nt = 0; nt < 4; nt++) {
                    mx = fmaxf(mx, acc[mt][nt][hh * 2]);
                    mx = fmaxf(mx, acc[mt][nt][hh * 2 + 1]);
                }
                mx = fmaxf(mx, __shfl_xor_sync(0xffffffffu, mx, 1));
                mx = fmaxf(mx, __shfl_xor_sync(0xffffffffu, mx, 2));
                if (tig == 0) redm[wn * 128 + rbase + mt * 16 + hh * 8 + g] = mx;
            }
        __syncthreads();

        #pragma unroll
        for (int mt = 0; mt < 2; mt++)
            #pragma unroll
            for (int hh = 0; hh < 2; hh++) {
                int i = mt * 2 + hh;
                int rloc = rbase + mt * 16 + hh * 8 + g;
                float mch = fmaxf(redm[rloc], redm[128 + rloc]);
                float mnew = fmaxf(mst[i], mch);
                float corr = __expf(mst[i] - mnew);
                mst[i] = mnew;
                float s = 0.f;
                #pragma unroll
                for (int nt = 0; nt < 4; nt++) {
                    uint32_t ph = exp2_h2((acc[mt][nt][hh * 2]     - mnew) * L2E,
                                          (acc[mt][nt][hh * 2 + 1] - mnew) * L2E);
                    KP[rloc * 36 + wn * 16 + nt * 4 + tig] = ph;
                    float2 pf = __half22float2(*(__half2*)&ph);
                    s += pf.x + pf.y;
                    accO[mt][nt][hh * 2]     *= corr;
                    accO[mt][nt][hh * 2 + 1] *= corr;
                }
                s += __shfl_xor_sync(0xffffffffu, s, 1);
                s += __shfl_xor_sync(0xffffffffu, s, 2);
                if (tig == 0) redl[wn * 128 + rloc] = s;
                lst[i] *= corr;
            }
        __syncthreads();
        #pragma unroll
        for (int mt = 0; mt < 2; mt++)
            #pragma unroll
            for (int hh = 0; hh < 2; hh++) {
                int rloc = rbase + mt * 16 + hh * 8 + g;
                lst[mt * 2 + hh] += redl[rloc] + redl[128 + rloc];
            }

        #pragma unroll
        for (int ks = 0; ks < 4; ks++) {
            int kw = ks * 8;
            uint32_t af[2][4], bf[4][2];
            #pragma unroll
            for (int mt = 0; mt < 2; mt++) {
                int r0 = rbase + mt * 16;
                ldsm_x4(af[mt][0], af[mt][1], af[mt][2], af[mt][3],
                        KP_b + (uint32_t)(((r0 + fr_row) * 36) + kw + fr_col) * 4);
            }
            uint32_t vaddr = Vs_b + (uint32_t)((ks * 16 + t_kb * 8 + lrow) * 144
                                               + (cbase + t_hb * 8) * 2);
            ldsm_x4_t(bf[0][0], bf[1][0], bf[0][1], bf[1][1], vaddr);
            ldsm_x4_t(bf[2][0], bf[3][0], bf[2][1], bf[3][1], vaddr + 32);
            #pragma unroll
            for (int mt = 0; mt < 2; mt++)
                #pragma unroll
                for (int nt = 0; nt < 4; nt++)
                    MMA16(accO[mt][nt], af[mt][0], af[mt][1], af[mt][2], af[mt][3],
                          bf[nt][0], bf[nt][1]);
        }
        __syncthreads();
    }

    #pragma unroll
    for (int mt = 0; mt < 2; mt++) {
        float inv0 = 1.0f / lst[mt * 2];
        float inv1 = 1.0f / lst[mt * 2 + 1];
        #pragma unroll
        for (int nt = 0; nt < 4; nt++) {
            int r = q0 + rbase + mt * 16 + g;
            int c = cbase + nt * 8 + 2 * tig;
            store2(&Ob[(long)r * 1024 + c],       accO[mt][nt][0] * inv0, accO[mt][nt][1] * inv0);
            store2(&Ob[(long)(r + 8) * 1024 + c], accO[mt][nt][2] * inv1, accO[mt][nt][3] * inv1);
        }
    }
}

__device__ __forceinline__ void flash_multi_body(
        const __half* __restrict__ Q, const __half* __restrict__ K,
        const __half* __restrict__ V, __half* __restrict__ O,
        int z, int xq, uint32_t* smw) {
    uint32_t* Qs = smw;
    uint32_t* Ks = smw + 8448;
    uint32_t* Ps = smw + 8448 + 2304;
    uint32_t* Vs = smw + 8448 + 2 * 2304;
    float* redm = (float*)(smw + 8448 + 3 * 2304);
    float* redl = redm + 256;

    const __half* Qb = Q + (long)z * SS * C2;
    const __half* Kb = K + (long)z * SS * C2;
    const __half* Vb = V + (long)z * SS * C2;
    int br = z >> 3, b = z & 7;
    __half* Ob = O + (long)b * SS * 1024 + 512 + br * 256;
    int q0 = xq * 64;

    int tid = threadIdx.x;
    int w = tid >> 5, lane = tid & 31;
    int wm = w & 1, wn = w >> 1;
    int g = lane >> 2, tig = lane & 3;
    int rbase = wm * 32;
    int lrow = lane & 7, lmat = lane >> 3;
    int fr_row = (lmat & 1) * 8 + lrow;
    int fr_col = (lmat >> 1) * 4;
    int t_kb = lmat >> 1, t_hb = lmat & 1;
    uint32_t Qs_b = cvsm(Qs), Ks_b = cvsm(Ks), Ps_b = cvsm(Ps), Vs_b = cvsm(Vs);

    #pragma unroll
    for (int f = 0; f < 8; f++) {
        int idx = tid + f * 256;
        int r = idx >> 5, c8 = idx & 31;
        uint4 qv = *(const uint4*)&Qb[(long)(q0 + r) * C2 + c8 * 8];
        *(uint4*)&Qs[r * 132 + c8 * 4] = qv;
    }

    int st_r = tid >> 3, st_w4 = (tid & 7) * 4, st_c = (tid & 7) * 8;
    uint4 sR[2];
    auto ldg_s = [&](const __half* P, int j, int dc) {
        #pragma unroll
        for (int f = 0; f < 2; f++)
            sR[f] = *(const uint4*)&P[(long)(j * 64 + st_r + f * 32) * C2 + dc * 64 + st_c];
    };
    auto sts_s = [&](uint32_t* D) {
        #pragma unroll
        for (int f = 0; f < 2; f++)
            *(uint4*)&D[(st_r + f * 32) * 36 + st_w4] = sR[f];
    };

    float accO[2][8][4];
    #pragma unroll
    for (int i = 0; i < 2; i++)
        #pragma unroll
        for (int j = 0; j < 8; j++)
            #pragma unroll
            for (int l = 0; l < 4; l++) accO[i][j][l] = 0.f;
    float mst[4] = { -1e30f, -1e30f, -1e30f, -1e30f };
    float lst[4] = { 0.f, 0.f, 0.f, 0.f };

    for (int j = 0; j < 16; j++) {
        float acc[2][2][4];
        #pragma unroll
        for (int i = 0; i < 2; i++)
            #pragma unroll
            for (int jj = 0; jj < 2; jj++)
                #pragma unroll
                for (int l = 0; l < 4; l++) acc[i][jj][l] = 0.f;

        ldg_s(Kb, j, 0);
        for (int dc = 0; dc < 4; dc++) {
            sts_s(Ks);
            __syncthreads();
            if (dc < 3) ldg_s(Kb, j, dc + 1);
            #pragma unroll
            for (int ks = 0; ks < 4; ks++) {
                int kw = ks * 8;
                uint32_t af[2][4], bf[2][2];
                #pragma unroll
                for (int mt = 0; mt < 2; mt++) {
                    int r0 = rbase + mt * 16;
                    ldsm_x4(af[mt][0], af[mt][1], af[mt][2], af[mt][3],
                            Qs_b + (uint32_t)(((r0 + fr_row) * 132) + dc * 32 + kw + fr_col) * 4);
                }
                ldsm_x4(bf[0][0], bf[1][0], bf[0][1], bf[1][1],
                        Ks_b + (uint32_t)(((wn * 16 + fr_row) * 36) + kw + fr_col) * 4);
                #pragma unroll
                for (int mt = 0; mt < 2; mt++)
                    #pragma unroll
                    for (int nt = 0; nt < 2; nt++)
                        MMA16(acc[mt][nt], af[mt][0], af[mt][1], af[mt][2], af[mt][3],
                              bf[nt][0], bf[nt][1]);
            }
            __syncthreads();
        }

        #pragma unroll
        for (int mt = 0; mt < 2; mt++)
            #pragma unroll
            for (int hh = 0; hh < 2; hh++) {
                float mx = -1e30f;
                #pragma unroll
                for (int nt = 0; nt < 2; nt++) {
                    mx = fmaxf(mx, acc[mt][nt][hh * 2]);
                    mx = fmaxf(mx, acc[mt][nt][hh * 2 + 1]);
                }
                mx = fmaxf(mx, __shfl_xor_sync(0xffffffffu, mx, 1));
                mx = fmaxf(mx, __shfl_xor_sync(0xffffffffu, mx, 2));
                if (tig == 0) redm[wn * 64 + rbase + mt * 16 + hh * 8 + g] = mx;
            }
        __syncthreads();

        #pragma unroll
        for (int mt = 0; mt < 2; mt++)
            #pragma unroll
            for (int hh = 0; hh < 2; hh++) {
                int i = mt * 2 + hh;
                int rloc = rbase + mt * 16 + hh * 8 + g;
                float mch = fmaxf(fmaxf(redm[rloc], redm[64 + rloc]),
                                  fmaxf(redm[128 + rloc], redm[192 + rloc]));
                float mnew = fmaxf(mst[i], mch);
                float corr = __expf(mst[i] - mnew);
                mst[i] = mnew;
                float s = 0.f;
                #pragma unroll
                for (int nt = 0; nt < 2; nt++) {
                    uint32_t ph = exp2_h2((acc[mt][nt][hh * 2]     - mnew) * L2E,
                                          (acc[mt][nt][hh * 2 + 1] - mnew) * L2E);
                    Ps[rloc * 36 + wn * 8 + nt * 4 + tig] = ph;
                    float2 pf = __half22float2(*(__half2*)&ph);
                    s += pf.x + pf.y;
                }
                s += __shfl_xor_sync(0xffffffffu, s, 1);
                s += __shfl_xor_sync(0xffffffffu, s, 2);
                if (tig == 0) redl[wn * 64 + rloc] = s;
                lst[i] *= corr;
                #pragma unroll
                for (int nt = 0; nt < 8; nt++) {
                    accO[mt][nt][hh * 2]     *= corr;
                    accO[mt][nt][hh * 2 + 1] *= corr;
                }
            }
        __syncthreads();
        #pragma unroll
        for (int mt = 0; mt < 2; mt++)
            #pragma unroll
            for (int hh = 0; hh < 2; hh++) {
                int rloc = rbase + mt * 16 + hh * 8 + g;
                lst[mt * 2 + hh] += redl[rloc] + redl[64 + rloc]
                                  + redl[128 + rloc] + redl[192 + rloc];
            }

        ldg_s(Vb, j, 0);
        for (int dc = 0; dc < 4; dc++) {
            sts_s(Vs);
            __syncthreads();
            if (dc < 3) ldg_s(Vb, j, dc + 1);
            #pragma unroll
            for (int ks = 0; ks < 4; ks++) {
                int kw = ks * 8;
                uint32_t af[2][4], bf[2][2];
                #pragma unroll
                for (int mt = 0; mt < 2; mt++) {
                    int r0 = rbase + mt * 16;
                    ldsm_x4(af[mt][0], af[mt][1], af[mt][2], af[mt][3],
                            Ps_b + (uint32_t)(((r0 + fr_row) * 36) + kw + fr_col) * 4);
                }
                uint32_t vaddr = Vs_b + (uint32_t)((ks * 16 + t_kb * 8 + lrow) * 144
                                                   + (wn * 16 + t_hb * 8) * 2);
                ldsm_x4_t(bf[0][0], bf[1][0], bf[0][1], bf[1][1], vaddr);
                #pragma unroll
                for (int mt = 0; mt < 2; mt++)
                    #pragma unroll
                    for (int nt = 0; nt < 2; nt++)
                        MMA16(accO[mt][dc * 2 + nt], af[mt][0], af[mt][1], af[mt][2], af[mt][3],
                              bf[nt][0], bf[nt][1]);
            }
            __syncthreads();
        }
    }

    #pragma unroll
    for (int mt = 0; mt < 2; mt++) {
        float inv0 = 1.0f / lst[mt * 2];
        float inv1 = 1.0f / lst[mt * 2 + 1];
        #pragma unroll
        for (int u = 0; u < 8; u++) {
            int dc = u >> 1, nt = u & 1;
            int r = q0 + rbase + mt * 16 + g;
            int c = dc * 64 + wn * 16 + nt * 8 + 2 * tig;
            store2(&Ob[(long)r * 1024 + c],       accO[mt][u][0] * inv0, accO[mt][u][1] * inv0);
            store2(&Ob[(long)(r + 8) * 1024 + c], accO[mt][u][2] * inv1, accO[mt][u][3] * inv1);
        }
    }
}

__global__ __launch_bounds__(256, 2) void flash_all(
        const __half* __restrict__ q, const __half* __restrict__ k,
        const __half* __restrict__ v,
        const __half* __restrict__ qm, const __half* __restrict__ km,
        const __half* __restrict__ vm, __half* __restrict__ comb) {
    extern __shared__ uint32_t smw[];
    int bx = blockIdx.x;
    if (bx < 512) flash_std_body(q, k, v, comb, bx >> 3, bx & 7, smw);
    else { int i = bx - 512; flash_multi_body(qm, km, vm, comb, i >> 4, i & 15, smw); }
}

// ---------------- launch ----------------
static void* symv(const void* s) { void* p = nullptr; cudaGetSymbolAddress(&p, s); return p; }

extern "C" void kernel_launch(void* const* d_in, const int* in_sizes, int n_in,
                              void* d_out, int out_size) {
    (void)in_sizes; (void)n_in; (void)out_size;
    const float* x      = (const float*)d_in[0];
    const float* pre_g  = (const float*)d_in[1];
    const float* pre_b  = (const float*)d_in[2];
    const float* norm_g = (const float*)d_in[3];
    const float* norm_b = (const float*)d_in[4];
    const float* post_g = (const float*)d_in[5];
    const float* post_b = (const float*)d_in[6];
    const float* pos    = (const float*)d_in[7];
    const float* sa_w1  = (const float*)d_in[8];
    const float* sa_b1  = (const float*)d_in[9];
    const float* sa_w2  = (const float*)d_in[10];
    const float* sa_b2  = (const float*)d_in[11];
    const float* sa_w3  = (const float*)d_in[12];
    const float* sa_b3  = (const float*)d_in[13];
    const float* wq     = (const float*)d_in[14];
    const float* wk     = (const float*)d_in[15];
    const float* wv     = (const float*)d_in[16];
    const float* wq0    = (const float*)d_in[17];
    const float* wk0    = (const float*)d_in[18];
    const float* wv0    = (const float*)d_in[19];
    const float* wq1    = (const float*)d_in[20];
    const float* wk1    = (const float*)d_in[21];
    const float* wv1    = (const float*)d_in[22];
    const float* ff_w1  = (const float*)d_in[23];
    const float* ff_b1  = (const float*)d_in[24];
    const float* ff_w2  = (const float*)d_in[25];
    const float* ff_b2  = (const float*)d_in[26];
    const float* out_w  = (const float*)d_in[27];
    const float* out_b  = (const float*)d_in[28];
    float* out = (float*)d_out;

    __half *hst = (__half*)symv(d_hst), *shnt = (__half*)symv(d_shnt), *senht = (__half*)symv(d_senht);
    __half *a1t = (__half*)symv(d_a1t), *a2t = (__half*)symv(d_a2t);
    float  *sw = (float*)symv(d_swt);
    __half *q = (__half*)symv(d_q), *k = (__half*)symv(d_k), *v = (__half*)symv(d_v);
    __half *qm = (__half*)symv(d_qm), *km = (__half*)symv(d_km), *vm = (__half*)symv(d_vm);
    __half *comb = (__half*)symv(d_comb), *f1 = (__half*)symv(d_f1), *fus = (__half*)symv(d_fus);
    float  *fin = (float*)symv(d_fin);
    __half *wb = (__half*)symv(d_w);
    __half *w2h = (__half*)symv(d_w2);

    // secondary stream + events (created once; capture-safe fork/join pattern)
    static cudaStream_t s1 = nullptr;
    static cudaEvent_t evFork = nullptr, evW = nullptr, evGN = nullptr, evConv = nullptr;
    if (!s1) {
        cudaStreamCreateWithFlags(&s1, cudaStreamNonBlocking);
        cudaEventCreateWithFlags(&evFork, cudaEventDisableTiming);
        cudaEventCreateWithFlags(&evW, cudaEventDisableTiming);
        cudaEventCreateWithFlags(&evGN, cudaEventDisableTiming);
        cudaEventCreateWithFlags(&evConv, cudaEventDisableTiming);
    }

    const int flSmem = FL_WORDS * 4;
    cudaFuncSetAttribute(flash_all, cudaFuncAttributeMaxDynamicSharedMemorySize, flSmem);
    const int gnSmem = 16 * 1024 * 4;
    cudaFuncSetAttribute(gn_fused, cudaFuncAttributeMaxDynamicSharedMemorySize, gnSmem);

    const float* wsrc[13] = { wq, wk, wv, wq0, wk0, wv0, wq1, wk1, wv1,
                              ff_w1, ff_w2, out_w, sa_w1 };
    const int wcnt[13] = { 262144, 262144, 262144, 131072, 131072, 131072,
                           131072, 131072, 131072, 524288, 262144, 262144, 32768 };
    WC wc; int off = 0;
    __half* hw[13];
    for (int i = 0; i < 13; i++) {
        wc.src[i] = wsrc[i]; wc.cnt4[i] = wcnt[i] / 4; wc.off[i] = off;
        hw[i] = wb + off;
        off += wcnt[i];
    }

    // fork: s1 runs weight conversion concurrently with gn_fused on stream 0
    cudaEventRecord(evFork, 0);
    cudaStreamWaitEvent(s1, evFork, 0);
    wcvt<<<dim3(512, 13), 256, 0, s1>>>(wc, wb);
    w2cvt<<<144, 256, 0, s1>>>(sa_w2, w2h);
    cudaEventRecord(evW, s1);

    gn_fused<<<BATCH * NGR, 256, gnSmem>>>(x, pre_g, pre_b, pos, norm_g, norm_b,
                                           hst, shnt);
    cudaEventRecord(evGN, 0);

    // s1: conv gate chain (needs hst + weights), overlapped with pq on stream 0
    cudaStreamWaitEvent(s1, evGN, 0);
    conv1_gemm<<<dim3(8, 1, BATCH), 256, 0, s1>>>(hst, hw[12], sa_b1, a1t);
    conv2_gemm<<<dim3(8, 1, BATCH), 256, 0, s1>>>(a1t, w2h, sa_b2, a2t);
    conv3_sig_t<<<BATCH * SS / 256, 256, 0, s1>>>(a2t, sa_w3, sa_b3, sw);
    senh_t_mul<<<BATCH * SS * CCH / 8 / 256, 256, 0, s1>>>(hst, sw, senht);
    cudaEventRecord(evConv, s1);

    // stream 0: QKV projections (needs shnt + weights)
    cudaStreamWaitEvent(0, evW, 0);
    GArg pq = {};
    pq.A[0] = shnt; pq.A[1] = shnt; pq.A[2] = shnt;
    pq.W[0] = hw[0]; pq.W[1] = hw[1]; pq.W[2] = hw[2];
    pq.Y[0] = q;    pq.Y[1] = k;    pq.Y[2] = v;
    pq.bias[0] = pq.bias[1] = pq.bias[2] = nullptr;
    pq.sc[0] = 0.125f; pq.sc[1] = 1.f; pq.sc[2] = 1.f;
    pq.aOuter = (long)SS * CCH; pq.yOuter = (long)SS * 512;
    pq.K = 512; pq.lda = 512; pq.N = 512; pq.ldy = 512; pq.act = 0;
    gemm128<__half><<<dim3(8, 4, 24), 256>>>(pq);

    // join: pm needs senht (conv chain) + weights
    cudaStreamWaitEvent(0, evConv, 0);
    long moff = 8LL * SS * C2;
    GArg pm = {};
    pm.A[0] = senht; pm.A[1] = shnt; pm.A[2] = shnt;
    pm.A[3] = senht; pm.A[4] = shnt; pm.A[5] = shnt;
    pm.W[0] = hw[3]; pm.W[1] = hw[4]; pm.W[2] = hw[5];
    pm.W[3] = hw[6]; pm.W[4] = hw[7]; pm.W[5] = hw[8];
    pm.Y[0] = qm;        pm.Y[1] = km;        pm.Y[2] = vm;
    pm.Y[3] = qm + moff; pm.Y[4] = km + moff; pm.Y[5] = vm + moff;
    for (int i = 0; i < 6; i++) pm.bias[i] = nullptr;
    pm.sc[0] = 0.0625f; pm.sc[1] = 1.f; pm.sc[2] = 1.f;
    pm.sc[3] = 0.0625f; pm.sc[4] = 1.f; pm.sc[5] = 1.f;
    pm.aOuter = (long)SS * CCH; pm.yOuter = (long)SS * C2;
    pm.K = 512; pm.lda = 512; pm.N = 256; pm.ldy = 256; pm.act = 0;
    gemm128<__half><<<dim3(8, 2, 48), 256>>>(pm);

    // merged flash
    flash_all<<<768, 256, flSmem>>>(q, k, v, qm, km, vm, comb);

    // ff1 (silu)
    GArg f1a = {};
    f1a.A[0] = comb; f1a.W[0] = hw[9]; f1a.Y[0] = f1; f1a.bias[0] = ff_b1;
    f1a.sc[0] = 1.f;
    f1a.aOuter = (long)SS * 2 * CCH; f1a.yOuter = (long)SS * CCH;
    f1a.K = 1024; f1a.lda = 1024; f1a.N = 512; f1a.ldy = 512; f1a.act = 1;
    gemm128<__half><<<dim3(8, 4, 8), 256>>>(f1a);
    // ff2
    GArg f2a = {};
    f2a.A[0] = f1; f2a.W[0] = hw[10]; f2a.Y[0] = fus; f2a.bias[0] = ff_b2;
    f2a.sc[0] = 1.f;
    f2a.aOuter = (long)SS * CCH; f2a.yOuter = (long)SS * CCH;
    f2a.K = 512; f2a.lda = 512; f2a.N = 512; f2a.ldy = 512; f2a.act = 0;
    gemm128<__half><<<dim3(8, 4, 8), 256>>>(f2a);
    // out proj
    GArg oa = {};
    oa.A[0] = fus; oa.W[0] = hw[11]; oa.Y[0] = fin; oa.bias[0] = out_b;
    oa.sc[0] = 1.f;
    oa.aOuter = (long)SS * CCH; oa.yOuter = (long)SS * CCH;
    oa.K = 512; oa.lda = 512; oa.N = 512; oa.ldy = 512; oa.act = 0;
    gemm128<float><<<dim3(8, 4, 8), 256>>>(oa);

    // post GN + residual
    gn_post_k<<<BATCH * NGR, 256>>>(fin, post_g, post_b, x, out);
}

// round 16
// speedup vs baseline: 1.1386x; 1.0097x over previous
#include <cuda_runtime.h>
#include <cuda_fp16.h>
#include <math.h>
#include <stdint.h>

#define BATCH 8
#define CCH 512
#define SS 1024
#define NHD 8
#define NGR 32
#define CG 16
#define C8 64
#define C2 256
#define GEPS 1e-6f
#define L2E 1.4426950408889634f

// ---------------- static scratch ----------------
__device__ __half d_hst  [BATCH*SS*CCH];
__device__ __half d_shnt [BATCH*SS*CCH];
__device__ __half d_senht[BATCH*SS*CCH];
__device__ __half d_a1t  [BATCH*SS*C8];
__device__ __half d_a2t  [BATCH*SS*C8];
__device__ __half d_q    [BATCH*SS*CCH];
__device__ __half d_k    [BATCH*SS*CCH];
__device__ __half d_v    [BATCH*SS*CCH];
__device__ __half d_qm   [2*BATCH*SS*C2];
__device__ __half d_km   [2*BATCH*SS*C2];
__device__ __half d_vm   [2*BATCH*SS*C2];
__device__ __half d_comb [BATCH*SS*2*CCH];
__device__ __half d_f1   [BATCH*SS*CCH];
__device__ __half d_fus  [BATCH*SS*CCH];
__device__ float  d_fin  [BATCH*SS*CCH];
__device__ __half d_w    [2654208];
__device__ __half d_w2   [36864];

// ---------------- helpers ----------------
__device__ __forceinline__ float blk_sum(float v, float* sb, int tid) {
    sb[tid] = v; __syncthreads();
    for (int o = 128; o > 0; o >>= 1) { if (tid < o) sb[tid] += sb[tid + o]; __syncthreads(); }
    float r = sb[0]; __syncthreads(); return r;
}
__device__ __forceinline__ float silu_f(float x) { return x / (1.0f + expf(-x)); }
__device__ __forceinline__ uint32_t pack2(float a, float b) {
    __half2 h = __floats2half2_rn(a, b);
    return *reinterpret_cast<uint32_t*>(&h);
}
__device__ __forceinline__ void store2(float* p, float a, float b) {
    *(float2*)p = make_float2(a, b);
}
__device__ __forceinline__ void store2(__half* p, float a, float b) {
    *(uint32_t*)p = pack2(a, b);
}
__device__ __forceinline__ uint32_t exp2_h2(float t0, float t1) {
    uint32_t h = pack2(t0, t1);
    uint32_t r;
    asm("ex2.approx.f16x2 %0, %1;" : "=r"(r) : "r"(h));
    return r;
}
__device__ __forceinline__ uint32_t cvsm(const void* p) {
    return (uint32_t)__cvta_generic_to_shared(p);
}
__device__ __forceinline__ void ldsm_x4(uint32_t& r0, uint32_t& r1, uint32_t& r2,
                                        uint32_t& r3, uint32_t addr) {
    asm volatile("ldmatrix.sync.aligned.m8n8.x4.shared.b16 {%0,%1,%2,%3}, [%4];"
        : "=r"(r0), "=r"(r1), "=r"(r2), "=r"(r3) : "r"(addr));
}
__device__ __forceinline__ void ldsm_x4_t(uint32_t& r0, uint32_t& r1, uint32_t& r2,
                                          uint32_t& r3, uint32_t addr) {
    asm volatile("ldmatrix.sync.aligned.m8n8.x4.trans.shared.b16 {%0,%1,%2,%3}, [%4];"
        : "=r"(r0), "=r"(r1), "=r"(r2), "=r"(r3) : "r"(addr));
}

#define MMA16(d, a0, a1, a2, a3, b0, b1) \
    asm volatile("mma.sync.aligned.m16n8k16.row.col.f32.f16.f16.f32 " \
        "{%0,%1,%2,%3},{%4,%5,%6,%7},{%8,%9},{%0,%1,%2,%3};" \
        : "+f"((d)[0]), "+f"((d)[1]), "+f"((d)[2]), "+f"((d)[3]) \
        : "r"(a0), "r"(a1), "r"(a2), "r"(a3), "r"(b0), "r"(b1))

// ---------------- weight conversion fp32 -> half ----------------
struct WC { const float* src[13]; int cnt4[13]; int off[13]; };
__global__ void wcvt(WC wc, __half* dst) {
    int which = blockIdx.y;
    int idx = blockIdx.x * 256 + threadIdx.x;
    if (idx < wc.cnt4[which]) {
        float4 v = *(const float4*)&wc.src[which][idx * 4];
        uint2 pk = make_uint2(pack2(v.x, v.y), pack2(v.z, v.w));
        *(uint2*)&dst[wc.off[which] + idx * 4] = pk;
    }
}
__global__ void w2cvt(const float* __restrict__ src, __half* __restrict__ dst) {
    int idx = blockIdx.x * 256 + threadIdx.x;
    if (idx < 36864) {
        int oc = idx / 576, rem = idx % 576;
        int tap = rem >> 6, ci = rem & 63;
        dst[idx] = __float2half(src[oc * 576 + ci * 9 + tap]);
    }
}

// =====================================================================
// Fused double GroupNorm -> half token-major hs_t, shn_t.
// =====================================================================
__global__ void gn_fused(const float* __restrict__ x,
                         const float* __restrict__ pre_g, const float* __restrict__ pre_b,
                         const float* __restrict__ pos,
                         const float* __restrict__ norm_g, const float* __restrict__ norm_b,
                         __half* __restrict__ hs_t, __half* __restrict__ shn_t) {
    extern __shared__ float xs[];
    __shared__ float sb[256];
    __shared__ float pgs[16], pbs[16], ngs[16], nbs[16];

    int tid = threadIdx.x;
    int b = blockIdx.x / NGR, gi = blockIdx.x % NGR;
    long base = (long)b * CCH * SS + (long)gi * CG * SS;
    if (tid < 16) {
        int c = gi * 16 + tid;
        pgs[tid] = pre_g[c]; pbs[tid] = pre_b[c];
        ngs[tid] = norm_g[c]; nbs[tid] = norm_b[c];
    }

    float s1 = 0.f, s2 = 0.f;
    for (int i = tid; i < CG * SS; i += 256) {
        float v = x[base + i];
        xs[i] = v; s1 += v; s2 += v * v;
    }
    s1 = blk_sum(s1, sb, tid);
    s2 = blk_sum(s2, sb, tid);
    float mu1 = s1 / (float)(CG * SS);
    float inv1 = rsqrtf(s2 / (float)(CG * SS) - mu1 * mu1 + GEPS);

    float t1 = 0.f, t2 = 0.f;
    for (int i = tid; i < CG * SS; i += 256) {
        int cl = i >> 10, s = i & 1023;
        int c = gi * CG + cl;
        float h = (xs[i] - mu1) * inv1 * pgs[cl] + pbs[cl] + pos[(long)c * SS + s];
        xs[i] = h;
        t1 += h; t2 += h * h;
    }
    t1 = blk_sum(t1, sb, tid);
    t2 = blk_sum(t2, sb, tid);
    float mu2 = t1 / (float)(CG * SS);
    float inv2 = rsqrtf(t2 / (float)(CG * SS) - mu2 * mu2 + GEPS);

    long tbase = ((long)b * SS) * CCH + gi * 16;
    for (int s = tid; s < SS; s += 256) {
        uint32_t wh[8], wn[8];
        #pragma unroll
        for (int cl = 0; cl < 16; cl += 2) {
            float h0 = xs[cl * 1024 + s], h1 = xs[(cl + 1) * 1024 + s];
            wh[cl >> 1] = pack2(h0, h1);
            float n0 = (h0 - mu2) * inv2 * ngs[cl] + nbs[cl];
            float n1 = (h1 - mu2) * inv2 * ngs[cl + 1] + nbs[cl + 1];
            wn[cl >> 1] = pack2(n0, n1);
        }
        __half* ph = hs_t + tbase + (long)s * CCH;
        *(uint4*)ph       = make_uint4(wh[0], wh[1], wh[2], wh[3]);
        *(uint4*)(ph + 8) = make_uint4(wh[4], wh[5], wh[6], wh[7]);
        __half* pn = shn_t + tbase + (long)s * CCH;
        *(uint4*)pn       = make_uint4(wn[0], wn[1], wn[2], wn[3]);
        *(uint4*)(pn + 8) = make_uint4(wn[4], wn[5], wn[6], wn[7]);
    }
}

// ---------------- group norm token-major + residual ----------------
__global__ void gn_post_k(const float* __restrict__ xt, const float* __restrict__ g,
                          const float* __restrict__ be, const float* __restrict__ resid,
                          float* __restrict__ y) {
    __shared__ float sb[256];
    int tid = threadIdx.x;
    int b = blockIdx.x / NGR, gi = blockIdx.x % NGR;
    long tbase = (long)b * SS * CCH + gi * CG;
    float s1 = 0.f, s2 = 0.f;
    for (int i = tid; i < CG * SS; i += 256) {
        int s = i >> 4, cl = i & 15;
        float v = xt[tbase + (long)s * CCH + cl]; s1 += v; s2 += v * v;
    }
    s1 = blk_sum(s1, sb, tid);
    s2 = blk_sum(s2, sb, tid);
    float mu = s1 / (float)(CG * SS);
    float var = s2 / (float)(CG * SS) - mu * mu;
    float inv = rsqrtf(var + GEPS);
    for (int i = tid; i < CG * SS; i += 256) {
        int s = i >> 4, cl = i & 15;
        int c = gi * CG + cl;
        float v = (xt[tbase + (long)s * CCH + cl] - mu) * inv * g[c] + be[c];
        long oidx = (long)b * CCH * SS + (long)c * SS + s;
        y[oidx] = v + resid[oidx];
    }
}

// =====================================================================
// Unified fp16 GEMM (NT), 128x128 tile, half weights.
// =====================================================================
struct GArg {
    const __half* A[6]; const __half* W[6]; void* Y[6]; const float* bias[6];
    float sc[6];
    long aOuter, yOuter;
    int K, lda, N, ldy, act;
};

template<typename OutT>
__global__ __launch_bounds__(256, 2) void gemm128(GArg ga) {
    __shared__ __align__(16) uint32_t As32[2 * 128 * 20];
    __shared__ __align__(16) uint32_t Bs32[2 * 128 * 20];

    int z = blockIdx.z;
    int which = z >> 3, b = z & 7;
    const __half* Ab = ga.A[which] + (long)b * ga.aOuter;
    const __half* Bb = ga.W[which];
    OutT*         Yb = (OutT*)ga.Y[which] + (long)b * ga.yOuter;
    const float* bias = ga.bias[which];
    float scl = ga.sc[which];
    int K = ga.K, lda = ga.lda, ldy = ga.ldy, act = ga.act;
    int m0 = blockIdx.x * 128, n0 = blockIdx.y * 128;

    int tid = threadIdx.x;
    int w = tid >> 5, lane = tid & 31;
    int wm = w & 1, wn = w >> 1;
    int g = lane >> 2, tig = lane & 3;
    int rbase = wm * 64, cbase = wn * 32;
    int lrow = lane & 7, lmat = lane >> 3;
    int fr_row = (lmat & 1) * 8 + lrow;
    int fr_col = (lmat >> 1) * 4;
    uint32_t As_b = cvsm(As32), Bs_b = cvsm(Bs32);

    float acc[4][4][4];
    #pragma unroll
    for (int i = 0; i < 4; i++)
        #pragma unroll
        for (int j = 0; j < 4; j++)
            #pragma unroll
            for (int l = 0; l < 4; l++) acc[i][j][l] = 0.f;

    uint4 aR[2], bR[2];
    int w4 = (tid & 3) * 4, mb = tid >> 2;

    auto ldg = [&](int k0) {
        #pragma unroll
        for (int it = 0; it < 2; it++)
            aR[it] = *(const uint4*)&Ab[(long)(m0 + mb + it * 64) * lda + k0 + w4 * 2];
        #pragma unroll
        for (int it = 0; it < 2; it++)
            bR[it] = *(const uint4*)&Bb[(long)(n0 + mb + it * 64) * K + k0 + w4 * 2];
    };
    auto sts = [&](int p) {
        uint32_t* Ad = As32 + p * 2560;
        uint32_t* Bd = Bs32 + p * 2560;
        #pragma unroll
        for (int it = 0; it < 2; it++)
            *(uint4*)&Ad[(mb + it * 64) * 20 + w4] = aR[it];
        #pragma unroll
        for (int it = 0; it < 2; it++)
            *(uint4*)&Bd[(mb + it * 64) * 20 + w4] = bR[it];
    };

    ldg(0); sts(0);
    __syncthreads();
    for (int k0 = 0; k0 < K; k0 += 32) {
        int p = (k0 >> 5) & 1;
        bool more = (k0 + 32 < K);
        if (more) ldg(k0 + 32);

        uint32_t Ap = As_b + (uint32_t)p * 2560 * 4;
        uint32_t Bp = Bs_b + (uint32_t)p * 2560 * 4;
        #pragma unroll
        for (int ks = 0; ks < 2; ks++) {
            int kw = ks * 8;
            uint32_t af[4][4], bf[4][2];
            #pragma unroll
            for (int mt = 0; mt < 4; mt++) {
                int r0 = rbase + mt * 16;
                ldsm_x4(af[mt][0], af[mt][1], af[mt][2], af[mt][3],
                        Ap + (uint32_t)(((r0 + fr_row) * 20) + kw + fr_col) * 4);
            }
            ldsm_x4(bf[0][0], bf[1][0], bf[2][0], bf[3][0],
                    Bp + (uint32_t)(((cbase + lmat * 8 + lrow) * 20) + kw) * 4);
            ldsm_x4(bf[0][1], bf[1][1], bf[2][1], bf[3][1],
                    Bp + (uint32_t)(((cbase + lmat * 8 + lrow) * 20) + kw + 4) * 4);
            #pragma unroll
            for (int mt = 0; mt < 4; mt++)
                #pragma unroll
                for (int nt = 0; nt < 4; nt++)
                    MMA16(acc[mt][nt], af[mt][0], af[mt][1], af[mt][2], af[mt][3],
                          bf[nt][0], bf[nt][1]);
        }
        if (more) sts(p ^ 1);
        __syncthreads();
    }

    #pragma unroll
    for (int mt = 0; mt < 4; mt++)
        #pragma unroll
        for (int nt = 0; nt < 4; nt++) {
            int r = m0 + rbase + mt * 16 + g;
            int cN = n0 + cbase + nt * 8 + 2 * tig;
            float b0 = bias ? bias[cN] : 0.f;
            float b1 = bias ? bias[cN + 1] : 0.f;
            float v0 = acc[mt][nt][0] * scl + b0;
            float v1 = acc[mt][nt][1] * scl + b1;
            float v2 = acc[mt][nt][2] * scl + b0;
            float v3 = acc[mt][nt][3] * scl + b1;
            if (act == 1) { v0 = silu_f(v0); v1 = silu_f(v1); v2 = silu_f(v2); v3 = silu_f(v3); }
            store2(&Yb[(long)r * ldy + cN],       v0, v1);
            store2(&Yb[(long)(r + 8) * ldy + cN], v2, v3);
        }
}

// =====================================================================
// conv1 as GEMM: a1t = silu(hst . w1 + b), half token-major out.
// =====================================================================
__global__ __launch_bounds__(256) void conv1_gemm(
        const __half* __restrict__ A, const __half* __restrict__ Bm,
        const float* __restrict__ bias, __half* __restrict__ Y) {
    __shared__ __align__(16) uint32_t As32[2 * 128 * 20];
    __shared__ __align__(16) uint32_t Bs32[2 * 64 * 20];

    int b = blockIdx.z;
    const __half* Ab = A + (long)b * SS * CCH;
    __half* Yb = Y + (long)b * SS * C8;
    int m0 = blockIdx.x * 128;

    int tid = threadIdx.x;
    int w = tid >> 5, lane = tid & 31;
    int wm = w & 3, wn = w >> 2;
    int g = lane >> 2, tig = lane & 3;
    int rbase = wm * 32, cbase = wn * 32;
    int lrow = lane & 7, lmat = lane >> 3;
    int fr_row = (lmat & 1) * 8 + lrow;
    int fr_col = (lmat >> 1) * 4;
    uint32_t As_b = cvsm(As32), Bs_b = cvsm(Bs32);

    float acc[2][4][4];
    #pragma unroll
    for (int i = 0; i < 2; i++)
        #pragma unroll
        for (int j = 0; j < 4; j++)
            #pragma unroll
            for (int l = 0; l < 4; l++) acc[i][j][l] = 0.f;

    uint4 aR[2], bR;
    int w4 = (tid & 3) * 4, mb = tid >> 2;

    auto ldg = [&](int k0) {
        #pragma unroll
        for (int it = 0; it < 2; it++)
            aR[it] = *(const uint4*)&Ab[(long)(m0 + mb + it * 64) * CCH + k0 + w4 * 2];
        bR = *(const uint4*)&Bm[(long)mb * 512 + k0 + w4 * 2];
    };
    auto sts = [&](int p) {
        uint32_t* Ad = As32 + p * 2560;
        uint32_t* Bd = Bs32 + p * 1280;
        #pragma unroll
        for (int it = 0; it < 2; it++)
            *(uint4*)&Ad[(mb + it * 64) * 20 + w4] = aR[it];
        *(uint4*)&Bd[mb * 20 + w4] = bR;
    };

    ldg(0); sts(0);
    __syncthreads();
    for (int k0 = 0; k0 < 512; k0 += 32) {
        int p = (k0 >> 5) & 1;
        bool more = (k0 + 32 < 512);
        if (more) ldg(k0 + 32);

        uint32_t Ap = As_b + (uint32_t)p * 2560 * 4;
        uint32_t Bp = Bs_b + (uint32_t)p * 1280 * 4;
        #pragma unroll
        for (int ks = 0; ks < 2; ks++) {
            int kw = ks * 8;
            uint32_t af[2][4], bf[4][2];
            #pragma unroll
            for (int mt = 0; mt < 2; mt++) {
                int r0 = rbase + mt * 16;
                ldsm_x4(af[mt][0], af[mt][1], af[mt][2], af[mt][3],
                        Ap + (uint32_t)(((r0 + fr_row) * 20) + kw + fr_col) * 4);
            }
            ldsm_x4(bf[0][0], bf[1][0], bf[2][0], bf[3][0],
                    Bp + (uint32_t)(((cbase + lmat * 8 + lrow) * 20) + kw) * 4);
            ldsm_x4(bf[0][1], bf[1][1], bf[2][1], bf[3][1],
                    Bp + (uint32_t)(((cbase + lmat * 8 + lrow) * 20) + kw + 4) * 4);
            #pragma unroll
            for (int mt = 0; mt < 2; mt++)
                #pragma unroll
                for (int nt = 0; nt < 4; nt++)
                    MMA16(acc[mt][nt], af[mt][0], af[mt][1], af[mt][2], af[mt][3],
                          bf[nt][0], bf[nt][1]);
        }
        if (more) sts(p ^ 1);
        __syncthreads();
    }

    #pragma unroll
    for (int mt = 0; mt < 2; mt++)
        #pragma unroll
        for (int nt = 0; nt < 4; nt++) {
            int r = m0 + rbase + mt * 16 + g;
            int cN = cbase + nt * 8 + 2 * tig;
            float b0 = bias[cN], b1 = bias[cN + 1];
            store2(&Yb[(long)r * C8 + cN],       silu_f(acc[mt][nt][0] + b0), silu_f(acc[mt][nt][1] + b1));
            store2(&Yb[(long)(r + 8) * C8 + cN], silu_f(acc[mt][nt][2] + b0), silu_f(acc[mt][nt][3] + b1));
        }
}

// =====================================================================
// conv2 as IMPLICIT GEMM (9 taps x 64 ci), zero-padded shifts.
// =====================================================================
__global__ __launch_bounds__(256) void conv2_gemm(
        const __half* __restrict__ A, const __half* __restrict__ Bm,
        const float* __restrict__ bias, __half* __restrict__ Y) {
    __shared__ __align__(16) uint32_t As32[128 * 36];
    __shared__ __align__(16) uint32_t Bs32[64 * 36];

    int b = blockIdx.z;
    const __half* Ab = A + (long)b * SS * C8;
    __half* Yb = Y + (long)b * SS * C8;
    int m0 = blockIdx.x * 128;

    int tid = threadIdx.x;
    int w = tid >> 5, lane = tid & 31;
    int wm = w & 3, wn = w >> 2;
    int g = lane >> 2, tig = lane & 3;
    int rbase = wm * 32, cbase = wn * 32;
    int lrow = lane & 7, lmat = lane >> 3;
    int fr_row = (lmat & 1) * 8 + lrow;
    int fr_col = (lmat >> 1) * 4;
    uint32_t As_b = cvsm(As32), Bs_b = cvsm(Bs32);

    float acc[2][4][4];
    #pragma unroll
    for (int i = 0; i < 2; i++)
        #pragma unroll
        for (int j = 0; j < 4; j++)
            #pragma unroll
            for (int l = 0; l < 4; l++) acc[i][j][l] = 0.f;

    uint4 aR[4], bR[2];

    auto ldg_tap = [&](int tap) {
        int dy = tap / 3 - 1, dx = tap % 3 - 1;
        #pragma unroll
        for (int f = 0; f < 4; f++) {
            int idx = tid + f * 256;
            int r = idx >> 3, c8 = idx & 7;
            int s = m0 + r;
            int sy = (s >> 5) + dy, sx = (s & 31) + dx;
            bool valid = ((unsigned)sy < 32u) && ((unsigned)sx < 32u);
            aR[f] = valid ? *(const uint4*)&Ab[(long)((sy << 5) + sx) * C8 + c8 * 8]
                          : make_uint4(0u, 0u, 0u, 0u);
        }
        #pragma unroll
        for (int f = 0; f < 2; f++) {
            int idx = tid + f * 256;
            int r = idx >> 3, c8 = idx & 7;
            bR[f] = *(const uint4*)&Bm[(long)r * 576 + tap * 64 + c8 * 8];
        }
    };
    auto sts_tap = [&]() {
        #pragma unroll
        for (int f = 0; f < 4; f++) {
            int idx = tid + f * 256;
            int r = idx >> 3, c8 = idx & 7;
            *(uint4*)&As32[r * 36 + c8 * 4] = aR[f];
        }
        #pragma unroll
        for (int f = 0; f < 2; f++) {
            int idx = tid + f * 256;
            int r = idx >> 3, c8 = idx & 7;
            *(uint4*)&Bs32[r * 36 + c8 * 4] = bR[f];
        }
    };

    ldg_tap(0);
    for (int tap = 0; tap < 9; tap++) {
        sts_tap();
        __syncthreads();
        if (tap < 8) ldg_tap(tap + 1);

        #pragma unroll
        for (int ks = 0; ks < 4; ks++) {
            int kw = ks * 8;
            uint32_t af[2][4], bf[4][2];
            #pragma unroll
            for (int mt = 0; mt < 2; mt++) {
                int r0 = rbase + mt * 16;
                ldsm_x4(af[mt][0], af[mt][1], af[mt][2], af[mt][3],
                        As_b + (uint32_t)(((r0 + fr_row) * 36) + kw + fr_col) * 4);
            }
            ldsm_x4(bf[0][0], bf[1][0], bf[2][0], bf[3][0],
                    Bs_b + (uint32_t)(((cbase + lmat * 8 + lrow) * 36) + kw) * 4);
            ldsm_x4(bf[0][1], bf[1][1], bf[2][1], bf[3][1],
                    Bs_b + (uint32_t)(((cbase + lmat * 8 + lrow) * 36) + kw + 4) * 4);
            #pragma unroll
            for (int mt = 0; mt < 2; mt++)
                #pragma unroll
                for (int nt = 0; nt < 4; nt++)
                    MMA16(acc[mt][nt], af[mt][0], af[mt][1], af[mt][2], af[mt][3],
                          bf[nt][0], bf[nt][1]);
        }
        __syncthreads();
    }

    #pragma unroll
    for (int mt = 0; mt < 2; mt++)
        #pragma unroll
        for (int nt = 0; nt < 4; nt++) {
            int r = m0 + rbase + mt * 16 + g;
            int cN = cbase + nt * 8 + 2 * tig;
            float b0 = bias[cN], b1 = bias[cN + 1];
            store2(&Yb[(long)r * C8 + cN],       silu_f(acc[mt][nt][0] + b0), silu_f(acc[mt][nt][1] + b1));
            store2(&Yb[(long)(r + 8) * C8 + cN], silu_f(acc[mt][nt][2] + b0), silu_f(acc[mt][nt][3] + b1));
        }
}

// ---------------- fused conv3(64->1)+sigmoid + senh scale ----------------
// Block: 32 tokens. Phase1: 8 thr/token dot(a2t, w)+sigmoid. Phase2: scale
// hs_t's 512 channels by the gate.
__global__ void conv3_senh(const __half* __restrict__ a2t, const float* __restrict__ w,
                           const float* __restrict__ bias, const __half* __restrict__ hs_t,
                           __half* __restrict__ senh_t) {
    __shared__ float ws[64];
    __shared__ float swv[32];
    int tid = threadIdx.x;
    if (tid < 64) ws[tid] = w[tid];
    __syncthreads();
    int tok0 = blockIdx.x * 32;
    {
        int t = tid >> 3, ln = tid & 7;
        long o = (long)(tok0 + t) * C8 + ln * 8;
        uint4 v = *(const uint4*)&a2t[o];
        const __half2* h2 = (const __half2*)&v;
        float acc = 0.f;
        #pragma unroll
        for (int u = 0; u < 4; u++) {
            float2 fv = __half22float2(h2[u]);
            acc += fv.x * ws[ln * 8 + u * 2] + fv.y * ws[ln * 8 + u * 2 + 1];
        }
        acc += __shfl_xor_sync(0xffffffffu, acc, 1);
        acc += __shfl_xor_sync(0xffffffffu, acc, 2);
        acc += __shfl_xor_sync(0xffffffffu, acc, 4);
        if (ln == 0) swv[t] = 1.0f / (1.0f + expf(-(acc + bias[0])));
    }
    __syncthreads();
    #pragma unroll
    for (int it = 0; it < 8; it++) {
        int idx = tid + it * 256;              // 0..2047
        int t = idx >> 6, c8 = idx & 63;
        __half2 m = __float2half2_rn(swv[t]);
        long o = (long)(tok0 + t) * CCH + c8 * 8;
        uint4 v = *(const uint4*)&hs_t[o];
        __half2* h = (__half2*)&v;
        h[0] = __hmul2(h[0], m); h[1] = __hmul2(h[1], m);
        h[2] = __hmul2(h[2], m); h[3] = __hmul2(h[3], m);
        *(uint4*)&senh_t[o] = v;
    }
}

// =====================================================================
// Merged flash attention. Multi branch: double-buffered K/V staging.
// smem words: std 11840; multi 8448 + 2*2304(K) + 2304(P) + 2*2304(V) + 512
//            = 20480  -> FL_WORDS = 20480 (81.9 KB, 2 CTAs/SM fits 164 KB)
// =====================================================================
#define FL_WORDS 20480

__device__ __forceinline__ void flash_std_body(
        const __half* __restrict__ Q, const __half* __restrict__ K,
        const __half* __restrict__ V, __half* __restrict__ O,
        int bh, int xq, uint32_t* smw) {
    uint32_t* Qs = smw;
    uint32_t* KP = smw + 128 * 36;
    uint32_t* Vs = smw + 2 * 128 * 36;
    float* redm = (float*)(smw + 2 * 128 * 36 + 64 * 36);
    float* redl = redm + 256;

    int b = bh >> 3, h = bh & 7;
    const __half* Qb = Q + (long)b * SS * CCH + h * 64;
    const __half* Kb = K + (long)b * SS * CCH + h * 64;
    const __half* Vb = V + (long)b * SS * CCH + h * 64;
    __half* Ob = O + (long)b * SS * (2 * CCH) + h * 64;
    int q0 = xq * 128;

    int tid = threadIdx.x;
    int w = tid >> 5, lane = tid & 31;
    int wm = w & 3, wn = w >> 2;
    int g = lane >> 2, tig = lane & 3;
    int rbase = wm * 32, cbase = wn * 32;
    int lrow = lane & 7, lmat = lane >> 3;
    int fr_row = (lmat & 1) * 8 + lrow;
    int fr_col = (lmat >> 1) * 4;
    int t_kb = lmat >> 1, t_hb = lmat & 1;
    uint32_t Qs_b = cvsm(Qs), KP_b = cvsm(KP), Vs_b = cvsm(Vs);

    #pragma unroll
    for (int f = 0; f < 4; f++) {
        int idx = tid + f * 256;
        int r = idx >> 3, w4 = (idx & 7) * 4;
        uint4 v4 = *(const uint4*)&Qb[(long)(q0 + r) * CCH + (idx & 7) * 8];
        *(uint4*)&Qs[r * 36 + w4] = v4;
    }

    uint4 kR[2], vR[2];
    int st_r = tid >> 3, st_w4 = (tid & 7) * 4, st_c = (tid & 7) * 8;
    auto ldg_kv = [&](int j) {
        #pragma unroll
        for (int f = 0; f < 2; f++) {
            long goff = (long)(j * 64 + st_r + f * 32) * CCH + st_c;
            kR[f] = *(const uint4*)&Kb[goff];
            vR[f] = *(const uint4*)&Vb[goff];
        }
    };
    auto sts_kv = [&]() {
        #pragma unroll
        for (int f = 0; f < 2; f++) {
            *(uint4*)&KP[(st_r + f * 32) * 36 + st_w4] = kR[f];
            *(uint4*)&Vs[(st_r + f * 32) * 36 + st_w4] = vR[f];
        }
    };

    float accO[2][4][4];
    #pragma unroll
    for (int i = 0; i < 2; i++)
        #pragma unroll
        for (int j = 0; j < 4; j++)
            #pragma unroll
            for (int l = 0; l < 4; l++) accO[i][j][l] = 0.f;
    float mst[4] = { -1e30f, -1e30f, -1e30f, -1e30f };
    float lst[4] = { 0.f, 0.f, 0.f, 0.f };

    ldg_kv(0);
    for (int j = 0; j < 16; j++) {
        sts_kv();
        __syncthreads();
        if (j + 1 < 16) ldg_kv(j + 1);

        float acc[2][4][4];
        #pragma unroll
        for (int i = 0; i < 2; i++)
            #pragma unroll
            for (int jj = 0; jj < 4; jj++)
                #pragma unroll
                for (int l = 0; l < 4; l++) acc[i][jj][l] = 0.f;
        #pragma unroll
        for (int ks = 0; ks < 4; ks++) {
            int kw = ks * 8;
            uint32_t af[2][4], bf[4][2];
            #pragma unroll
            for (int mt = 0; mt < 2; mt++) {
                int r0 = rbase + mt * 16;
                ldsm_x4(af[mt][0], af[mt][1], af[mt][2], af[mt][3],
                        Qs_b + (uint32_t)(((r0 + fr_row) * 36) + kw + fr_col) * 4);
            }
            ldsm_x4(bf[0][0], bf[1][0], bf[2][0], bf[3][0],
                    KP_b + (uint32_t)(((cbase + lmat * 8 + lrow) * 36) + kw) * 4);
            ldsm_x4(bf[0][1], bf[1][1], bf[2][1], bf[3][1],
                    KP_b + (uint32_t)(((cbase + lmat * 8 + lrow) * 36) + kw + 4) * 4);
            #pragma unroll
            for (int mt = 0; mt < 2; mt++)
                #pragma unroll
                for (int nt = 0; nt < 4; nt++)
                    MMA16(acc[mt][nt], af[mt][0], af[mt][1], af[mt][2], af[mt][3],
                          bf[nt][0], bf[nt][1]);
        }

        #pragma unroll
        for (int mt = 0; mt < 2; mt++)
            #pragma unroll
            for (int hh = 0; hh < 2; hh++) {
                float mx = -1e30f;
                #pragma unroll
                for (int nt = 0; nt < 4; nt++) {
                    mx = fmaxf(mx, acc[mt][nt][hh * 2]);
                    mx = fmaxf(mx, acc[mt][nt][hh * 2 + 1]);
                }
                mx = fmaxf(mx, __shfl_xor_sync(0xffffffffu, mx, 1));
                mx = fmaxf(mx, __shfl_xor_sync(0xffffffffu, mx, 2));
                if (tig == 0) redm[wn * 128 + rbase + mt * 16 + hh * 8 + g] = mx;
            }
        __syncthreads();

        #pragma unroll
        for (int mt = 0; mt < 2; mt++)
            #pragma unroll
            for (int hh = 0; hh < 2; hh++) {
                int i = mt * 2 + hh;
                int rloc = rbase + mt * 16 + hh * 8 + g;
                float mch = fmaxf(redm[rloc], redm[128 + rloc]);
                float mnew = fmaxf(mst[i], mch);
                float corr = __expf(mst[i] - mnew);
                mst[i] = mnew;
                float s = 0.f;
                #pragma unroll
                for (int nt = 0; nt < 4; nt++) {
                    uint32_t ph = exp2_h2((acc[mt][nt][hh * 2]     - mnew) * L2E,
                                          (acc[mt][nt][hh * 2 + 1] - mnew) * L2E);
                    KP[rloc * 36 + wn * 16 + nt * 4 + tig] = ph;
                    float2 pf = __half22float2(*(__half2*)&ph);
                    s += pf.x + pf.y;
                    accO[mt][nt][hh * 2]     *= corr;
                    accO[mt][nt][hh * 2 + 1] *= corr;
                }
                s += __shfl_xor_sync(0xffffffffu, s, 1);
                s += __shfl_xor_sync(0xffffffffu, s, 2);
                if (tig == 0) redl[wn * 128 + rloc] = s;
                lst[i] *= corr;
            }
        __syncthreads();
        #pragma unroll
        for (int mt = 0; mt < 2; mt++)
            #pragma unroll
            for (int hh = 0; hh < 2; hh++) {
                int rloc = rbase + mt * 16 + hh * 8 + g;
                lst[mt * 2 + hh] += redl[rloc] + redl[128 + rloc];
            }

        #pragma unroll
        for (int ks = 0; ks < 4; ks++) {
            int kw = ks * 8;
            uint32_t af[2][4], bf[4][2];
            #pragma unroll
            for (int mt = 0; mt < 2; mt++) {
                int r0 = rbase + mt * 16;
                ldsm_x4(af[mt][0], af[mt][1], af[mt][2], af[mt][3],
                        KP_b + (uint32_t)(((r0 + fr_row) * 36) + kw + fr_col) * 4);
            }
            uint32_t vaddr = Vs_b + (uint32_t)((ks * 16 + t_kb * 8 + lrow) * 144
                                               + (cbase + t_hb * 8) * 2);
            ldsm_x4_t(bf[0][0], bf[1][0], bf[0][1], bf[1][1], vaddr);
            ldsm_x4_t(bf[2][0], bf[3][0], bf[2][1], bf[3][1], vaddr + 32);
            #pragma unroll
            for (int mt = 0; mt < 2; mt++)
                #pragma unroll
                for (int nt = 0; nt < 4; nt++)
                    MMA16(accO[mt][nt], af[mt][0], af[mt][1], af[mt][2], af[mt][3],
                          bf[nt][0], bf[nt][1]);
        }
        __syncthreads();
    }

    #pragma unroll
    for (int mt = 0; mt < 2; mt++) {
        float inv0 = 1.0f / lst[mt * 2];
        float inv1 = 1.0f / lst[mt * 2 + 1];
        #pragma unroll
        for (int nt = 0; nt < 4; nt++) {
            int r = q0 + rbase + mt * 16 + g;
            int c = cbase + nt * 8 + 2 * tig;
            store2(&Ob[(long)r * 1024 + c],       accO[mt][nt][0] * inv0, accO[mt][nt][1] * inv0);
            store2(&Ob[(long)(r + 8) * 1024 + c], accO[mt][nt][2] * inv1, accO[mt][nt][3] * inv1);
        }
    }
}

__device__ __forceinline__ void flash_multi_body(
        const __half* __restrict__ Q, const __half* __restrict__ K,
        const __half* __restrict__ V, __half* __restrict__ O,
        int z, int xq, uint32_t* smw) {
    uint32_t* Qs  = smw;                       // [64][132]
    uint32_t* Ks0 = smw + 8448;                // [64][36] x2 ping-pong
    uint32_t* Ps  = smw + 8448 + 2 * 2304;     // [64][36]
    uint32_t* Vs0 = smw + 8448 + 3 * 2304;     // [64][36] x2 ping-pong
    float* redm = (float*)(smw + 8448 + 5 * 2304);
    float* redl = redm + 256;

    const __half* Qb = Q + (long)z * SS * C2;
    const __half* Kb = K + (long)z * SS * C2;
    const __half* Vb = V + (long)z * SS * C2;
    int br = z >> 3, b = z & 7;
    __half* Ob = O + (long)b * SS * 1024 + 512 + br * 256;
    int q0 = xq * 64;

    int tid = threadIdx.x;
    int w = tid >> 5, lane = tid & 31;
    int wm = w & 1, wn = w >> 1;
    int g = lane >> 2, tig = lane & 3;
    int rbase = wm * 32;
    int lrow = lane & 7, lmat = lane >> 3;
    int fr_row = (lmat & 1) * 8 + lrow;
    int fr_col = (lmat >> 1) * 4;
    int t_kb = lmat >> 1, t_hb = lmat & 1;
    uint32_t Qs_b = cvsm(Qs), Ks_b = cvsm(Ks0), Ps_b = cvsm(Ps), Vs_b = cvsm(Vs0);

    #pragma unroll
    for (int f = 0; f < 8; f++) {
        int idx = tid + f * 256;
        int r = idx >> 5, c8 = idx & 31;
        uint4 qv = *(const uint4*)&Qb[(long)(q0 + r) * C2 + c8 * 8];
        *(uint4*)&Qs[r * 132 + c8 * 4] = qv;
    }

    int st_r = tid >> 3, st_w4 = (tid & 7) * 4, st_c = (tid & 7) * 8;
    uint4 sR[2];
    auto ldg_s = [&](const __half* P, int j, int dc) {
        #pragma unroll
        for (int f = 0; f < 2; f++)
            sR[f] = *(const uint4*)&P[(long)(j * 64 + st_r + f * 32) * C2 + dc * 64 + st_c];
    };
    auto sts_s = [&](uint32_t* D) {
        #pragma unroll
        for (int f = 0; f < 2; f++)
            *(uint4*)&D[(st_r + f * 32) * 36 + st_w4] = sR[f];
    };

    float accO[2][8][4];
    #pragma unroll
    for (int i = 0; i < 2; i++)
        #pragma unroll
        for (int j = 0; j < 8; j++)
            #pragma unroll
            for (int l = 0; l < 4; l++) accO[i][j][l] = 0.f;
    float mst[4] = { -1e30f, -1e30f, -1e30f, -1e30f };
    float lst[4] = { 0.f, 0.f, 0.f, 0.f };

    for (int j = 0; j < 16; j++) {
        float acc[2][2][4];
        #pragma unroll
        for (int i = 0; i < 2; i++)
            #pragma unroll
            for (int jj = 0; jj < 2; jj++)
                #pragma unroll
                for (int l = 0; l < 4; l++) acc[i][jj][l] = 0.f;

        // ---- scores, K double-buffered ----
        ldg_s(Kb, j, 0);
        sts_s(Ks0);
        __syncthreads();
        for (int dc = 0; dc < 4; dc++) {
            int p = dc & 1;
            bool more = (dc < 3);
            if (more) ldg_s(Kb, j, dc + 1);
            uint32_t Kp = Ks_b + (uint32_t)p * 2304 * 4;
            #pragma unroll
            for (int ks = 0; ks < 4; ks++) {
                int kw = ks * 8;
                uint32_t af[2][4], bf[2][2];
                #pragma unroll
                for (int mt = 0; mt < 2; mt++) {
                    int r0 = rbase + mt * 16;
                    ldsm_x4(af[mt][0], af[mt][1], af[mt][2], af[mt][3],
                            Qs_b + (uint32_t)(((r0 + fr_row) * 132) + dc * 32 + kw + fr_col) * 4);
                }
                ldsm_x4(bf[0][0], bf[1][0], bf[0][1], bf[1][1],
                        Kp + (uint32_t)(((wn * 16 + fr_row) * 36) + kw + fr_col) * 4);
                #pragma unroll
                for (int mt = 0; mt < 2; mt++)
                    #pragma unroll
                    for (int nt = 0; nt < 2; nt++)
                        MMA16(acc[mt][nt], af[mt][0], af[mt][1], af[mt][2], af[mt][3],
                              bf[nt][0], bf[nt][1]);
            }
            if (more) sts_s(Ks0 + (p ^ 1) * 2304);
            __syncthreads();
        }

        // ---- online softmax ----
        #pragma unroll
        for (int mt = 0; mt < 2; mt++)
            #pragma unroll
            for (int hh = 0; hh < 2; hh++) {
                float mx = -1e30f;
                #pragma unroll
                for (int nt = 0; nt < 2; nt++) {
                    mx = fmaxf(mx, acc[mt][nt][hh * 2]);
                    mx = fmaxf(mx, acc[mt][nt][hh * 2 + 1]);
                }
                mx = fmaxf(mx, __shfl_xor_sync(0xffffffffu, mx, 1));
                mx = fmaxf(mx, __shfl_xor_sync(0xffffffffu, mx, 2));
                if (tig == 0) redm[wn * 64 + rbase + mt * 16 + hh * 8 + g] = mx;
            }
        __syncthreads();

        #pragma unroll
        for (int mt = 0; mt < 2; mt++)
            #pragma unroll
            for (int hh = 0; hh < 2; hh++) {
                int i = mt * 2 + hh;
                int rloc = rbase + mt * 16 + hh * 8 + g;
                float mch = fmaxf(fmaxf(redm[rloc], redm[64 + rloc]),
                                  fmaxf(redm[128 + rloc], redm[192 + rloc]));
                float mnew = fmaxf(mst[i], mch);
                float corr = __expf(mst[i] - mnew);
                mst[i] = mnew;
                float s = 0.f;
                #pragma unroll
                for (int nt = 0; nt < 2; nt++) {
                    uint32_t ph = exp2_h2((acc[mt][nt][hh * 2]     - mnew) * L2E,
                                          (acc[mt][nt][hh * 2 + 1] - mnew) * L2E);
                    Ps[rloc * 36 + wn * 8 + nt * 4 + tig] = ph;
                    float2 pf = __half22float2(*(__half2*)&ph);
                    s += pf.x + pf.y;
                }
                s += __shfl_xor_sync(0xffffffffu, s, 1);
                s += __shfl_xor_sync(0xffffffffu, s, 2);
                if (tig == 0) redl[wn * 64 + rloc] = s;
                lst[i] *= corr;
                #pragma unroll
                for (int nt = 0; nt < 8; nt++) {
                    accO[mt][nt][hh * 2]     *= corr;
                    accO[mt][nt][hh * 2 + 1] *= corr;
                }
            }
        __syncthreads();
        #pragma unroll
        for (int mt = 0; mt < 2; mt++)
            #pragma unroll
            for (int hh = 0; hh < 2; hh++) {
                int rloc = rbase + mt * 16 + hh * 8 + g;
                lst[mt * 2 + hh] += redl[rloc] + redl[64 + rloc]
                                  + redl[128 + rloc] + redl[192 + rloc];
            }

        // ---- O += P V, V double-buffered ----
        ldg_s(Vb, j, 0);
        sts_s(Vs0);
        __syncthreads();
        for (int dc = 0; dc < 4; dc++) {
            int p = dc & 1;
            bool more = (dc < 3);
            if (more) ldg_s(Vb, j, dc + 1);
            uint32_t Vp = Vs_b + (uint32_t)p * 2304 * 4;
            #pragma unroll
            for (int ks = 0; ks < 4; ks++) {
                int kw = ks * 8;
                uint32_t af[2][4], bf[2][2];
                #pragma unroll
                for (int mt = 0; mt < 2; mt++) {
                    int r0 = rbase + mt * 16;
                    ldsm_x4(af[mt][0], af[mt][1], af[mt][2], af[mt][3],
                            Ps_b + (uint32_t)(((r0 + fr_row) * 36) + kw + fr_col) * 4);
                }
                uint32_t vaddr = Vp + (uint32_t)((ks * 16 + t_kb * 8 + lrow) * 144
                                                 + (wn * 16 + t_hb * 8) * 2);
                ldsm_x4_t(bf[0][0], bf[1][0], bf[0][1], bf[1][1], vaddr);
                #pragma unroll
                for (int mt = 0; mt < 2; mt++)
                    #pragma unroll
                    for (int nt = 0; nt < 2; nt++)
                        MMA16(accO[mt][dc * 2 + nt], af[mt][0], af[mt][1], af[mt][2], af[mt][3],
                              bf[nt][0], bf[nt][1]);
            }
            if (more) sts_s(Vs0 + (p ^ 1) * 2304);
            __syncthreads();
        }
    }

    #pragma unroll
    for (int mt = 0; mt < 2; mt++) {
        float inv0 = 1.0f / lst[mt * 2];
        float inv1 = 1.0f / lst[mt * 2 + 1];
        #pragma unroll
        for (int u = 0; u < 8; u++) {
            int dc = u >> 1, nt = u & 1;
            int r = q0 + rbase + mt * 16 + g;
            int c = dc * 64 + wn * 16 + nt * 8 + 2 * tig;
            store2(&Ob[(long)r * 1024 + c],       accO[mt][u][0] * inv0, accO[mt][u][1] * inv0);
            store2(&Ob[(long)(r + 8) * 1024 + c], accO[mt][u][2] * inv1, accO[mt][u][3] * inv1);
        }
    }
}

__global__ __launch_bounds__(256, 2) void flash_all(
        const __half* __restrict__ q, const __half* __restrict__ k,
        const __half* __restrict__ v,
        const __half* __restrict__ qm, const __half* __restrict__ km,
        const __half* __restrict__ vm, __half* __restrict__ comb) {
    extern __shared__ uint32_t smw[];
    int bx = blockIdx.x;
    if (bx < 512) flash_std_body(q, k, v, comb, bx >> 3, bx & 7, smw);
    else { int i = bx - 512; flash_multi_body(qm, km, vm, comb, i >> 4, i & 15, smw); }
}

// ---------------- launch ----------------
static void* symv(const void* s) { void* p = nullptr; cudaGetSymbolAddress(&p, s); return p; }

extern "C" void kernel_launch(void* const* d_in, const int* in_sizes, int n_in,
                              void* d_out, int out_size) {
    (void)in_sizes; (void)n_in; (void)out_size;
    const float* x      = (const float*)d_in[0];
    const float* pre_g  = (const float*)d_in[1];
    const float* pre_b  = (const float*)d_in[2];
    const float* norm_g = (const float*)d_in[3];
    const float* norm_b = (const float*)d_in[4];
    const float* post_g = (const float*)d_in[5];
    const float* post_b = (const float*)d_in[6];
    const float* pos    = (const float*)d_in[7];
    const float* sa_w1  = (const float*)d_in[8];
    const float* sa_b1  = (const float*)d_in[9];
    const float* sa_w2  = (const float*)d_in[10];
    const float* sa_b2  = (const float*)d_in[11];
    const float* sa_w3  = (const float*)d_in[12];
    const float* sa_b3  = (const float*)d_in[13];
    const float* wq     = (const float*)d_in[14];
    const float* wk     = (const float*)d_in[15];
    const float* wv     = (const float*)d_in[16];
    const float* wq0    = (const float*)d_in[17];
    const float* wk0    = (const float*)d_in[18];
    const float* wv0    = (const float*)d_in[19];
    const float* wq1    = (const float*)d_in[20];
    const float* wk1    = (const float*)d_in[21];
    const float* wv1    = (const float*)d_in[22];
    const float* ff_w1  = (const float*)d_in[23];
    const float* ff_b1  = (const float*)d_in[24];
    const float* ff_w2  = (const float*)d_in[25];
    const float* ff_b2  = (const float*)d_in[26];
    const float* out_w  = (const float*)d_in[27];
    const float* out_b  = (const float*)d_in[28];
    float* out = (float*)d_out;

    __half *hst = (__half*)symv(d_hst), *shnt = (__half*)symv(d_shnt), *senht = (__half*)symv(d_senht);
    __half *a1t = (__half*)symv(d_a1t), *a2t = (__half*)symv(d_a2t);
    __half *q = (__half*)symv(d_q), *k = (__half*)symv(d_k), *v = (__half*)symv(d_v);
    __half *qm = (__half*)symv(d_qm), *km = (__half*)symv(d_km), *vm = (__half*)symv(d_vm);
    __half *comb = (__half*)symv(d_comb), *f1 = (__half*)symv(d_f1), *fus = (__half*)symv(d_fus);
    float  *fin = (float*)symv(d_fin);
    __half *wb = (__half*)symv(d_w);
    __half *w2h = (__half*)symv(d_w2);

    static cudaStream_t s1 = nullptr;
    static cudaEvent_t evFork = nullptr, evW = nullptr, evGN = nullptr, evConv = nullptr;
    if (!s1) {
        cudaStreamCreateWithFlags(&s1, cudaStreamNonBlocking);
        cudaEventCreateWithFlags(&evFork, cudaEventDisableTiming);
        cudaEventCreateWithFlags(&evW, cudaEventDisableTiming);
        cudaEventCreateWithFlags(&evGN, cudaEventDisableTiming);
        cudaEventCreateWithFlags(&evConv, cudaEventDisableTiming);
    }

    const int flSmem = FL_WORDS * 4;
    cudaFuncSetAttribute(flash_all, cudaFuncAttributeMaxDynamicSharedMemorySize, flSmem);
    const int gnSmem = 16 * 1024 * 4;
    cudaFuncSetAttribute(gn_fused, cudaFuncAttributeMaxDynamicSharedMemorySize, gnSmem);

    const float* wsrc[13] = { wq, wk, wv, wq0, wk0, wv0, wq1, wk1, wv1,
                              ff_w1, ff_w2, out_w, sa_w1 };
    const int wcnt[13] = { 262144, 262144, 262144, 131072, 131072, 131072,
                           131072, 131072, 131072, 524288, 262144, 262144, 32768 };
    WC wc; int off = 0;
    __half* hw[13];
    for (int i = 0; i < 13; i++) {
        wc.src[i] = wsrc[i]; wc.cnt4[i] = wcnt[i] / 4; wc.off[i] = off;
        hw[i] = wb + off;
        off += wcnt[i];
    }

    // fork: weight conversion on s1 under gn_fused
    cudaEventRecord(evFork, 0);
    cudaStreamWaitEvent(s1, evFork, 0);
    wcvt<<<dim3(512, 13), 256, 0, s1>>>(wc, wb);
    w2cvt<<<144, 256, 0, s1>>>(sa_w2, w2h);
    cudaEventRecord(evW, s1);

    gn_fused<<<BATCH * NGR, 256, gnSmem>>>(x, pre_g, pre_b, pos, norm_g, norm_b,
                                           hst, shnt);
    cudaEventRecord(evGN, 0);

    // s1: conv gate chain under pq
    cudaStreamWaitEvent(s1, evGN, 0);
    conv1_gemm<<<dim3(8, 1, BATCH), 256, 0, s1>>>(hst, hw[12], sa_b1, a1t);
    conv2_gemm<<<dim3(8, 1, BATCH), 256, 0, s1>>>(a1t, w2h, sa_b2, a2t);
    conv3_senh<<<BATCH * SS / 32, 256, 0, s1>>>(a2t, sa_w3, sa_b3, hst, senht);
    cudaEventRecord(evConv, s1);

    // stream 0: QKV projections
    cudaStreamWaitEvent(0, evW, 0);
    GArg pq = {};
    pq.A[0] = shnt; pq.A[1] = shnt; pq.A[2] = shnt;
    pq.W[0] = hw[0]; pq.W[1] = hw[1]; pq.W[2] = hw[2];
    pq.Y[0] = q;    pq.Y[1] = k;    pq.Y[2] = v;
    pq.bias[0] = pq.bias[1] = pq.bias[2] = nullptr;
    pq.sc[0] = 0.125f; pq.sc[1] = 1.f; pq.sc[2] = 1.f;
    pq.aOuter = (long)SS * CCH; pq.yOuter = (long)SS * 512;
    pq.K = 512; pq.lda = 512; pq.N = 512; pq.ldy = 512; pq.act = 0;
    gemm128<__half><<<dim3(8, 4, 24), 256>>>(pq);

    // join: pm needs senht
    cudaStreamWaitEvent(0, evConv, 0);
    long moff = 8LL * SS * C2;
    GArg pm = {};
    pm.A[0] = senht; pm.A[1] = shnt; pm.A[2] = shnt;
    pm.A[3] = senht; pm.A[4] = shnt; pm.A[5] = shnt;
    pm.W[0] = hw[3]; pm.W[1] = hw[4]; pm.W[2] = hw[5];
    pm.W[3] = hw[6]; pm.W[4] = hw[7]; pm.W[5] = hw[8];
    pm.Y[0] = qm;        pm.Y[1] = km;        pm.Y[2] = vm;
    pm.Y[3] = qm + moff; pm.Y[4] = km + moff; pm.Y[5] = vm + moff;
    for (int i = 0; i < 6; i++) pm.bias[i] = nullptr;
    pm.sc[0] = 0.0625f; pm.sc[1] = 1.f; pm.sc[2] = 1.f;
    pm.sc[3] = 0.0625f; pm.sc[4] = 1.f; pm.sc[5] = 1.f;
    pm.aOuter = (long)SS * CCH; pm.yOuter = (long)SS * C2;
    pm.K = 512; pm.lda = 512; pm.N = 256; pm.ldy = 256; pm.act = 0;
    gemm128<__half><<<dim3(8, 2, 48), 256>>>(pm);

    // merged flash
    flash_all<<<768, 256, flSmem>>>(q, k, v, qm, km, vm, comb);

    // ff1 (silu)
    GArg f1a = {};
    f1a.A[0] = comb; f1a.W[0] = hw[9]; f1a.Y[0] = f1; f1a.bias[0] = ff_b1;
    f1a.sc[0] = 1.f;
    f1a.aOuter = (long)SS * 2 * CCH; f1a.yOuter = (long)SS * CCH;
    f1a.K = 1024; f1a.lda = 1024; f1a.N = 512; f1a.ldy = 512; f1a.act = 1;
    gemm128<__half><<<dim3(8, 4, 8), 256>>>(f1a);
    // ff2
    GArg f2a = {};
    f2a.A[0] = f1; f2a.W[0] = hw[10]; f2a.Y[0] = fus; f2a.bias[0] = ff_b2;
    f2a.sc[0] = 1.f;
    f2a.aOuter = (long)SS * CCH; f2a.yOuter = (long)SS * CCH;
    f2a.K = 512; f2a.lda = 512; f2a.N = 512; f2a.ldy = 512; f2a.act = 0;
    gemm128<__half><<<dim3(8, 4, 8), 256>>>(f2a);
    // out proj
    GArg oa = {};
    oa.A[0] = fus; oa.W[0] = hw[11]; oa.Y[0] = fin; oa.bias[0] = out_b;
    oa.sc[0] = 1.f;
    oa.aOuter = (long)SS * CCH; oa.yOuter = (long)SS * CCH;
    oa.K = 512; oa.lda = 512; oa.N = 512; oa.ldy = 512; oa.act = 0;
    gemm128<float><<<dim3(8, 4, 8), 256>>>(oa);

    // post GN + residual
    gn_post_k<<<BATCH * NGR, 256>>>(fin, post_g, post_b, x, out);
}

// round 17
// speedup vs baseline: 1.2041x; 1.0575x over previous
#include <cuda_runtime.h>
#include <cuda_fp16.h>
#include <math.h>
#include <stdint.h>

#define BATCH 8
#define CCH 512
#define SS 1024
#define NHD 8
#define NGR 32
#define CG 16
#define C8 64
#define C2 256
#define GEPS 1e-6f
#define L2E 1.4426950408889634f

// ---------------- static scratch ----------------
__device__ __half d_hst  [BATCH*SS*CCH];
__device__ __half d_shnt [BATCH*SS*CCH];
__device__ __half d_senht[BATCH*SS*CCH];
__device__ __half d_a1t  [BATCH*SS*C8];
__device__ __half d_a2t  [BATCH*SS*C8];
__device__ __half d_q    [BATCH*SS*CCH];
__device__ __half d_k    [BATCH*SS*CCH];
__device__ __half d_v    [BATCH*SS*CCH];
__device__ __half d_qm   [2*BATCH*SS*C2];
__device__ __half d_km   [2*BATCH*SS*C2];
__device__ __half d_vm   [2*BATCH*SS*C2];
__device__ __half d_comb [BATCH*SS*2*CCH];
__device__ __half d_f1   [BATCH*SS*CCH];
__device__ __half d_fus  [BATCH*SS*CCH];
__device__ float  d_fin  [BATCH*SS*CCH];
__device__ __half d_w    [2654208];
__device__ __half d_w2   [36864];

// ---------------- helpers ----------------
__device__ __forceinline__ float blk_sum(float v, float* sb, int tid) {
    sb[tid] = v; __syncthreads();
    for (int o = 128; o > 0; o >>= 1) { if (tid < o) sb[tid] += sb[tid + o]; __syncthreads(); }
    float r = sb[0]; __syncthreads(); return r;
}
__device__ __forceinline__ float silu_f(float x) { return x / (1.0f + expf(-x)); }
__device__ __forceinline__ uint32_t pack2(float a, float b) {
    __half2 h = __floats2half2_rn(a, b);
    return *reinterpret_cast<uint32_t*>(&h);
}
__device__ __forceinline__ void store2(float* p, float a, float b) {
    *(float2*)p = make_float2(a, b);
}
__device__ __forceinline__ void store2(__half* p, float a, float b) {
    *(uint32_t*)p = pack2(a, b);
}
__device__ __forceinline__ uint32_t exp2_h2(float t0, float t1) {
    uint32_t h = pack2(t0, t1);
    uint32_t r;
    asm("ex2.approx.f16x2 %0, %1;" : "=r"(r) : "r"(h));
    return r;
}
__device__ __forceinline__ uint32_t cvsm(const void* p) {
    return (uint32_t)__cvta_generic_to_shared(p);
}
__device__ __forceinline__ void ldsm_x4(uint32_t& r0, uint32_t& r1, uint32_t& r2,
                                        uint32_t& r3, uint32_t addr) {
    asm volatile("ldmatrix.sync.aligned.m8n8.x4.shared.b16 {%0,%1,%2,%3}, [%4];"
        : "=r"(r0), "=r"(r1), "=r"(r2), "=r"(r3) : "r"(addr));
}
__device__ __forceinline__ void ldsm_x4_t(uint32_t& r0, uint32_t& r1, uint32_t& r2,
                                          uint32_t& r3, uint32_t addr) {
    asm volatile("ldmatrix.sync.aligned.m8n8.x4.trans.shared.b16 {%0,%1,%2,%3}, [%4];"
        : "=r"(r0), "=r"(r1), "=r"(r2), "=r"(r3) : "r"(addr));
}

#define MMA16(d, a0, a1, a2, a3, b0, b1) \
    asm volatile("mma.sync.aligned.m16n8k16.row.col.f32.f16.f16.f32 " \
        "{%0,%1,%2,%3},{%4,%5,%6,%7},{%8,%9},{%0,%1,%2,%3};" \
        : "+f"((d)[0]), "+f"((d)[1]), "+f"((d)[2]), "+f"((d)[3]) \
        : "r"(a0), "r"(a1), "r"(a2), "r"(a3), "r"(b0), "r"(b1))

// ---------------- weight conversion fp32 -> half ----------------
struct WC { const float* src[13]; int cnt4[13]; int off[13]; };
__global__ void wcvt(WC wc, __half* dst) {
    int which = blockIdx.y;
    int idx = blockIdx.x * 256 + threadIdx.x;
    if (idx < wc.cnt4[which]) {
        float4 v = *(const float4*)&wc.src[which][idx * 4];
        uint2 pk = make_uint2(pack2(v.x, v.y), pack2(v.z, v.w));
        *(uint2*)&dst[wc.off[which] + idx * 4] = pk;
    }
}
__global__ void w2cvt(const float* __restrict__ src, __half* __restrict__ dst) {
    int idx = blockIdx.x * 256 + threadIdx.x;
    if (idx < 36864) {
        int oc = idx / 576, rem = idx % 576;
        int tap = rem >> 6, ci = rem & 63;
        dst[idx] = __float2half(src[oc * 576 + ci * 9 + tap]);
    }
}

// =====================================================================
// Fused double GroupNorm -> half token-major hs_t, shn_t.
// =====================================================================
__global__ void gn_fused(const float* __restrict__ x,
                         const float* __restrict__ pre_g, const float* __restrict__ pre_b,
                         const float* __restrict__ pos,
                         const float* __restrict__ norm_g, const float* __restrict__ norm_b,
                         __half* __restrict__ hs_t, __half* __restrict__ shn_t) {
    extern __shared__ float xs[];
    __shared__ float sb[256];
    __shared__ float pgs[16], pbs[16], ngs[16], nbs[16];

    int tid = threadIdx.x;
    int b = blockIdx.x / NGR, gi = blockIdx.x % NGR;
    long base = (long)b * CCH * SS + (long)gi * CG * SS;
    if (tid < 16) {
        int c = gi * 16 + tid;
        pgs[tid] = pre_g[c]; pbs[tid] = pre_b[c];
        ngs[tid] = norm_g[c]; nbs[tid] = norm_b[c];
    }

    float s1 = 0.f, s2 = 0.f;
    for (int i = tid; i < CG * SS; i += 256) {
        float v = x[base + i];
        xs[i] = v; s1 += v; s2 += v * v;
    }
    s1 = blk_sum(s1, sb, tid);
    s2 = blk_sum(s2, sb, tid);
    float mu1 = s1 / (float)(CG * SS);
    float inv1 = rsqrtf(s2 / (float)(CG * SS) - mu1 * mu1 + GEPS);

    float t1 = 0.f, t2 = 0.f;
    for (int i = tid; i < CG * SS; i += 256) {
        int cl = i >> 10, s = i & 1023;
        int c = gi * CG + cl;
        float h = (xs[i] - mu1) * inv1 * pgs[cl] + pbs[cl] + pos[(long)c * SS + s];
        xs[i] = h;
        t1 += h; t2 += h * h;
    }
    t1 = blk_sum(t1, sb, tid);
    t2 = blk_sum(t2, sb, tid);
    float mu2 = t1 / (float)(CG * SS);
    float inv2 = rsqrtf(t2 / (float)(CG * SS) - mu2 * mu2 + GEPS);

    long tbase = ((long)b * SS) * CCH + gi * 16;
    for (int s = tid; s < SS; s += 256) {
        uint32_t wh[8], wn[8];
        #pragma unroll
        for (int cl = 0; cl < 16; cl += 2) {
            float h0 = xs[cl * 1024 + s], h1 = xs[(cl + 1) * 1024 + s];
            wh[cl >> 1] = pack2(h0, h1);
            float n0 = (h0 - mu2) * inv2 * ngs[cl] + nbs[cl];
            float n1 = (h1 - mu2) * inv2 * ngs[cl + 1] + nbs[cl + 1];
            wn[cl >> 1] = pack2(n0, n1);
        }
        __half* ph = hs_t + tbase + (long)s * CCH;
        *(uint4*)ph       = make_uint4(wh[0], wh[1], wh[2], wh[3]);
        *(uint4*)(ph + 8) = make_uint4(wh[4], wh[5], wh[6], wh[7]);
        __half* pn = shn_t + tbase + (long)s * CCH;
        *(uint4*)pn       = make_uint4(wn[0], wn[1], wn[2], wn[3]);
        *(uint4*)(pn + 8) = make_uint4(wn[4], wn[5], wn[6], wn[7]);
    }
}

// ---------------- group norm token-major + residual ----------------
__global__ void gn_post_k(const float* __restrict__ xt, const float* __restrict__ g,
                          const float* __restrict__ be, const float* __restrict__ resid,
                          float* __restrict__ y) {
    __shared__ float sb[256];
    int tid = threadIdx.x;
    int b = blockIdx.x / NGR, gi = blockIdx.x % NGR;
    long tbase = (long)b * SS * CCH + gi * CG;
    float s1 = 0.f, s2 = 0.f;
    for (int i = tid; i < CG * SS; i += 256) {
        int s = i >> 4, cl = i & 15;
        float v = xt[tbase + (long)s * CCH + cl]; s1 += v; s2 += v * v;
    }
    s1 = blk_sum(s1, sb, tid);
    s2 = blk_sum(s2, sb, tid);
    float mu = s1 / (float)(CG * SS);
    float var = s2 / (float)(CG * SS) - mu * mu;
    float inv = rsqrtf(var + GEPS);
    for (int i = tid; i < CG * SS; i += 256) {
        int s = i >> 4, cl = i & 15;
        int c = gi * CG + cl;
        float v = (xt[tbase + (long)s * CCH + cl] - mu) * inv * g[c] + be[c];
        long oidx = (long)b * CCH * SS + (long)c * SS + s;
        y[oidx] = v + resid[oidx];
    }
}

// =====================================================================
// Unified fp16 GEMM (NT), 128x128 tile, half weights.
// =====================================================================
struct GArg {
    const __half* A[6]; const __half* W[6]; void* Y[6]; const float* bias[6];
    float sc[6];
    long aOuter, yOuter;
    int K, lda, N, ldy, act;
};

template<typename OutT>
__global__ __launch_bounds__(256, 2) void gemm128(GArg ga) {
    __shared__ __align__(16) uint32_t As32[2 * 128 * 20];
    __shared__ __align__(16) uint32_t Bs32[2 * 128 * 20];

    int z = blockIdx.z;
    int which = z >> 3, b = z & 7;
    const __half* Ab = ga.A[which] + (long)b * ga.aOuter;
    const __half* Bb = ga.W[which];
    OutT*         Yb = (OutT*)ga.Y[which] + (long)b * ga.yOuter;
    const float* bias = ga.bias[which];
    float scl = ga.sc[which];
    int K = ga.K, lda = ga.lda, ldy = ga.ldy, act = ga.act;
    int m0 = blockIdx.x * 128, n0 = blockIdx.y * 128;

    int tid = threadIdx.x;
    int w = tid >> 5, lane = tid & 31;
    int wm = w & 1, wn = w >> 1;
    int g = lane >> 2, tig = lane & 3;
    int rbase = wm * 64, cbase = wn * 32;
    int lrow = lane & 7, lmat = lane >> 3;
    int fr_row = (lmat & 1) * 8 + lrow;
    int fr_col = (lmat >> 1) * 4;
    uint32_t As_b = cvsm(As32), Bs_b = cvsm(Bs32);

    float acc[4][4][4];
    #pragma unroll
    for (int i = 0; i < 4; i++)
        #pragma unroll
        for (int j = 0; j < 4; j++)
            #pragma unroll
            for (int l = 0; l < 4; l++) acc[i][j][l] = 0.f;

    uint4 aR[2], bR[2];
    int w4 = (tid & 3) * 4, mb = tid >> 2;

    auto ldg = [&](int k0) {
        #pragma unroll
        for (int it = 0; it < 2; it++)
            aR[it] = *(const uint4*)&Ab[(long)(m0 + mb + it * 64) * lda + k0 + w4 * 2];
        #pragma unroll
        for (int it = 0; it < 2; it++)
            bR[it] = *(const uint4*)&Bb[(long)(n0 + mb + it * 64) * K + k0 + w4 * 2];
    };
    auto sts = [&](int p) {
        uint32_t* Ad = As32 + p * 2560;
        uint32_t* Bd = Bs32 + p * 2560;
        #pragma unroll
        for (int it = 0; it < 2; it++)
            *(uint4*)&Ad[(mb + it * 64) * 20 + w4] = aR[it];
        #pragma unroll
        for (int it = 0; it < 2; it++)
            *(uint4*)&Bd[(mb + it * 64) * 20 + w4] = bR[it];
    };

    ldg(0); sts(0);
    __syncthreads();
    for (int k0 = 0; k0 < K; k0 += 32) {
        int p = (k0 >> 5) & 1;
        bool more = (k0 + 32 < K);
        if (more) ldg(k0 + 32);

        uint32_t Ap = As_b + (uint32_t)p * 2560 * 4;
        uint32_t Bp = Bs_b + (uint32_t)p * 2560 * 4;
        #pragma unroll
        for (int ks = 0; ks < 2; ks++) {
            int kw = ks * 8;
            uint32_t af[4][4], bf[4][2];
            #pragma unroll
            for (int mt = 0; mt < 4; mt++) {
                int r0 = rbase + mt * 16;
                ldsm_x4(af[mt][0], af[mt][1], af[mt][2], af[mt][3],
                        Ap + (uint32_t)(((r0 + fr_row) * 20) + kw + fr_col) * 4);
            }
            ldsm_x4(bf[0][0], bf[1][0], bf[2][0], bf[3][0],
                    Bp + (uint32_t)(((cbase + lmat * 8 + lrow) * 20) + kw) * 4);
            ldsm_x4(bf[0][1], bf[1][1], bf[2][1], bf[3][1],
                    Bp + (uint32_t)(((cbase + lmat * 8 + lrow) * 20) + kw + 4) * 4);
            #pragma unroll
            for (int mt = 0; mt < 4; mt++)
                #pragma unroll
                for (int nt = 0; nt < 4; nt++)
                    MMA16(acc[mt][nt], af[mt][0], af[mt][1], af[mt][2], af[mt][3],
                          bf[nt][0], bf[nt][1]);
        }
        if (more) sts(p ^ 1);
        __syncthreads();
    }

    #pragma unroll
    for (int mt = 0; mt < 4; mt++)
        #pragma unroll
        for (int nt = 0; nt < 4; nt++) {
            int r = m0 + rbase + mt * 16 + g;
            int cN = n0 + cbase + nt * 8 + 2 * tig;
            float b0 = bias ? bias[cN] : 0.f;
            float b1 = bias ? bias[cN + 1] : 0.f;
            float v0 = acc[mt][nt][0] * scl + b0;
            float v1 = acc[mt][nt][1] * scl + b1;
            float v2 = acc[mt][nt][2] * scl + b0;
            float v3 = acc[mt][nt][3] * scl + b1;
            if (act == 1) { v0 = silu_f(v0); v1 = silu_f(v1); v2 = silu_f(v2); v3 = silu_f(v3); }
            store2(&Yb[(long)r * ldy + cN],       v0, v1);
            store2(&Yb[(long)(r + 8) * ldy + cN], v2, v3);
        }
}

// =====================================================================
// conv1 as GEMM: a1t = silu(hst . w1 + b), half token-major out.
// =====================================================================
__global__ __launch_bounds__(256) void conv1_gemm(
        const __half* __restrict__ A, const __half* __restrict__ Bm,
        const float* __restrict__ bias, __half* __restrict__ Y) {
    __shared__ __align__(16) uint32_t As32[2 * 128 * 20];
    __shared__ __align__(16) uint32_t Bs32[2 * 64 * 20];

    int b = blockIdx.z;
    const __half* Ab = A + (long)b * SS * CCH;
    __half* Yb = Y + (long)b * SS * C8;
    int m0 = blockIdx.x * 128;

    int tid = threadIdx.x;
    int w = tid >> 5, lane = tid & 31;
    int wm = w & 3, wn = w >> 2;
    int g = lane >> 2, tig = lane & 3;
    int rbase = wm * 32, cbase = wn * 32;
    int lrow = lane & 7, lmat = lane >> 3;
    int fr_row = (lmat & 1) * 8 + lrow;
    int fr_col = (lmat >> 1) * 4;
    uint32_t As_b = cvsm(As32), Bs_b = cvsm(Bs32);

    float acc[2][4][4];
    #pragma unroll
    for (int i = 0; i < 2; i++)
        #pragma unroll
        for (int j = 0; j < 4; j++)
            #pragma unroll
            for (int l = 0; l < 4; l++) acc[i][j][l] = 0.f;

    uint4 aR[2], bR;
    int w4 = (tid & 3) * 4, mb = tid >> 2;

    auto ldg = [&](int k0) {
        #pragma unroll
        for (int it = 0; it < 2; it++)
            aR[it] = *(const uint4*)&Ab[(long)(m0 + mb + it * 64) * CCH + k0 + w4 * 2];
        bR = *(const uint4*)&Bm[(long)mb * 512 + k0 + w4 * 2];
    };
    auto sts = [&](int p) {
        uint32_t* Ad = As32 + p * 2560;
        uint32_t* Bd = Bs32 + p * 1280;
        #pragma unroll
        for (int it = 0; it < 2; it++)
            *(uint4*)&Ad[(mb + it * 64) * 20 + w4] = aR[it];
        *(uint4*)&Bd[mb * 20 + w4] = bR;
    };

    ldg(0); sts(0);
    __syncthreads();
    for (int k0 = 0; k0 < 512; k0 += 32) {
        int p = (k0 >> 5) & 1;
        bool more = (k0 + 32 < 512);
        if (more) ldg(k0 + 32);

        uint32_t Ap = As_b + (uint32_t)p * 2560 * 4;
        uint32_t Bp = Bs_b + (uint32_t)p * 1280 * 4;
        #pragma unroll
        for (int ks = 0; ks < 2; ks++) {
            int kw = ks * 8;
            uint32_t af[2][4], bf[4][2];
            #pragma unroll
            for (int mt = 0; mt < 2; mt++) {
                int r0 = rbase + mt * 16;
                ldsm_x4(af[mt][0], af[mt][1], af[mt][2], af[mt][3],
                        Ap + (uint32_t)(((r0 + fr_row) * 20) + kw + fr_col) * 4);
            }
            ldsm_x4(bf[0][0], bf[1][0], bf[2][0], bf[3][0],
                    Bp + (uint32_t)(((cbase + lmat * 8 + lrow) * 20) + kw) * 4);
            ldsm_x4(bf[0][1], bf[1][1], bf[2][1], bf[3][1],
                    Bp + (uint32_t)(((cbase + lmat * 8 + lrow) * 20) + kw + 4) * 4);
            #pragma unroll
            for (int mt = 0; mt < 2; mt++)
                #pragma unroll
                for (int nt = 0; nt < 4; nt++)
                    MMA16(acc[mt][nt], af[mt][0], af[mt][1], af[mt][2], af[mt][3],
                          bf[nt][0], bf[nt][1]);
        }
        if (more) sts(p ^ 1);
        __syncthreads();
    }

    #pragma unroll
    for (int mt = 0; mt < 2; mt++)
        #pragma unroll
        for (int nt = 0; nt < 4; nt++) {
            int r = m0 + rbase + mt * 16 + g;
            int cN = cbase + nt * 8 + 2 * tig;
            float b0 = bias[cN], b1 = bias[cN + 1];
            store2(&Yb[(long)r * C8 + cN],       silu_f(acc[mt][nt][0] + b0), silu_f(acc[mt][nt][1] + b1));
            store2(&Yb[(long)(r + 8) * C8 + cN], silu_f(acc[mt][nt][2] + b0), silu_f(acc[mt][nt][3] + b1));
        }
}

// =====================================================================
// conv2 as IMPLICIT GEMM (9 taps x 64 ci), zero-padded shifts.
// =====================================================================
__global__ __launch_bounds__(256) void conv2_gemm(
        const __half* __restrict__ A, const __half* __restrict__ Bm,
        const float* __restrict__ bias, __half* __restrict__ Y) {
    __shared__ __align__(16) uint32_t As32[128 * 36];
    __shared__ __align__(16) uint32_t Bs32[64 * 36];

    int b = blockIdx.z;
    const __half* Ab = A + (long)b * SS * C8;
    __half* Yb = Y + (long)b * SS * C8;
    int m0 = blockIdx.x * 128;

    int tid = threadIdx.x;
    int w = tid >> 5, lane = tid & 31;
    int wm = w & 3, wn = w >> 2;
    int g = lane >> 2, tig = lane & 3;
    int rbase = wm * 32, cbase = wn * 32;
    int lrow = lane & 7, lmat = lane >> 3;
    int fr_row = (lmat & 1) * 8 + lrow;
    int fr_col = (lmat >> 1) * 4;
    uint32_t As_b = cvsm(As32), Bs_b = cvsm(Bs32);

    float acc[2][4][4];
    #pragma unroll
    for (int i = 0; i < 2; i++)
        #pragma unroll
        for (int j = 0; j < 4; j++)
            #pragma unroll
            for (int l = 0; l < 4; l++) acc[i][j][l] = 0.f;

    uint4 aR[4], bR[2];

    auto ldg_tap = [&](int tap) {
        int dy = tap / 3 - 1, dx = tap % 3 - 1;
        #pragma unroll
        for (int f = 0; f < 4; f++) {
            int idx = tid + f * 256;
            int r = idx >> 3, c8 = idx & 7;
            int s = m0 + r;
            int sy = (s >> 5) + dy, sx = (s & 31) + dx;
            bool valid = ((unsigned)sy < 32u) && ((unsigned)sx < 32u);
            aR[f] = valid ? *(const uint4*)&Ab[(long)((sy << 5) + sx) * C8 + c8 * 8]
                          : make_uint4(0u, 0u, 0u, 0u);
        }
        #pragma unroll
        for (int f = 0; f < 2; f++) {
            int idx = tid + f * 256;
            int r = idx >> 3, c8 = idx & 7;
            bR[f] = *(const uint4*)&Bm[(long)r * 576 + tap * 64 + c8 * 8];
        }
    };
    auto sts_tap = [&]() {
        #pragma unroll
        for (int f = 0; f < 4; f++) {
            int idx = tid + f * 256;
            int r = idx >> 3, c8 = idx & 7;
            *(uint4*)&As32[r * 36 + c8 * 4] = aR[f];
        }
        #pragma unroll
        for (int f = 0; f < 2; f++) {
            int idx = tid + f * 256;
            int r = idx >> 3, c8 = idx & 7;
            *(uint4*)&Bs32[r * 36 + c8 * 4] = bR[f];
        }
    };

    ldg_tap(0);
    for (int tap = 0; tap < 9; tap++) {
        sts_tap();
        __syncthreads();
        if (tap < 8) ldg_tap(tap + 1);

        #pragma unroll
        for (int ks = 0; ks < 4; ks++) {
            int kw = ks * 8;
            uint32_t af[2][4], bf[4][2];
            #pragma unroll
            for (int mt = 0; mt < 2; mt++) {
                int r0 = rbase + mt * 16;
                ldsm_x4(af[mt][0], af[mt][1], af[mt][2], af[mt][3],
                        As_b + (uint32_t)(((r0 + fr_row) * 36) + kw + fr_col) * 4);
            }
            ldsm_x4(bf[0][0], bf[1][0], bf[2][0], bf[3][0],
                    Bs_b + (uint32_t)(((cbase + lmat * 8 + lrow) * 36) + kw) * 4);
            ldsm_x4(bf[0][1], bf[1][1], bf[2][1], bf[3][1],
                    Bs_b + (uint32_t)(((cbase + lmat * 8 + lrow) * 36) + kw + 4) * 4);
            #pragma unroll
            for (int mt = 0; mt < 2; mt++)
                #pragma unroll
                for (int nt = 0; nt < 4; nt++)
                    MMA16(acc[mt][nt], af[mt][0], af[mt][1], af[mt][2], af[mt][3],
                          bf[nt][0], bf[nt][1]);
        }
        __syncthreads();
    }

    #pragma unroll
    for (int mt = 0; mt < 2; mt++)
        #pragma unroll
        for (int nt = 0; nt < 4; nt++) {
            int r = m0 + rbase + mt * 16 + g;
            int cN = cbase + nt * 8 + 2 * tig;
            float b0 = bias[cN], b1 = bias[cN + 1];
            store2(&Yb[(long)r * C8 + cN],       silu_f(acc[mt][nt][0] + b0), silu_f(acc[mt][nt][1] + b1));
            store2(&Yb[(long)(r + 8) * C8 + cN], silu_f(acc[mt][nt][2] + b0), silu_f(acc[mt][nt][3] + b1));
        }
}

// ---------------- fused conv3(64->1)+sigmoid + senh scale ----------------
__global__ void conv3_senh(const __half* __restrict__ a2t, const float* __restrict__ w,
                           const float* __restrict__ bias, const __half* __restrict__ hs_t,
                           __half* __restrict__ senh_t) {
    __shared__ float ws[64];
    __shared__ float swv[32];
    int tid = threadIdx.x;
    if (tid < 64) ws[tid] = w[tid];
    __syncthreads();
    int tok0 = blockIdx.x * 32;
    {
        int t = tid >> 3, ln = tid & 7;
        long o = (long)(tok0 + t) * C8 + ln * 8;
        uint4 v = *(const uint4*)&a2t[o];
        const __half2* h2 = (const __half2*)&v;
        float acc = 0.f;
        #pragma unroll
        for (int u = 0; u < 4; u++) {
            float2 fv = __half22float2(h2[u]);
            acc += fv.x * ws[ln * 8 + u * 2] + fv.y * ws[ln * 8 + u * 2 + 1];
        }
        acc += __shfl_xor_sync(0xffffffffu, acc, 1);
        acc += __shfl_xor_sync(0xffffffffu, acc, 2);
        acc += __shfl_xor_sync(0xffffffffu, acc, 4);
        if (ln == 0) swv[t] = 1.0f / (1.0f + expf(-(acc + bias[0])));
    }
    __syncthreads();
    #pragma unroll
    for (int it = 0; it < 8; it++) {
        int idx = tid + it * 256;
        int t = idx >> 6, c8 = idx & 63;
        __half2 m = __float2half2_rn(swv[t]);
        long o = (long)(tok0 + t) * CCH + c8 * 8;
        uint4 v = *(const uint4*)&hs_t[o];
        __half2* h = (__half2*)&v;
        h[0] = __hmul2(h[0], m); h[1] = __hmul2(h[1], m);
        h[2] = __hmul2(h[2], m); h[3] = __hmul2(h[3], m);
        *(uint4*)&senh_t[o] = v;
    }
}

// =====================================================================
// Flash attention split into two kernels for cross-stream overlap.
// std smem: 12032 words; multi smem: 20480 words.
// =====================================================================
#define FS_WORDS 12032
#define FM_WORDS 20480

__device__ __forceinline__ void flash_std_body(
        const __half* __restrict__ Q, const __half* __restrict__ K,
        const __half* __restrict__ V, __half* __restrict__ O,
        int bh, int xq, uint32_t* smw) {
    uint32_t* Qs = smw;
    uint32_t* KP = smw + 128 * 36;
    uint32_t* Vs = smw + 2 * 128 * 36;
    float* redm = (float*)(smw + 2 * 128 * 36 + 64 * 36);
    float* redl = redm + 256;

    int b = bh >> 3, h = bh & 7;
    const __half* Qb = Q + (long)b * SS * CCH + h * 64;
    const __half* Kb = K + (long)b * SS * CCH + h * 64;
    const __half* Vb = V + (long)b * SS * CCH + h * 64;
    __half* Ob = O + (long)b * SS * (2 * CCH) + h * 64;
    int q0 = xq * 128;

    int tid = threadIdx.x;
    int w = tid >> 5, lane = tid & 31;
    int wm = w & 3, wn = w >> 2;
    int g = lane >> 2, tig = lane & 3;
    int rbase = wm * 32, cbase = wn * 32;
    int lrow = lane & 7, lmat = lane >> 3;
    int fr_row = (lmat & 1) * 8 + lrow;
    int fr_col = (lmat >> 1) * 4;
    int t_kb = lmat >> 1, t_hb = lmat & 1;
    uint32_t Qs_b = cvsm(Qs), KP_b = cvsm(KP), Vs_b = cvsm(Vs);

    #pragma unroll
    for (int f = 0; f < 4; f++) {
        int idx = tid + f * 256;
        int r = idx >> 3, w4 = (idx & 7) * 4;
        uint4 v4 = *(const uint4*)&Qb[(long)(q0 + r) * CCH + (idx & 7) * 8];
        *(uint4*)&Qs[r * 36 + w4] = v4;
    }

    uint4 kR[2], vR[2];
    int st_r = tid >> 3, st_w4 = (tid & 7) * 4, st_c = (tid & 7) * 8;
    auto ldg_kv = [&](int j) {
        #pragma unroll
        for (int f = 0; f < 2; f++) {
            long goff = (long)(j * 64 + st_r + f * 32) * CCH + st_c;
            kR[f] = *(const uint4*)&Kb[goff];
            vR[f] = *(const uint4*)&Vb[goff];
        }
    };
    auto sts_kv = [&]() {
        #pragma unroll
        for (int f = 0; f < 2; f++) {
            *(uint4*)&KP[(st_r + f * 32) * 36 + st_w4] = kR[f];
            *(uint4*)&Vs[(st_r + f * 32) * 36 + st_w4] = vR[f];
        }
    };

    float accO[2][4][4];
    #pragma unroll
    for (int i = 0; i < 2; i++)
        #pragma unroll
        for (int j = 0; j < 4; j++)
            #pragma unroll
            for (int l = 0; l < 4; l++) accO[i][j][l] = 0.f;
    float mst[4] = { -1e30f, -1e30f, -1e30f, -1e30f };
    float lst[4] = { 0.f, 0.f, 0.f, 0.f };

    ldg_kv(0);
    for (int j = 0; j < 16; j++) {
        sts_kv();
        __syncthreads();
        if (j + 1 < 16) ldg_kv(j + 1);

        float acc[2][4][4];
        #pragma unroll
        for (int i = 0; i < 2; i++)
            #pragma unroll
            for (int jj = 0; jj < 4; jj++)
                #pragma unroll
                for (int l = 0; l < 4; l++) acc[i][jj][l] = 0.f;
        #pragma unroll
        for (int ks = 0; ks < 4; ks++) {
            int kw = ks * 8;
            uint32_t af[2][4], bf[4][2];
            #pragma unroll
            for (int mt = 0; mt < 2; mt++) {
                int r0 = rbase + mt * 16;
                ldsm_x4(af[mt][0], af[mt][1], af[mt][2], af[mt][3],
                        Qs_b + (uint32_t)(((r0 + fr_row) * 36) + kw + fr_col) * 4);
            }
            ldsm_x4(bf[0][0], bf[1][0], bf[2][0], bf[3][0],
                    KP_b + (uint32_t)(((cbase + lmat * 8 + lrow) * 36) + kw) * 4);
            ldsm_x4(bf[0][1], bf[1][1], bf[2][1], bf[3][1],
                    KP_b + (uint32_t)(((cbase + lmat * 8 + lrow) * 36) + kw + 4) * 4);
            #pragma unroll
            for (int mt = 0; mt < 2; mt++)
                #pragma unroll
                for (int nt = 0; nt < 4; nt++)
                    MMA16(acc[mt][nt], af[mt][0], af[mt][1], af[mt][2], af[mt][3],
                          bf[nt][0], bf[nt][1]);
        }

        #pragma unroll
        for (int mt = 0; mt < 2; mt++)
            #pragma unroll
            for (int hh = 0; hh < 2; hh++) {
                float mx = -1e30f;
                #pragma unroll
                for (int nt = 0; nt < 4; nt++) {
                    mx = fmaxf(mx, acc[mt][nt][hh * 2]);
                    mx = fmaxf(mx, acc[mt][nt][hh * 2 + 1]);
                }
                mx = fmaxf(mx, __shfl_xor_sync(0xffffffffu, mx, 1));
                mx = fmaxf(mx, __shfl_xor_sync(0xffffffffu, mx, 2));
                if (tig == 0) redm[wn * 128 + rbase + mt * 16 + hh * 8 + g] = mx;
            }
        __syncthreads();

        #pragma unroll
        for (int mt = 0; mt < 2; mt++)
            #pragma unroll
            for (int hh = 0; hh < 2; hh++) {
                int i = mt * 2 + hh;
                int rloc = rbase + mt * 16 + hh * 8 + g;
                float mch = fmaxf(redm[rloc], redm[128 + rloc]);
                float mnew = fmaxf(mst[i], mch);
                float corr = __expf(mst[i] - mnew);
                mst[i] = mnew;
                float s = 0.f;
                #pragma unroll
                for (int nt = 0; nt < 4; nt++) {
                    uint32_t ph = exp2_h2((acc[mt][nt][hh * 2]     - mnew) * L2E,
                                          (acc[mt][nt][hh * 2 + 1] - mnew) * L2E);
                    KP[rloc * 36 + wn * 16 + nt * 4 + tig] = ph;
                    float2 pf = __half22float2(*(__half2*)&ph);
                    s += pf.x + pf.y;
                    accO[mt][nt][hh * 2]     *= corr;
                    accO[mt][nt][hh * 2 + 1] *= corr;
                }
                s += __shfl_xor_sync(0xffffffffu, s, 1);
                s += __shfl_xor_sync(0xffffffffu, s, 2);
                if (tig == 0) redl[wn * 128 + rloc] = s;
                lst[i] *= corr;
            }
        __syncthreads();
        #pragma unroll
        for (int mt = 0; mt < 2; mt++)
            #pragma unroll
            for (int hh = 0; hh < 2; hh++) {
                int rloc = rbase + mt * 16 + hh * 8 + g;
                lst[mt * 2 + hh] += redl[rloc] + redl[128 + rloc];
            }

        #pragma unroll
        for (int ks = 0; ks < 4; ks++) {
            int kw = ks * 8;
            uint32_t af[2][4], bf[4][2];
            #pragma unroll
            for (int mt = 0; mt < 2; mt++) {
                int r0 = rbase + mt * 16;
                ldsm_x4(af[mt][0], af[mt][1], af[mt][2], af[mt][3],
                        KP_b + (uint32_t)(((r0 + fr_row) * 36) + kw + fr_col) * 4);
            }
            uint32_t vaddr = Vs_b + (uint32_t)((ks * 16 + t_kb * 8 + lrow) * 144
                                               + (cbase + t_hb * 8) * 2);
            ldsm_x4_t(bf[0][0], bf[1][0], bf[0][1], bf[1][1], vaddr);
            ldsm_x4_t(bf[2][0], bf[3][0], bf[2][1], bf[3][1], vaddr + 32);
            #pragma unroll
            for (int mt = 0; mt < 2; mt++)
                #pragma unroll
                for (int nt = 0; nt < 4; nt++)
                    MMA16(accO[mt][nt], af[mt][0], af[mt][1], af[mt][2], af[mt][3],
                          bf[nt][0], bf[nt][1]);
        }
        __syncthreads();
    }

    #pragma unroll
    for (int mt = 0; mt < 2; mt++) {
        float inv0 = 1.0f / lst[mt * 2];
        float inv1 = 1.0f / lst[mt * 2 + 1];
        #pragma unroll
        for (int nt = 0; nt < 4; nt++) {
            int r = q0 + rbase + mt * 16 + g;
            int c = cbase + nt * 8 + 2 * tig;
            store2(&Ob[(long)r * 1024 + c],       accO[mt][nt][0] * inv0, accO[mt][nt][1] * inv0);
            store2(&Ob[(long)(r + 8) * 1024 + c], accO[mt][nt][2] * inv1, accO[mt][nt][3] * inv1);
        }
    }
}

__device__ __forceinline__ void flash_multi_body(
        const __half* __restrict__ Q, const __half* __restrict__ K,
        const __half* __restrict__ V, __half* __restrict__ O,
        int z, int xq, uint32_t* smw) {
    uint32_t* Qs  = smw;
    uint32_t* Ks0 = smw + 8448;
    uint32_t* Ps  = smw + 8448 + 2 * 2304;
    uint32_t* Vs0 = smw + 8448 + 3 * 2304;
    float* redm = (float*)(smw + 8448 + 5 * 2304);
    float* redl = redm + 256;

    const __half* Qb = Q + (long)z * SS * C2;
    const __half* Kb = K + (long)z * SS * C2;
    const __half* Vb = V + (long)z * SS * C2;
    int br = z >> 3, b = z & 7;
    __half* Ob = O + (long)b * SS * 1024 + 512 + br * 256;
    int q0 = xq * 64;

    int tid = threadIdx.x;
    int w = tid >> 5, lane = tid & 31;
    int wm = w & 1, wn = w >> 1;
    int g = lane >> 2, tig = lane & 3;
    int rbase = wm * 32;
    int lrow = lane & 7, lmat = lane >> 3;
    int fr_row = (lmat & 1) * 8 + lrow;
    int fr_col = (lmat >> 1) * 4;
    int t_kb = lmat >> 1, t_hb = lmat & 1;
    uint32_t Qs_b = cvsm(Qs), Ks_b = cvsm(Ks0), Ps_b = cvsm(Ps), Vs_b = cvsm(Vs0);

    #pragma unroll
    for (int f = 0; f < 8; f++) {
        int idx = tid + f * 256;
        int r = idx >> 5, c8 = idx & 31;
        uint4 qv = *(const uint4*)&Qb[(long)(q0 + r) * C2 + c8 * 8];
        *(uint4*)&Qs[r * 132 + c8 * 4] = qv;
    }

    int st_r = tid >> 3, st_w4 = (tid & 7) * 4, st_c = (tid & 7) * 8;
    uint4 sR[2];
    auto ldg_s = [&](const __half* P, int j, int dc) {
        #pragma unroll
        for (int f = 0; f < 2; f++)
            sR[f] = *(const uint4*)&P[(long)(j * 64 + st_r + f * 32) * C2 + dc * 64 + st_c];
    };
    auto sts_s = [&](uint32_t* D) {
        #pragma unroll
        for (int f = 0; f < 2; f++)
            *(uint4*)&D[(st_r + f * 32) * 36 + st_w4] = sR[f];
    };

    float accO[2][8][4];
    #pragma unroll
    for (int i = 0; i < 2; i++)
        #pragma unroll
        for (int j = 0; j < 8; j++)
            #pragma unroll
            for (int l = 0; l < 4; l++) accO[i][j][l] = 0.f;
    float mst[4] = { -1e30f, -1e30f, -1e30f, -1e30f };
    float lst[4] = { 0.f, 0.f, 0.f, 0.f };

    for (int j = 0; j < 16; j++) {
        float acc[2][2][4];
        #pragma unroll
        for (int i = 0; i < 2; i++)
            #pragma unroll
            for (int jj = 0; jj < 2; jj++)
                #pragma unroll
                for (int l = 0; l < 4; l++) acc[i][jj][l] = 0.f;

        ldg_s(Kb, j, 0);
        sts_s(Ks0);
        __syncthreads();
        for (int dc = 0; dc < 4; dc++) {
            int p = dc & 1;
            bool more = (dc < 3);
            if (more) ldg_s(Kb, j, dc + 1);
            uint32_t Kp = Ks_b + (uint32_t)p * 2304 * 4;
            #pragma unroll
            for (int ks = 0; ks < 4; ks++) {
                int kw = ks * 8;
                uint32_t af[2][4], bf[2][2];
                #pragma unroll
                for (int mt = 0; mt < 2; mt++) {
                    int r0 = rbase + mt * 16;
                    ldsm_x4(af[mt][0], af[mt][1], af[mt][2], af[mt][3],
                            Qs_b + (uint32_t)(((r0 + fr_row) * 132) + dc * 32 + kw + fr_col) * 4);
                }
                ldsm_x4(bf[0][0], bf[1][0], bf[0][1], bf[1][1],
                        Kp + (uint32_t)(((wn * 16 + fr_row) * 36) + kw + fr_col) * 4);
                #pragma unroll
                for (int mt = 0; mt < 2; mt++)
                    #pragma unroll
                    for (int nt = 0; nt < 2; nt++)
                        MMA16(acc[mt][nt], af[mt][0], af[mt][1], af[mt][2], af[mt][3],
                              bf[nt][0], bf[nt][1]);
            }
            if (more) sts_s(Ks0 + (p ^ 1) * 2304);
            __syncthreads();
        }

        #pragma unroll
        for (int mt = 0; mt < 2; mt++)
            #pragma unroll
            for (int hh = 0; hh < 2; hh++) {
                float mx = -1e30f;
                #pragma unroll
                for (int nt = 0; nt < 2; nt++) {
                    mx = fmaxf(mx, acc[mt][nt][hh * 2]);
                    mx = fmaxf(mx, acc[mt][nt][hh * 2 + 1]);
                }
                mx = fmaxf(mx, __shfl_xor_sync(0xffffffffu, mx, 1));
                mx = fmaxf(mx, __shfl_xor_sync(0xffffffffu, mx, 2));
                if (tig == 0) redm[wn * 64 + rbase + mt * 16 + hh * 8 + g] = mx;
            }
        __syncthreads();

        #pragma unroll
        for (int mt = 0; mt < 2; mt++)
            #pragma unroll
            for (int hh = 0; hh < 2; hh++) {
                int i = mt * 2 + hh;
                int rloc = rbase + mt * 16 + hh * 8 + g;
                float mch = fmaxf(fmaxf(redm[rloc], redm[64 + rloc]),
                                  fmaxf(redm[128 + rloc], redm[192 + rloc]));
                float mnew = fmaxf(mst[i], mch);
                float corr = __expf(mst[i] - mnew);
                mst[i] = mnew;
                float s = 0.f;
                #pragma unroll
                for (int nt = 0; nt < 2; nt++) {
                    uint32_t ph = exp2_h2((acc[mt][nt][hh * 2]     - mnew) * L2E,
                                          (acc[mt][nt][hh * 2 + 1] - mnew) * L2E);
                    Ps[rloc * 36 + wn * 8 + nt * 4 + tig] = ph;
                    float2 pf = __half22float2(*(__half2*)&ph);
                    s += pf.x + pf.y;
                }
                s += __shfl_xor_sync(0xffffffffu, s, 1);
                s += __shfl_xor_sync(0xffffffffu, s, 2);
                if (tig == 0) redl[wn * 64 + rloc] = s;
                lst[i] *= corr;
                #pragma unroll
                for (int nt = 0; nt < 8; nt++) {
                    accO[mt][nt][hh * 2]     *= corr;
                    accO[mt][nt][hh * 2 + 1] *= corr;
                }
            }
        __syncthreads();
        #pragma unroll
        for (int mt = 0; mt < 2; mt++)
            #pragma unroll
            for (int hh = 0; hh < 2; hh++) {
                int rloc = rbase + mt * 16 + hh * 8 + g;
                lst[mt * 2 + hh] += redl[rloc] + redl[64 + rloc]
                                  + redl[128 + rloc] + redl[192 + rloc];
            }

        ldg_s(Vb, j, 0);
        sts_s(Vs0);
        __syncthreads();
        for (int dc = 0; dc < 4; dc++) {
            int p = dc & 1;
            bool more = (dc < 3);
            if (more) ldg_s(Vb, j, dc + 1);
            uint32_t Vp = Vs_b + (uint32_t)p * 2304 * 4;
            #pragma unroll
            for (int ks = 0; ks < 4; ks++) {
                int kw = ks * 8;
                uint32_t af[2][4], bf[2][2];
                #pragma unroll
                for (int mt = 0; mt < 2; mt++) {
                    int r0 = rbase + mt * 16;
                    ldsm_x4(af[mt][0], af[mt][1], af[mt][2], af[mt][3],
                            Ps_b + (uint32_t)(((r0 + fr_row) * 36) + kw + fr_col) * 4);
                }
                uint32_t vaddr = Vp + (uint32_t)((ks * 16 + t_kb * 8 + lrow) * 144
                                                 + (wn * 16 + t_hb * 8) * 2);
                ldsm_x4_t(bf[0][0], bf[1][0], bf[0][1], bf[1][1], vaddr);
                #pragma unroll
                for (int mt = 0; mt < 2; mt++)
                    #pragma unroll
                    for (int nt = 0; nt < 2; nt++)
                        MMA16(accO[mt][dc * 2 + nt], af[mt][0], af[mt][1], af[mt][2], af[mt][3],
                              bf[nt][0], bf[nt][1]);
            }
            if (more) sts_s(Vs0 + (p ^ 1) * 2304);
            __syncthreads();
        }
    }

    #pragma unroll
    for (int mt = 0; mt < 2; mt++) {
        float inv0 = 1.0f / lst[mt * 2];
        float inv1 = 1.0f / lst[mt * 2 + 1];
        #pragma unroll
        for (int u = 0; u < 8; u++) {
            int dc = u >> 1, nt = u & 1;
            int r = q0 + rbase + mt * 16 + g;
            int c = dc * 64 + wn * 16 + nt * 8 + 2 * tig;
            store2(&Ob[(long)r * 1024 + c],       accO[mt][u][0] * inv0, accO[mt][u][1] * inv0);
            store2(&Ob[(long)(r + 8) * 1024 + c], accO[mt][u][2] * inv1, accO[mt][u][3] * inv1);
        }
    }
}

__global__ __launch_bounds__(256, 2) void flash_std_k(
        const __half* __restrict__ q, const __half* __restrict__ k,
        const __half* __restrict__ v, __half* __restrict__ comb) {
    extern __shared__ uint32_t smw[];
    flash_std_body(q, k, v, comb, blockIdx.x >> 3, blockIdx.x & 7, smw);
}

__global__ __launch_bounds__(256, 2) void flash_multi_k(
        const __half* __restrict__ qm, const __half* __restrict__ km,
        const __half* __restrict__ vm, __half* __restrict__ comb) {
    extern __shared__ uint32_t smw[];
    flash_multi_body(qm, km, vm, comb, blockIdx.x >> 4, blockIdx.x & 15, smw);
}

// ---------------- launch ----------------
static void* symv(const void* s) { void* p = nullptr; cudaGetSymbolAddress(&p, s); return p; }

extern "C" void kernel_launch(void* const* d_in, const int* in_sizes, int n_in,
                              void* d_out, int out_size) {
    (void)in_sizes; (void)n_in; (void)out_size;
    const float* x      = (const float*)d_in[0];
    const float* pre_g  = (const float*)d_in[1];
    const float* pre_b  = (const float*)d_in[2];
    const float* norm_g = (const float*)d_in[3];
    const float* norm_b = (const float*)d_in[4];
    const float* post_g = (const float*)d_in[5];
    const float* post_b = (const float*)d_in[6];
    const float* pos    = (const float*)d_in[7];
    const float* sa_w1  = (const float*)d_in[8];
    const float* sa_b1  = (const float*)d_in[9];
    const float* sa_w2  = (const float*)d_in[10];
    const float* sa_b2  = (const float*)d_in[11];
    const float* sa_w3  = (const float*)d_in[12];
    const float* sa_b3  = (const float*)d_in[13];
    const float* wq     = (const float*)d_in[14];
    const float* wk     = (const float*)d_in[15];
    const float* wv     = (const float*)d_in[16];
    const float* wq0    = (const float*)d_in[17];
    const float* wk0    = (const float*)d_in[18];
    const float* wv0    = (const float*)d_in[19];
    const float* wq1    = (const float*)d_in[20];
    const float* wk1    = (const float*)d_in[21];
    const float* wv1    = (const float*)d_in[22];
    const float* ff_w1  = (const float*)d_in[23];
    const float* ff_b1  = (const float*)d_in[24];
    const float* ff_w2  = (const float*)d_in[25];
    const float* ff_b2  = (const float*)d_in[26];
    const float* out_w  = (const float*)d_in[27];
    const float* out_b  = (const float*)d_in[28];
    float* out = (float*)d_out;

    __half *hst = (__half*)symv(d_hst), *shnt = (__half*)symv(d_shnt), *senht = (__half*)symv(d_senht);
    __half *a1t = (__half*)symv(d_a1t), *a2t = (__half*)symv(d_a2t);
    __half *q = (__half*)symv(d_q), *k = (__half*)symv(d_k), *v = (__half*)symv(d_v);
    __half *qm = (__half*)symv(d_qm), *km = (__half*)symv(d_km), *vm = (__half*)symv(d_vm);
    __half *comb = (__half*)symv(d_comb), *f1 = (__half*)symv(d_f1), *fus = (__half*)symv(d_fus);
    float  *fin = (float*)symv(d_fin);
    __half *wb = (__half*)symv(d_w);
    __half *w2h = (__half*)symv(d_w2);

    static cudaStream_t s1 = nullptr;
    static cudaEvent_t evFork = nullptr, evW = nullptr, evGN = nullptr, evMulti = nullptr;
    if (!s1) {
        cudaStreamCreateWithFlags(&s1, cudaStreamNonBlocking);
        cudaEventCreateWithFlags(&evFork, cudaEventDisableTiming);
        cudaEventCreateWithFlags(&evW, cudaEventDisableTiming);
        cudaEventCreateWithFlags(&evGN, cudaEventDisableTiming);
        cudaEventCreateWithFlags(&evMulti, cudaEventDisableTiming);
    }

    cudaFuncSetAttribute(flash_std_k, cudaFuncAttributeMaxDynamicSharedMemorySize, FS_WORDS * 4);
    cudaFuncSetAttribute(flash_multi_k, cudaFuncAttributeMaxDynamicSharedMemorySize, FM_WORDS * 4);
    const int gnSmem = 16 * 1024 * 4;
    cudaFuncSetAttribute(gn_fused, cudaFuncAttributeMaxDynamicSharedMemorySize, gnSmem);

    const float* wsrc[13] = { wq, wk, wv, wq0, wk0, wv0, wq1, wk1, wv1,
                              ff_w1, ff_w2, out_w, sa_w1 };
    const int wcnt[13] = { 262144, 262144, 262144, 131072, 131072, 131072,
                           131072, 131072, 131072, 524288, 262144, 262144, 32768 };
    WC wc; int off = 0;
    __half* hw[13];
    for (int i = 0; i < 13; i++) {
        wc.src[i] = wsrc[i]; wc.cnt4[i] = wcnt[i] / 4; wc.off[i] = off;
        hw[i] = wb + off;
        off += wcnt[i];
    }

    // fork: weight conversion on s1 under gn_fused
    cudaEventRecord(evFork, 0);
    cudaStreamWaitEvent(s1, evFork, 0);
    wcvt<<<dim3(512, 13), 256, 0, s1>>>(wc, wb);
    w2cvt<<<144, 256, 0, s1>>>(sa_w2, w2h);
    cudaEventRecord(evW, s1);

    gn_fused<<<BATCH * NGR, 256, gnSmem>>>(x, pre_g, pre_b, pos, norm_g, norm_b,
                                           hst, shnt);
    cudaEventRecord(evGN, 0);

    // s1: conv gate chain -> pm -> flash_multi (entire multi branch)
    cudaStreamWaitEvent(s1, evGN, 0);
    conv1_gemm<<<dim3(8, 1, BATCH), 256, 0, s1>>>(hst, hw[12], sa_b1, a1t);
    conv2_gemm<<<dim3(8, 1, BATCH), 256, 0, s1>>>(a1t, w2h, sa_b2, a2t);
    conv3_senh<<<BATCH * SS / 32, 256, 0, s1>>>(a2t, sa_w3, sa_b3, hst, senht);

    long moff = 8LL * SS * C2;
    GArg pm = {};
    pm.A[0] = senht; pm.A[1] = shnt; pm.A[2] = shnt;
    pm.A[3] = senht; pm.A[4] = shnt; pm.A[5] = shnt;
    pm.W[0] = hw[3]; pm.W[1] = hw[4]; pm.W[2] = hw[5];
    pm.W[3] = hw[6]; pm.W[4] = hw[7]; pm.W[5] = hw[8];
    pm.Y[0] = qm;        pm.Y[1] = km;        pm.Y[2] = vm;
    pm.Y[3] = qm + moff; pm.Y[4] = km + moff; pm.Y[5] = vm + moff;
    for (int i = 0; i < 6; i++) pm.bias[i] = nullptr;
    pm.sc[0] = 0.0625f; pm.sc[1] = 1.f; pm.sc[2] = 1.f;
    pm.sc[3] = 0.0625f; pm.sc[4] = 1.f; pm.sc[5] = 1.f;
    pm.aOuter = (long)SS * CCH; pm.yOuter = (long)SS * C2;
    pm.K = 512; pm.lda = 512; pm.N = 256; pm.ldy = 256; pm.act = 0;
    gemm128<__half><<<dim3(8, 2, 48), 256, 0, s1>>>(pm);

    flash_multi_k<<<256, 256, FM_WORDS * 4, s1>>>(qm, km, vm, comb);
    cudaEventRecord(evMulti, s1);

    // stream 0: QKV projections -> flash_std
    cudaStreamWaitEvent(0, evW, 0);
    GArg pq = {};
    pq.A[0] = shnt; pq.A[1] = shnt; pq.A[2] = shnt;
    pq.W[0] = hw[0]; pq.W[1] = hw[1]; pq.W[2] = hw[2];
    pq.Y[0] = q;    pq.Y[1] = k;    pq.Y[2] = v;
    pq.bias[0] = pq.bias[1] = pq.bias[2] = nullptr;
    pq.sc[0] = 0.125f; pq.sc[1] = 1.f; pq.sc[2] = 1.f;
    pq.aOuter = (long)SS * CCH; pq.yOuter = (long)SS * 512;
    pq.K = 512; pq.lda = 512; pq.N = 512; pq.ldy = 512; pq.act = 0;
    gemm128<__half><<<dim3(8, 4, 24), 256>>>(pq);

    flash_std_k<<<512, 256, FS_WORDS * 4>>>(q, k, v, comb);

    // join: ff1 needs both halves of comb
    cudaStreamWaitEvent(0, evMulti, 0);
    GArg f1a = {};
    f1a.A[0] = comb; f1a.W[0] = hw[9]; f1a.Y[0] = f1; f1a.bias[0] = ff_b1;
    f1a.sc[0] = 1.f;
    f1a.aOuter = (long)SS * 2 * CCH; f1a.yOuter = (long)SS * CCH;
    f1a.K = 1024; f1a.lda = 1024; f1a.N = 512; f1a.ldy = 512; f1a.act = 1;
    gemm128<__half><<<dim3(8, 4, 8), 256>>>(f1a);
    // ff2
    GArg f2a = {};
    f2a.A[0] = f1; f2a.W[0] = hw[10]; f2a.Y[0] = fus; f2a.bias[0] = ff_b2;
    f2a.sc[0] = 1.f;
    f2a.aOuter = (long)SS * CCH; f2a.yOuter = (long)SS * CCH;
    f2a.K = 512; f2a.lda = 512; f2a.N = 512; f2a.ldy = 512; f2a.act = 0;
    gemm128<__half><<<dim3(8, 4, 8), 256>>>(f2a);
    // out proj
    GArg oa = {};
    oa.A[0] = fus; oa.W[0] = hw[11]; oa.Y[0] = fin; oa.bias[0] = out_b;
    oa.sc[0] = 1.f;
    oa.aOuter = (long)SS * CCH; oa.yOuter = (long)SS * CCH;
    oa.K = 512; oa.lda = 512; oa.N = 512; oa.ldy = 512; oa.act = 0;
    gemm128<float><<<dim3(8, 4, 8), 256>>>(oa);

    // post GN + residual
    gn_post_k<<<BATCH * NGR, 256>>>(fin, post_g, post_b, x, out);
}